// round 1
// baseline (speedup 1.0000x reference)
#include <cuda_runtime.h>
#include <cstdint>

// ---------------------------------------------------------------------------
// Problem constants (fixed by the dataset)
// ---------------------------------------------------------------------------
constexpr int NN   = 20000;          // nodes
constexpr int FIN  = 128;            // input features
constexpr int HEADS = 8;
constexpr int HIDC  = 64;
constexpr int D1    = HEADS * HIDC;  // 512
constexpr int REP   = 512;
constexpr int NCLS  = 133;
constexpr int EE    = 200000;        // edges (no self loops)
constexpr int ESL   = EE + NN;       // edges incl. self loops = 220000

// ---------------------------------------------------------------------------
// Scratch layout (floats). Zero-region first so one memset covers it.
// ---------------------------------------------------------------------------
constexpr size_t OFF_OUT1   = 0;                                    // N*512
constexpr size_t OFF_FINAL  = OFF_OUT1   + (size_t)NN * 512;        // N*1536
constexpr size_t OFF_HL     = OFF_FINAL  + (size_t)NN * 1536;       // N*256
constexpr size_t OFF_HR     = OFF_HL     + (size_t)NN * 256;        // N*256
constexpr size_t OFF_AMAX1  = OFF_HR     + (size_t)NN * 256;        // N*8 (uint)
constexpr size_t OFF_DEN1   = OFF_AMAX1  + (size_t)NN * 8;          // N*8
constexpr size_t OFF_AMAX2  = OFF_DEN1   + (size_t)NN * 8;          // N (uint)
constexpr size_t OFF_DEN2   = OFF_AMAX2  + (size_t)NN;              // N
constexpr size_t OFF_CNTL   = OFF_DEN2   + (size_t)NN;              // N
constexpr size_t OFF_CNTR   = OFF_CNTL   + (size_t)NN;              // N
constexpr size_t ZEND       = OFF_CNTR   + (size_t)NN;              // zeroed [0,ZEND)

constexpr size_t OFF_XL1    = ZEND;                                 // N*512
constexpr size_t OFF_S1     = OFF_XL1    + (size_t)NN * 512;        // N*8
constexpr size_t OFF_DD1    = OFF_S1     + (size_t)NN * 8;          // N*8
constexpr size_t OFF_ALPHA1 = OFF_DD1    + (size_t)NN * 8;          // ESL*8
constexpr size_t OFF_EX1    = OFF_ALPHA1 + (size_t)ESL * 8;         // ESL*8
constexpr size_t OFF_X1     = OFF_EX1    + (size_t)ESL * 8;         // N*512
constexpr size_t OFF_XL2    = OFF_X1     + (size_t)NN * 512;        // N*512
constexpr size_t OFF_S2     = OFF_XL2    + (size_t)NN * 512;        // N
constexpr size_t OFF_DD2    = OFF_S2     + (size_t)NN;              // N
constexpr size_t OFF_ALPHA2 = OFF_DD2    + (size_t)NN;              // ESL
constexpr size_t OFF_EX2    = OFF_ALPHA2 + (size_t)ESL;             // ESL
constexpr size_t OFF_BSL    = OFF_EX2    + (size_t)ESL;             // N
constexpr size_t OFF_BSR    = OFF_BSL    + (size_t)NN;              // N
constexpr size_t OFF_HIDC   = OFF_BSR    + (size_t)NN;              // N*512
constexpr size_t TOTALF     = OFF_HIDC   + (size_t)NN * 512;

__device__ float g_scratch[TOTALF];

// ---------------------------------------------------------------------------
// Helpers
// ---------------------------------------------------------------------------
__device__ __forceinline__ unsigned fenc(float f) {
    unsigned u = __float_as_uint(f);
    return (u & 0x80000000u) ? ~u : (u | 0x80000000u);
}
__device__ __forceinline__ float fdec(unsigned u) {
    return (u & 0x80000000u) ? __uint_as_float(u & 0x7FFFFFFFu)
                             : __uint_as_float(~u);
}
__device__ __forceinline__ void red_add_v4(float* p, float4 v) {
    asm volatile("red.global.add.v4.f32 [%0], {%1,%2,%3,%4};"
                 :: "l"(p), "f"(v.x), "f"(v.y), "f"(v.z), "f"(v.w) : "memory");
}
__device__ __forceinline__ void edge_sd(const int* __restrict__ ei, int e,
                                        int& s, int& d) {
    if (e < EE) { s = ei[e]; d = ei[EE + e]; }
    else        { s = d = e - EE; }
}
__device__ __forceinline__ float lrelu02(float x) {
    return x > 0.f ? x : 0.2f * x;
}

// ---------------------------------------------------------------------------
// GEMM: C[M,N] = A[M,K] @ B[K,N] (+ bias[col] * bscale[row]) (+ relu)
// 128x128 tile, BK=8, 256 threads, 8x8 microtile. K must be multiple of 8.
// ---------------------------------------------------------------------------
__global__ __launch_bounds__(256)
void sgemm(const float* __restrict__ A, const float* __restrict__ B,
           float* __restrict__ C, int M, int N, int K,
           int lda, int ldb, int ldc,
           const float* __restrict__ bias, const float* __restrict__ bscale,
           int relu)
{
    __shared__ float As[8][128];
    __shared__ float Bs[8][128];
    const int tid = threadIdx.x;
    const int bm = blockIdx.y * 128, bn = blockIdx.x * 128;
    const int ty = tid >> 4, tx = tid & 15;

    float acc[8][8];
#pragma unroll
    for (int i = 0; i < 8; i++)
#pragma unroll
        for (int j = 0; j < 8; j++) acc[i][j] = 0.f;

    for (int k0 = 0; k0 < K; k0 += 8) {
#pragma unroll
        for (int i = 0; i < 4; i++) {
            int idx = tid + i * 256;
            int m = idx >> 3, kk = idx & 7;
            int gm = bm + m;
            As[kk][m] = (gm < M) ? A[(size_t)gm * lda + k0 + kk] : 0.f;
        }
#pragma unroll
        for (int i = 0; i < 4; i++) {
            int idx = tid + i * 256;
            int n = idx & 127, kk = idx >> 7;
            int gn = bn + n;
            Bs[kk][n] = (gn < N) ? B[(size_t)(k0 + kk) * ldb + gn] : 0.f;
        }
        __syncthreads();
#pragma unroll
        for (int kk = 0; kk < 8; kk++) {
            float a[8], b[8];
#pragma unroll
            for (int i = 0; i < 8; i++) a[i] = As[kk][ty * 8 + i];
#pragma unroll
            for (int j = 0; j < 8; j++) b[j] = Bs[kk][tx * 8 + j];
#pragma unroll
            for (int i = 0; i < 8; i++)
#pragma unroll
                for (int j = 0; j < 8; j++)
                    acc[i][j] += a[i] * b[j];
        }
        __syncthreads();
    }

#pragma unroll
    for (int i = 0; i < 8; i++) {
        int row = bm + ty * 8 + i;
        if (row >= M) continue;
        float bsc = 1.f;
        if (bias && bscale) bsc = bscale[row];
#pragma unroll
        for (int j = 0; j < 8; j++) {
            int col = bn + tx * 8 + j;
            if (col >= N) continue;
            float v = acc[i][j];
            if (bias) v += bias[col] * bsc;
            if (relu) v = fmaxf(v, 0.f);
            C[(size_t)row * ldc + col] = v;
        }
    }
}

// ---------------------------------------------------------------------------
// GAT1: per-(node,head) attention logits s1,d1
// ---------------------------------------------------------------------------
__global__ void k_sd1(const float* __restrict__ xl1,
                      const float* __restrict__ as1, const float* __restrict__ ad1,
                      float* __restrict__ s1, float* __restrict__ d1)
{
    int idx = blockIdx.x * blockDim.x + threadIdx.x;
    if (idx >= NN * HEADS) return;
    int n = idx >> 3, h = idx & 7;
    const float4* xr = (const float4*)(xl1 + (size_t)n * 512 + h * 64);
    const float4* av = (const float4*)(as1 + h * 64);
    const float4* bv = (const float4*)(ad1 + h * 64);
    float ss = 0.f, dd = 0.f;
#pragma unroll
    for (int q = 0; q < 16; q++) {
        float4 x = xr[q], a = av[q], b = bv[q];
        ss += x.x * a.x + x.y * a.y + x.z * a.z + x.w * a.w;
        dd += x.x * b.x + x.y * b.y + x.z * b.z + x.w * b.w;
    }
    s1[idx] = ss; d1[idx] = dd;
}

// Edge alpha + atomic max over dst (encoded uint)
__global__ void k_alpha1(const int* __restrict__ ei,
                         const float* __restrict__ s1, const float* __restrict__ d1,
                         float* __restrict__ alpha1, unsigned* __restrict__ amax1)
{
    int idx = blockIdx.x * blockDim.x + threadIdx.x;
    if (idx >= ESL * HEADS) return;
    int e = idx >> 3, h = idx & 7;
    int s, d; edge_sd(ei, e, s, d);
    float a = lrelu02(s1[s * 8 + h] + d1[d * 8 + h]);
    alpha1[idx] = a;
    atomicMax(amax1 + d * 8 + h, fenc(a));
}

__global__ void k_ex1(const int* __restrict__ ei,
                      const float* __restrict__ alpha1, const unsigned* __restrict__ amax1,
                      float* __restrict__ ex1, float* __restrict__ den1)
{
    int idx = blockIdx.x * blockDim.x + threadIdx.x;
    if (idx >= ESL * HEADS) return;
    int e = idx >> 3, h = idx & 7;
    int s, d; edge_sd(ei, e, s, d);
    float ex = expf(alpha1[idx] - fdec(amax1[d * 8 + h]));
    ex1[idx] = ex;
    atomicAdd(den1 + d * 8 + h, ex);
}

// Aggregation: warp per edge, 16 floats/lane (one head per lane group of 4)
__global__ void k_agg1(const int* __restrict__ ei, const float* __restrict__ xl1,
                       const float* __restrict__ ex1, const float* __restrict__ den1,
                       float* __restrict__ out1)
{
    int warp = (blockIdx.x * blockDim.x + threadIdx.x) >> 5;
    int lane = threadIdx.x & 31;
    if (warp >= ESL) return;
    int s, d; edge_sd(ei, warp, s, d);
    float w = 0.f;
    if (lane < 8) w = ex1[(size_t)warp * 8 + lane] / (den1[d * 8 + lane] + 1e-16f);
    float wh = __shfl_sync(0xffffffffu, w, lane >> 2);
    const float4* sp = (const float4*)(xl1 + (size_t)s * 512) + lane * 4;
    float* dp = out1 + (size_t)d * 512 + lane * 16;
#pragma unroll
    for (int q = 0; q < 4; q++) {
        float4 v = sp[q];
        v.x *= wh; v.y *= wh; v.z *= wh; v.w *= wh;
        red_add_v4(dp + q * 4, v);
    }
}

__global__ void k_elu(const float* __restrict__ out1, const float* __restrict__ b1,
                      float* __restrict__ x1)
{
    int idx = blockIdx.x * blockDim.x + threadIdx.x;
    if (idx >= NN * 512) return;
    float v = out1[idx] + b1[idx & 511];
    x1[idx] = v > 0.f ? v : expm1f(v);
}

// ---------------------------------------------------------------------------
// GAT2 (1 head, 512 channels)
// ---------------------------------------------------------------------------
__global__ void k_sd2(const float* __restrict__ xl2,
                      const float* __restrict__ as2, const float* __restrict__ ad2,
                      float* __restrict__ s2, float* __restrict__ d2)
{
    int warp = (blockIdx.x * blockDim.x + threadIdx.x) >> 5;
    int lane = threadIdx.x & 31;
    if (warp >= NN) return;
    const float4* xr = (const float4*)(xl2 + (size_t)warp * 512) + lane * 4;
    const float4* av = (const float4*)as2 + lane * 4;
    const float4* bv = (const float4*)ad2 + lane * 4;
    float ss = 0.f, dd = 0.f;
#pragma unroll
    for (int q = 0; q < 4; q++) {
        float4 x = xr[q], a = av[q], b = bv[q];
        ss += x.x * a.x + x.y * a.y + x.z * a.z + x.w * a.w;
        dd += x.x * b.x + x.y * b.y + x.z * b.z + x.w * b.w;
    }
#pragma unroll
    for (int o = 16; o > 0; o >>= 1) {
        ss += __shfl_xor_sync(0xffffffffu, ss, o);
        dd += __shfl_xor_sync(0xffffffffu, dd, o);
    }
    if (lane == 0) { s2[warp] = ss; d2[warp] = dd; }
}

__global__ void k_alpha2(const int* __restrict__ ei,
                         const float* __restrict__ s2, const float* __restrict__ d2,
                         float* __restrict__ alpha2, unsigned* __restrict__ amax2)
{
    int e = blockIdx.x * blockDim.x + threadIdx.x;
    if (e >= ESL) return;
    int s, d; edge_sd(ei, e, s, d);
    float a = lrelu02(s2[s] + d2[d]);
    alpha2[e] = a;
    atomicMax(amax2 + d, fenc(a));
}

__global__ void k_ex2(const int* __restrict__ ei,
                      const float* __restrict__ alpha2, const unsigned* __restrict__ amax2,
                      float* __restrict__ ex2, float* __restrict__ den2)
{
    int e = blockIdx.x * blockDim.x + threadIdx.x;
    if (e >= ESL) return;
    int s, d; edge_sd(ei, e, s, d);
    float ex = expf(alpha2[e] - fdec(amax2[d]));
    ex2[e] = ex;
    atomicAdd(den2 + d, ex);
}

// Aggregation into g_final columns [0,512) with row stride 1536
__global__ void k_agg2(const int* __restrict__ ei, const float* __restrict__ xl2,
                       const float* __restrict__ ex2, const float* __restrict__ den2,
                       float* __restrict__ finalb)
{
    int warp = (blockIdx.x * blockDim.x + threadIdx.x) >> 5;
    int lane = threadIdx.x & 31;
    if (warp >= ESL) return;
    int s, d; edge_sd(ei, warp, s, d);
    float w = 0.f;
    if (lane == 0) w = ex2[warp] / (den2[d] + 1e-16f);
    w = __shfl_sync(0xffffffffu, w, 0);
    const float4* sp = (const float4*)(xl2 + (size_t)s * 512) + lane * 4;
    float* dp = finalb + (size_t)d * 1536 + lane * 16;
#pragma unroll
    for (int q = 0; q < 4; q++) {
        float4 v = sp[q];
        v.x *= w; v.y *= w; v.z *= w; v.w *= w;
        red_add_v4(dp + q * 4, v);
    }
}

__global__ void k_bias2(float* __restrict__ finalb, const float* __restrict__ b2)
{
    int idx = blockIdx.x * blockDim.x + threadIdx.x;
    if (idx >= NN * 512) return;
    int n = idx >> 9, c = idx & 511;
    finalb[(size_t)n * 1536 + c] += b2[c];
}

// ---------------------------------------------------------------------------
// Synapse: per-edge max-pool(4 pts x 6) -> relu(xp@We1+be1) [256] -> scatter
// (We2 applied at node level later; linearity of the second MLP layer)
// ---------------------------------------------------------------------------
__global__ void k_syn(const int* __restrict__ ei, const float* __restrict__ synapse,
                      const float* __restrict__ We1, const float* __restrict__ be1,
                      float* __restrict__ Hl, float* __restrict__ Hr,
                      float* __restrict__ cntL, float* __restrict__ cntR)
{
    int e = (blockIdx.x * blockDim.x + threadIdx.x) >> 5;
    int lane = threadIdx.x & 31;
    if (e >= EE) return;
    int s = ei[e], d = ei[EE + e];
    float m = 0.f;
    if (lane < 6) {
        const float* sp = synapse + (size_t)e * 24 + lane;
        m = sp[0];
        m = fmaxf(m, sp[6]);
        m = fmaxf(m, sp[12]);
        m = fmaxf(m, sp[18]);
    }
    float xp[6];
#pragma unroll
    for (int j = 0; j < 6; j++) xp[j] = __shfl_sync(0xffffffffu, m, j);

    float h[8];
#pragma unroll
    for (int o = 0; o < 8; o++) {
        int col = lane * 8 + o;
        float acc = be1[col];
#pragma unroll
        for (int k = 0; k < 6; k++) acc += xp[k] * We1[k * 256 + col];
        h[o] = fmaxf(acc, 0.f);
    }
    float* pl = Hl + (size_t)s * 256 + lane * 8;
    float* pr = Hr + (size_t)d * 256 + lane * 8;
    red_add_v4(pl,     make_float4(h[0], h[1], h[2], h[3]));
    red_add_v4(pl + 4, make_float4(h[4], h[5], h[6], h[7]));
    red_add_v4(pr,     make_float4(h[0], h[1], h[2], h[3]));
    red_add_v4(pr + 4, make_float4(h[4], h[5], h[6], h[7]));
    if (lane == 0) {
        atomicAdd(cntL + s, 1.f);
        atomicAdd(cntR + d, 1.f);
    }
}

__global__ void k_mean(float* __restrict__ Hl, float* __restrict__ Hr,
                       const float* __restrict__ cntL, const float* __restrict__ cntR,
                       float* __restrict__ bsL, float* __restrict__ bsR)
{
    int idx = blockIdx.x * blockDim.x + threadIdx.x;
    if (idx >= NN * 256) return;
    int n = idx >> 8;
    float cl = cntL[n], cr = cntR[n];
    Hl[idx] *= 1.f / fmaxf(cl, 1.f);
    Hr[idx] *= 1.f / fmaxf(cr, 1.f);
    if ((idx & 255) == 0) {
        bsL[n] = cl > 0.f ? 1.f : 0.f;
        bsR[n] = cr > 0.f ? 1.f : 0.f;
    }
}

// ---------------------------------------------------------------------------
// Host launcher
// ---------------------------------------------------------------------------
extern "C" void kernel_launch(void* const* d_in, const int* in_sizes, int n_in,
                              void* d_out, int out_size)
{
    const int*   ei      = (const int*)d_in[0];
    const float* synapse = (const float*)d_in[2];
    int ib = 4;
    if (n_in > 4 && in_sizes[4] == 1) ib = 5;   // skip scalar scatter_size if present
    const float* x_param = (const float*)d_in[ib + 0];
    const float* W1  = (const float*)d_in[ib + 1];
    const float* as1 = (const float*)d_in[ib + 2];
    const float* ad1 = (const float*)d_in[ib + 3];
    const float* b1  = (const float*)d_in[ib + 4];
    const float* W2  = (const float*)d_in[ib + 5];
    const float* as2 = (const float*)d_in[ib + 6];
    const float* ad2 = (const float*)d_in[ib + 7];
    const float* b2  = (const float*)d_in[ib + 8];
    const float* We1 = (const float*)d_in[ib + 9];
    const float* be1 = (const float*)d_in[ib + 10];
    const float* We2 = (const float*)d_in[ib + 11];
    const float* be2 = (const float*)d_in[ib + 12];
    const float* Wc1 = (const float*)d_in[ib + 13];
    const float* bc1 = (const float*)d_in[ib + 14];
    const float* Wc2 = (const float*)d_in[ib + 15];
    const float* bc2 = (const float*)d_in[ib + 16];
    float* out = (float*)d_out;

    void* sp = nullptr;
    cudaGetSymbolAddress(&sp, g_scratch);
    float* S = (float*)sp;

    float*    out1   = S + OFF_OUT1;
    float*    finalb = S + OFF_FINAL;
    float*    Hl     = S + OFF_HL;
    float*    Hr     = S + OFF_HR;
    unsigned* amax1  = (unsigned*)(S + OFF_AMAX1);
    float*    den1   = S + OFF_DEN1;
    unsigned* amax2  = (unsigned*)(S + OFF_AMAX2);
    float*    den2   = S + OFF_DEN2;
    float*    cntL   = S + OFF_CNTL;
    float*    cntR   = S + OFF_CNTR;
    float*    xl1    = S + OFF_XL1;
    float*    s1     = S + OFF_S1;
    float*    dd1    = S + OFF_DD1;
    float*    alpha1 = S + OFF_ALPHA1;
    float*    ex1    = S + OFF_EX1;
    float*    x1     = S + OFF_X1;
    float*    xl2    = S + OFF_XL2;
    float*    s2     = S + OFF_S2;
    float*    dd2    = S + OFF_DD2;
    float*    alpha2 = S + OFF_ALPHA2;
    float*    ex2    = S + OFF_EX2;
    float*    bsL    = S + OFF_BSL;
    float*    bsR    = S + OFF_BSR;
    float*    hidc   = S + OFF_HIDC;

    cudaMemsetAsync(S, 0, ZEND * sizeof(float));

    dim3 tpb(256);

    // GAT1
    {
        dim3 g((D1 + 127) / 128, (NN + 127) / 128);
        sgemm<<<g, tpb>>>(x_param, W1, xl1, NN, D1, FIN, FIN, D1, D1,
                          nullptr, nullptr, 0);
    }
    k_sd1<<<(NN * HEADS + 255) / 256, tpb>>>(xl1, as1, ad1, s1, dd1);
    k_alpha1<<<(ESL * HEADS + 255) / 256, tpb>>>(ei, s1, dd1, alpha1, amax1);
    k_ex1<<<(ESL * HEADS + 255) / 256, tpb>>>(ei, alpha1, amax1, ex1, den1);
    k_agg1<<<(ESL * 32 + 255) / 256, tpb>>>(ei, xl1, ex1, den1, out1);
    k_elu<<<(NN * 512 + 255) / 256, tpb>>>(out1, b1, x1);

    // GAT2 (writes into g_final cols [0,512))
    {
        dim3 g((REP + 127) / 128, (NN + 127) / 128);
        sgemm<<<g, tpb>>>(x1, W2, xl2, NN, REP, D1, D1, REP, REP,
                          nullptr, nullptr, 0);
    }
    k_sd2<<<(NN * 32 + 255) / 256, tpb>>>(xl2, as2, ad2, s2, dd2);
    k_alpha2<<<(ESL + 255) / 256, tpb>>>(ei, s2, dd2, alpha2, amax2);
    k_ex2<<<(ESL + 255) / 256, tpb>>>(ei, alpha2, amax2, ex2, den2);
    k_agg2<<<(ESL * 32 + 255) / 256, tpb>>>(ei, xl2, ex2, den2, finalb);
    k_bias2<<<(NN * 512 + 255) / 256, tpb>>>(finalb, b2);

    // Synapse encoder hidden + scatter means (256-dim, We2 folded to node level)
    k_syn<<<(EE * 32 + 255) / 256, tpb>>>(ei, synapse, We1, be1, Hl, Hr, cntL, cntR);
    k_mean<<<(NN * 256 + 255) / 256, tpb>>>(Hl, Hr, cntL, cntR, bsL, bsR);

    // left/right = mean(H) @ We2 + be2*(cnt>0) -> g_final cols [512,1024)/[1024,1536)
    {
        dim3 g((REP + 127) / 128, (NN + 127) / 128);
        sgemm<<<g, tpb>>>(Hl, We2, finalb + 512, NN, REP, 256, 256, REP, 1536,
                          be2, bsL, 0);
        sgemm<<<g, tpb>>>(Hr, We2, finalb + 1024, NN, REP, 256, 256, REP, 1536,
                          be2, bsR, 0);
    }

    // Classifier
    {
        dim3 g((512 + 127) / 128, (NN + 127) / 128);
        sgemm<<<g, tpb>>>(finalb, Wc1, hidc, NN, 512, 1536, 1536, 512, 512,
                          bc1, nullptr, 1);
    }
    {
        dim3 g((NCLS + 127) / 128, (NN + 127) / 128);
        sgemm<<<g, tpb>>>(hidc, Wc2, out, NN, NCLS, 512, 512, NCLS, NCLS,
                          bc2, nullptr, 0);
    }
}

// round 3
// speedup vs baseline: 1.6941x; 1.6941x over previous
#include <cuda_runtime.h>
#include <cuda_bf16.h>
#include <cstdint>

// ---------------------------------------------------------------------------
// Problem constants
// ---------------------------------------------------------------------------
constexpr int NN   = 20000;
constexpr int FIN  = 128;
constexpr int HEADS = 8;
constexpr int HIDC  = 64;
constexpr int D1    = HEADS * HIDC;  // 512
constexpr int REP   = 512;
constexpr int NCLS  = 133;
constexpr int EE    = 200000;
constexpr int ESL   = EE + NN;       // 220000

// ---------------------------------------------------------------------------
// fp32 scratch layout (zero-region first: one memset covers it)
// ---------------------------------------------------------------------------
constexpr size_t OFF_OUT1   = 0;
constexpr size_t OFF_FINAL  = OFF_OUT1   + (size_t)NN * 512;
constexpr size_t OFF_HL     = OFF_FINAL  + (size_t)NN * 1536;
constexpr size_t OFF_HR     = OFF_HL     + (size_t)NN * 256;
constexpr size_t OFF_AMAX1  = OFF_HR     + (size_t)NN * 256;
constexpr size_t OFF_DEN1   = OFF_AMAX1  + (size_t)NN * 8;
constexpr size_t OFF_AMAX2  = OFF_DEN1   + (size_t)NN * 8;
constexpr size_t OFF_DEN2   = OFF_AMAX2  + (size_t)NN;
constexpr size_t OFF_CNTL   = OFF_DEN2   + (size_t)NN;
constexpr size_t OFF_CNTR   = OFF_CNTL   + (size_t)NN;
constexpr size_t ZEND       = OFF_CNTR   + (size_t)NN;

constexpr size_t OFF_XL1    = ZEND;
constexpr size_t OFF_S1     = OFF_XL1    + (size_t)NN * 512;
constexpr size_t OFF_DD1    = OFF_S1     + (size_t)NN * 8;
constexpr size_t OFF_ALPHA1 = OFF_DD1    + (size_t)NN * 8;
constexpr size_t OFF_EX1    = OFF_ALPHA1 + (size_t)ESL * 8;
constexpr size_t OFF_X1     = OFF_EX1    + (size_t)ESL * 8;
constexpr size_t OFF_XL2    = OFF_X1     + (size_t)NN * 512;
constexpr size_t OFF_S2     = OFF_XL2    + (size_t)NN * 512;
constexpr size_t OFF_DD2    = OFF_S2     + (size_t)NN;
constexpr size_t OFF_ALPHA2 = OFF_DD2    + (size_t)NN;
constexpr size_t OFF_EX2    = OFF_ALPHA2 + (size_t)ESL;
constexpr size_t OFF_BSL    = OFF_EX2    + (size_t)ESL;
constexpr size_t OFF_BSR    = OFF_BSL    + (size_t)NN;
constexpr size_t OFF_HIDC   = OFF_BSR    + (size_t)NN;
constexpr size_t TOTALF     = OFF_HIDC   + (size_t)NN * 512;

__device__ float g_scratch[TOTALF];

// ---------------------------------------------------------------------------
// bf16 split scratch (hi/lo pairs). Weights stored transposed [NP, K].
// ---------------------------------------------------------------------------
constexpr size_t SZ_XP  = (size_t)NN * 128;
constexpr size_t SZ_X1  = (size_t)NN * 512;
constexpr size_t SZ_H   = (size_t)NN * 256;
constexpr size_t SZ_F   = (size_t)NN * 1536;
constexpr size_t SZ_HC  = (size_t)NN * 512;
constexpr size_t SZ_W1  = 512 * 128;
constexpr size_t SZ_W2  = 512 * 512;
constexpr size_t SZ_WE2 = 512 * 256;
constexpr size_t SZ_WC1 = 512 * 1536;
constexpr size_t SZ_WC2 = 256 * 512;

constexpr size_t B_XPH  = 0;
constexpr size_t B_XPL  = B_XPH  + SZ_XP;
constexpr size_t B_X1H  = B_XPL  + SZ_XP;
constexpr size_t B_X1L  = B_X1H  + SZ_X1;
constexpr size_t B_HLH  = B_X1L  + SZ_X1;
constexpr size_t B_HLL  = B_HLH  + SZ_H;
constexpr size_t B_HRH  = B_HLL  + SZ_H;
constexpr size_t B_HRL  = B_HRH  + SZ_H;
constexpr size_t B_FH   = B_HRL  + SZ_H;
constexpr size_t B_FL   = B_FH   + SZ_F;
constexpr size_t B_HCH  = B_FL   + SZ_F;
constexpr size_t B_HCL  = B_HCH  + SZ_HC;
constexpr size_t B_W1H  = B_HCL  + SZ_HC;
constexpr size_t B_W1L  = B_W1H  + SZ_W1;
constexpr size_t B_W2H  = B_W1L  + SZ_W1;
constexpr size_t B_W2L  = B_W2H  + SZ_W2;
constexpr size_t B_WE2H = B_W2L  + SZ_W2;
constexpr size_t B_WE2L = B_WE2H + SZ_WE2;
constexpr size_t B_WC1H = B_WE2L + SZ_WE2;
constexpr size_t B_WC1L = B_WC1H + SZ_WC1;
constexpr size_t B_WC2H = B_WC1L + SZ_WC1;
constexpr size_t B_WC2L = B_WC2H + SZ_WC2;
constexpr size_t TOTALB = B_WC2L + SZ_WC2;

__device__ __align__(256) __nv_bfloat16 g_bf[TOTALB];

// ---------------------------------------------------------------------------
// Portable PTX helpers (sm_80-baseline only: cp.async, ldmatrix, mma.sync)
// ---------------------------------------------------------------------------
__device__ __forceinline__ uint32_t smem_to_u32(const void* p) {
    uint32_t a;
    asm("{ .reg .u64 t; cvta.to.shared.u64 t, %1; cvt.u32.u64 %0, t; }"
        : "=r"(a) : "l"(p));
    return a;
}
#define SWZ(off) ((off) ^ (((off) >> 3) & 0x70))

// ---------------------------------------------------------------------------
// mma.sync GEMM: C[M, realN] = A[M,K] @ Wt^T  (Wt stored [NP,K], bf16 split)
// CTA 128x128, BK=64, cp.async double buffer, 3 passes (hh, hl, lh).
// ---------------------------------------------------------------------------
constexpr int TG_SMEM = 2 * 32768;   // 64 KB

__global__ __launch_bounds__(256)
void tgemm(const __nv_bfloat16* __restrict__ Ah, const __nv_bfloat16* __restrict__ Al,
           const __nv_bfloat16* __restrict__ Bh, const __nv_bfloat16* __restrict__ Bl,
           float* __restrict__ C, int M, int K, int realN, int ldc,
           const float* __restrict__ bias, const float* __restrict__ bscale, int relu)
{
    extern __shared__ __align__(1024) char smem[];
    const uint32_t sb = smem_to_u32(smem);
    const int tid = threadIdx.x;
    const int w = tid >> 5, l = tid & 31;
    const int m0 = blockIdx.x * 128, n0 = blockIdx.y * 128;
    const int wm = w & 1, wn = w >> 1;          // 2 x 4 warp grid, warp tile 64x32
    const int Kc = K >> 6;
    const int nch = 3 * Kc;

    float acc[4][4][4];
#pragma unroll
    for (int a = 0; a < 4; a++)
#pragma unroll
        for (int b = 0; b < 4; b++)
#pragma unroll
            for (int c = 0; c < 4; c++) acc[a][b][c] = 0.f;

    auto load_chunk = [&](int c, int st) {
        int part = c / Kc, kblk = c - part * Kc;
        const __nv_bfloat16* As = (part < 2) ? Ah : Al;
        const __nv_bfloat16* Bs = (part == 1) ? Bl : Bh;
        uint32_t abase = sb + st * 32768;
        uint32_t bbase = abase + 16384;
#pragma unroll
        for (int j = 0; j < 4; j++) {
            int id = tid + j * 256;
            int r = id >> 3, ck = id & 7;
            {
                int grow = m0 + r;
                const void* g = As + (size_t)grow * K + kblk * 64 + ck * 8;
                uint32_t d = abase + SWZ((uint32_t)(r * 128 + ck * 16));
                int sz = (grow < M) ? 16 : 0;
                asm volatile("cp.async.cg.shared.global [%0], [%1], 16, %2;"
                             :: "r"(d), "l"(g), "r"(sz));
            }
            {
                const void* g = Bs + (size_t)(n0 + r) * K + kblk * 64 + ck * 8;
                uint32_t d = bbase + SWZ((uint32_t)(r * 128 + ck * 16));
                asm volatile("cp.async.cg.shared.global [%0], [%1], 16;"
                             :: "r"(d), "l"(g));
            }
        }
        asm volatile("cp.async.commit_group;" ::: "memory");
    };

    auto compute = [&](int st) {
        uint32_t abase = sb + st * 32768;
        uint32_t bbase = abase + 16384;
#pragma unroll
        for (int ks = 0; ks < 4; ks++) {
            int kb = ks * 16;
            uint32_t af[4][4];
#pragma unroll
            for (int mt = 0; mt < 4; mt++) {
                int m = wm * 64 + mt * 16 + (l & 7) + ((l >> 3) & 1) * 8;
                int ke = kb + (l >> 4) * 8;
                uint32_t addr = abase + SWZ((uint32_t)(m * 128 + ke * 2));
                asm volatile("ldmatrix.sync.aligned.m8n8.x4.shared.b16 {%0,%1,%2,%3}, [%4];"
                             : "=r"(af[mt][0]), "=r"(af[mt][1]),
                               "=r"(af[mt][2]), "=r"(af[mt][3]) : "r"(addr));
            }
            uint32_t bf[4][2];
#pragma unroll
            for (int g = 0; g < 2; g++) {
                int n = wn * 32 + g * 16 + ((l >> 4) & 1) * 8 + (l & 7);
                int ke = kb + ((l >> 3) & 1) * 8;
                uint32_t addr = bbase + SWZ((uint32_t)(n * 128 + ke * 2));
                uint32_t r0, r1, r2, r3;
                asm volatile("ldmatrix.sync.aligned.m8n8.x4.shared.b16 {%0,%1,%2,%3}, [%4];"
                             : "=r"(r0), "=r"(r1), "=r"(r2), "=r"(r3) : "r"(addr));
                bf[2 * g][0] = r0; bf[2 * g][1] = r1;
                bf[2 * g + 1][0] = r2; bf[2 * g + 1][1] = r3;
            }
#pragma unroll
            for (int mt = 0; mt < 4; mt++)
#pragma unroll
                for (int nt = 0; nt < 4; nt++) {
                    asm volatile(
                        "mma.sync.aligned.m16n8k16.row.col.f32.bf16.bf16.f32 "
                        "{%0,%1,%2,%3}, {%4,%5,%6,%7}, {%8,%9}, {%0,%1,%2,%3};"
                        : "+f"(acc[mt][nt][0]), "+f"(acc[mt][nt][1]),
                          "+f"(acc[mt][nt][2]), "+f"(acc[mt][nt][3])
                        : "r"(af[mt][0]), "r"(af[mt][1]), "r"(af[mt][2]), "r"(af[mt][3]),
                          "r"(bf[nt][0]), "r"(bf[nt][1]));
                }
        }
    };

    load_chunk(0, 0);
    for (int c = 0; c < nch; c++) {
        asm volatile("cp.async.wait_group 0;" ::: "memory");
        __syncthreads();
        if (c + 1 < nch) load_chunk(c + 1, (c + 1) & 1);
        compute(c & 1);
    }

    // Epilogue: direct register -> gmem
    const int rbase = m0 + wm * 64, cbase = n0 + wn * 32;
#pragma unroll
    for (int mt = 0; mt < 4; mt++) {
#pragma unroll
        for (int half = 0; half < 2; half++) {
            int row = rbase + mt * 16 + (l >> 2) + half * 8;
            if (row >= M) continue;
            float bs = 1.f;
            if (bias && bscale) bs = bscale[row];
#pragma unroll
            for (int nt = 0; nt < 4; nt++) {
                int col = cbase + nt * 8 + (l & 3) * 2;
#pragma unroll
                for (int q = 0; q < 2; q++) {
                    int cc = col + q;
                    if (cc >= realN) continue;
                    float v = acc[mt][nt][half * 2 + q];
                    if (bias) v += bias[cc] * bs;
                    if (relu) v = fmaxf(v, 0.f);
                    C[(size_t)row * ldc + cc] = v;
                }
            }
        }
    }
}

// ---------------------------------------------------------------------------
// bf16 split preps
// ---------------------------------------------------------------------------
__global__ void k_split(const float* __restrict__ x, __nv_bfloat16* __restrict__ h,
                        __nv_bfloat16* __restrict__ l, int n)
{
    int i = blockIdx.x * blockDim.x + threadIdx.x;
    if (i >= n) return;
    float v = x[i];
    __nv_bfloat16 hi = __float2bfloat16(v);
    h[i] = hi;
    l[i] = __float2bfloat16(v - __bfloat162float(hi));
}

// W [K,N] fp32 -> hi/lo [NP,K] bf16 (transposed, zero-padded rows)
__global__ void k_wprep(const float* __restrict__ W, __nv_bfloat16* __restrict__ h,
                        __nv_bfloat16* __restrict__ l, int K, int N, int NP)
{
    int i = blockIdx.x * blockDim.x + threadIdx.x;
    if (i >= NP * K) return;
    int n = i / K, k = i - n * K;
    float v = (n < N) ? W[(size_t)k * N + n] : 0.f;
    __nv_bfloat16 hi = __float2bfloat16(v);
    h[i] = hi;
    l[i] = __float2bfloat16(v - __bfloat162float(hi));
}

// ---------------------------------------------------------------------------
// Graph/scatter helpers
// ---------------------------------------------------------------------------
__device__ __forceinline__ unsigned fenc(float f) {
    unsigned u = __float_as_uint(f);
    return (u & 0x80000000u) ? ~u : (u | 0x80000000u);
}
__device__ __forceinline__ float fdec(unsigned u) {
    return (u & 0x80000000u) ? __uint_as_float(u & 0x7FFFFFFFu) : __uint_as_float(~u);
}
__device__ __forceinline__ void red_add_v4(float* p, float4 v) {
    asm volatile("red.global.add.v4.f32 [%0], {%1,%2,%3,%4};"
                 :: "l"(p), "f"(v.x), "f"(v.y), "f"(v.z), "f"(v.w) : "memory");
}
__device__ __forceinline__ void edge_sd(const int* __restrict__ ei, int e, int& s, int& d) {
    if (e < EE) { s = ei[e]; d = ei[EE + e]; }
    else        { s = d = e - EE; }
}
__device__ __forceinline__ float lrelu02(float x) { return x > 0.f ? x : 0.2f * x; }

__global__ void k_sd1(const float* __restrict__ xl1,
                      const float* __restrict__ as1, const float* __restrict__ ad1,
                      float* __restrict__ s1, float* __restrict__ d1)
{
    int idx = blockIdx.x * blockDim.x + threadIdx.x;
    if (idx >= NN * HEADS) return;
    int n = idx >> 3, h = idx & 7;
    const float4* xr = (const float4*)(xl1 + (size_t)n * 512 + h * 64);
    const float4* av = (const float4*)(as1 + h * 64);
    const float4* bv = (const float4*)(ad1 + h * 64);
    float ss = 0.f, dd = 0.f;
#pragma unroll
    for (int q = 0; q < 16; q++) {
        float4 x = xr[q], a = av[q], b = bv[q];
        ss += x.x * a.x + x.y * a.y + x.z * a.z + x.w * a.w;
        dd += x.x * b.x + x.y * b.y + x.z * b.z + x.w * b.w;
    }
    s1[idx] = ss; d1[idx] = dd;
}

__global__ void k_alpha1(const int* __restrict__ ei,
                         const float* __restrict__ s1, const float* __restrict__ d1,
                         float* __restrict__ alpha1, unsigned* __restrict__ amax1)
{
    int idx = blockIdx.x * blockDim.x + threadIdx.x;
    if (idx >= ESL * HEADS) return;
    int e = idx >> 3, h = idx & 7;
    int s, d; edge_sd(ei, e, s, d);
    float a = lrelu02(s1[s * 8 + h] + d1[d * 8 + h]);
    alpha1[idx] = a;
    atomicMax(amax1 + d * 8 + h, fenc(a));
}

__global__ void k_ex1(const int* __restrict__ ei,
                      const float* __restrict__ alpha1, const unsigned* __restrict__ amax1,
                      float* __restrict__ ex1, float* __restrict__ den1)
{
    int idx = blockIdx.x * blockDim.x + threadIdx.x;
    if (idx >= ESL * HEADS) return;
    int e = idx >> 3, h = idx & 7;
    int s, d; edge_sd(ei, e, s, d);
    float ex = expf(alpha1[idx] - fdec(amax1[d * 8 + h]));
    ex1[idx] = ex;
    atomicAdd(den1 + d * 8 + h, ex);
}

__global__ void k_agg1(const int* __restrict__ ei, const float* __restrict__ xl1,
                       const float* __restrict__ ex1, const float* __restrict__ den1,
                       float* __restrict__ out1)
{
    int warp = (blockIdx.x * blockDim.x + threadIdx.x) >> 5;
    int lane = threadIdx.x & 31;
    if (warp >= ESL) return;
    int s, d; edge_sd(ei, warp, s, d);
    float w = 0.f;
    if (lane < 8) w = ex1[(size_t)warp * 8 + lane] / (den1[d * 8 + lane] + 1e-16f);
    float wh = __shfl_sync(0xffffffffu, w, lane >> 2);
    const float4* sp = (const float4*)(xl1 + (size_t)s * 512) + lane * 4;
    float* dp = out1 + (size_t)d * 512 + lane * 16;
#pragma unroll
    for (int q = 0; q < 4; q++) {
        float4 v = sp[q];
        v.x *= wh; v.y *= wh; v.z *= wh; v.w *= wh;
        red_add_v4(dp + q * 4, v);
    }
}

__global__ void k_elu(const float* __restrict__ out1, const float* __restrict__ b1,
                      float* __restrict__ x1)
{
    int idx = blockIdx.x * blockDim.x + threadIdx.x;
    if (idx >= NN * 512) return;
    float v = out1[idx] + b1[idx & 511];
    x1[idx] = v > 0.f ? v : expm1f(v);
}

__global__ void k_sd2(const float* __restrict__ xl2,
                      const float* __restrict__ as2, const float* __restrict__ ad2,
                      float* __restrict__ s2, float* __restrict__ d2)
{
    int warp = (blockIdx.x * blockDim.x + threadIdx.x) >> 5;
    int lane = threadIdx.x & 31;
    if (warp >= NN) return;
    const float4* xr = (const float4*)(xl2 + (size_t)warp * 512) + lane * 4;
    const float4* av = (const float4*)as2 + lane * 4;
    const float4* bv = (const float4*)ad2 + lane * 4;
    float ss = 0.f, dd = 0.f;
#pragma unroll
    for (int q = 0; q < 4; q++) {
        float4 x = xr[q], a = av[q], b = bv[q];
        ss += x.x * a.x + x.y * a.y + x.z * a.z + x.w * a.w;
        dd += x.x * b.x + x.y * b.y + x.z * b.z + x.w * b.w;
    }
#pragma unroll
    for (int o = 16; o > 0; o >>= 1) {
        ss += __shfl_xor_sync(0xffffffffu, ss, o);
        dd += __shfl_xor_sync(0xffffffffu, dd, o);
    }
    if (lane == 0) { s2[warp] = ss; d2[warp] = dd; }
}

__global__ void k_alpha2(const int* __restrict__ ei,
                         const float* __restrict__ s2, const float* __restrict__ d2,
                         float* __restrict__ alpha2, unsigned* __restrict__ amax2)
{
    int e = blockIdx.x * blockDim.x + threadIdx.x;
    if (e >= ESL) return;
    int s, d; edge_sd(ei, e, s, d);
    float a = lrelu02(s2[s] + d2[d]);
    alpha2[e] = a;
    atomicMax(amax2 + d, fenc(a));
}

__global__ void k_ex2(const int* __restrict__ ei,
                      const float* __restrict__ alpha2, const unsigned* __restrict__ amax2,
                      float* __restrict__ ex2, float* __restrict__ den2)
{
    int e = blockIdx.x * blockDim.x + threadIdx.x;
    if (e >= ESL) return;
    int s, d; edge_sd(ei, e, s, d);
    float ex = expf(alpha2[e] - fdec(amax2[d]));
    ex2[e] = ex;
    atomicAdd(den2 + d, ex);
}

__global__ void k_agg2(const int* __restrict__ ei, const float* __restrict__ xl2,
                       const float* __restrict__ ex2, const float* __restrict__ den2,
                       float* __restrict__ finalb)
{
    int warp = (blockIdx.x * blockDim.x + threadIdx.x) >> 5;
    int lane = threadIdx.x & 31;
    if (warp >= ESL) return;
    int s, d; edge_sd(ei, warp, s, d);
    float w = 0.f;
    if (lane == 0) w = ex2[warp] / (den2[d] + 1e-16f);
    w = __shfl_sync(0xffffffffu, w, 0);
    const float4* sp = (const float4*)(xl2 + (size_t)s * 512) + lane * 4;
    float* dp = finalb + (size_t)d * 1536 + lane * 16;
#pragma unroll
    for (int q = 0; q < 4; q++) {
        float4 v = sp[q];
        v.x *= w; v.y *= w; v.z *= w; v.w *= w;
        red_add_v4(dp + q * 4, v);
    }
}

__global__ void k_bias2(float* __restrict__ finalb, const float* __restrict__ b2)
{
    int idx = blockIdx.x * blockDim.x + threadIdx.x;
    if (idx >= NN * 512) return;
    int n = idx >> 9, c = idx & 511;
    finalb[(size_t)n * 1536 + c] += b2[c];
}

__global__ void k_syn(const int* __restrict__ ei, const float* __restrict__ synapse,
                      const float* __restrict__ We1, const float* __restrict__ be1,
                      float* __restrict__ Hl, float* __restrict__ Hr,
                      float* __restrict__ cntL, float* __restrict__ cntR)
{
    int e = (blockIdx.x * blockDim.x + threadIdx.x) >> 5;
    int lane = threadIdx.x & 31;
    if (e >= EE) return;
    int s = ei[e], d = ei[EE + e];
    float m = 0.f;
    if (lane < 6) {
        const float* sp = synapse + (size_t)e * 24 + lane;
        m = sp[0];
        m = fmaxf(m, sp[6]);
        m = fmaxf(m, sp[12]);
        m = fmaxf(m, sp[18]);
    }
    float xp[6];
#pragma unroll
    for (int j = 0; j < 6; j++) xp[j] = __shfl_sync(0xffffffffu, m, j);

    float h[8];
#pragma unroll
    for (int o = 0; o < 8; o++) {
        int col = lane * 8 + o;
        float acc = be1[col];
#pragma unroll
        for (int k = 0; k < 6; k++) acc += xp[k] * We1[k * 256 + col];
        h[o] = fmaxf(acc, 0.f);
    }
    float* pl = Hl + (size_t)s * 256 + lane * 8;
    float* pr = Hr + (size_t)d * 256 + lane * 8;
    red_add_v4(pl,     make_float4(h[0], h[1], h[2], h[3]));
    red_add_v4(pl + 4, make_float4(h[4], h[5], h[6], h[7]));
    red_add_v4(pr,     make_float4(h[0], h[1], h[2], h[3]));
    red_add_v4(pr + 4, make_float4(h[4], h[5], h[6], h[7]));
    if (lane == 0) {
        atomicAdd(cntL + s, 1.f);
        atomicAdd(cntR + d, 1.f);
    }
}

__global__ void k_mean(float* __restrict__ Hl, float* __restrict__ Hr,
                       const float* __restrict__ cntL, const float* __restrict__ cntR,
                       float* __restrict__ bsL, float* __restrict__ bsR)
{
    int idx = blockIdx.x * blockDim.x + threadIdx.x;
    if (idx >= NN * 256) return;
    int n = idx >> 8;
    float cl = cntL[n], cr = cntR[n];
    Hl[idx] *= 1.f / fmaxf(cl, 1.f);
    Hr[idx] *= 1.f / fmaxf(cr, 1.f);
    if ((idx & 255) == 0) {
        bsL[n] = cl > 0.f ? 1.f : 0.f;
        bsR[n] = cr > 0.f ? 1.f : 0.f;
    }
}

// ---------------------------------------------------------------------------
// Host launcher
// ---------------------------------------------------------------------------
extern "C" void kernel_launch(void* const* d_in, const int* in_sizes, int n_in,
                              void* d_out, int out_size)
{
    const int*   ei      = (const int*)d_in[0];
    const float* synapse = (const float*)d_in[2];
    int ib = 4;
    if (n_in > 4 && in_sizes[4] == 1) ib = 5;
    const float* x_param = (const float*)d_in[ib + 0];
    const float* W1  = (const float*)d_in[ib + 1];
    const float* as1 = (const float*)d_in[ib + 2];
    const float* ad1 = (const float*)d_in[ib + 3];
    const float* b1  = (const float*)d_in[ib + 4];
    const float* W2  = (const float*)d_in[ib + 5];
    const float* as2 = (const float*)d_in[ib + 6];
    const float* ad2 = (const float*)d_in[ib + 7];
    const float* b2  = (const float*)d_in[ib + 8];
    const float* We1 = (const float*)d_in[ib + 9];
    const float* be1 = (const float*)d_in[ib + 10];
    const float* We2 = (const float*)d_in[ib + 11];
    const float* be2 = (const float*)d_in[ib + 12];
    const float* Wc1 = (const float*)d_in[ib + 13];
    const float* bc1 = (const float*)d_in[ib + 14];
    const float* Wc2 = (const float*)d_in[ib + 15];
    const float* bc2 = (const float*)d_in[ib + 16];
    float* out = (float*)d_out;

    void* sp = nullptr;
    cudaGetSymbolAddress(&sp, g_scratch);
    float* S = (float*)sp;
    void* bp = nullptr;
    cudaGetSymbolAddress(&bp, g_bf);
    __nv_bfloat16* B = (__nv_bfloat16*)bp;

    cudaFuncSetAttribute(tgemm, cudaFuncAttributeMaxDynamicSharedMemorySize, TG_SMEM);

    float*    out1   = S + OFF_OUT1;
    float*    finalb = S + OFF_FINAL;
    float*    Hl     = S + OFF_HL;
    float*    Hr     = S + OFF_HR;
    unsigned* amax1  = (unsigned*)(S + OFF_AMAX1);
    float*    den1   = S + OFF_DEN1;
    unsigned* amax2  = (unsigned*)(S + OFF_AMAX2);
    float*    den2   = S + OFF_DEN2;
    float*    cntL   = S + OFF_CNTL;
    float*    cntR   = S + OFF_CNTR;
    float*    xl1    = S + OFF_XL1;
    float*    s1     = S + OFF_S1;
    float*    dd1    = S + OFF_DD1;
    float*    alpha1 = S + OFF_ALPHA1;
    float*    ex1    = S + OFF_EX1;
    float*    x1     = S + OFF_X1;
    float*    xl2    = S + OFF_XL2;
    float*    s2     = S + OFF_S2;
    float*    dd2    = S + OFF_DD2;
    float*    alpha2 = S + OFF_ALPHA2;
    float*    ex2    = S + OFF_EX2;
    float*    bsL    = S + OFF_BSL;
    float*    bsR    = S + OFF_BSR;
    float*    hidc   = S + OFF_HIDC;

    cudaMemsetAsync(S, 0, ZEND * sizeof(float));

    dim3 tpb(256);
    const int MT = (NN + 127) / 128;   // 157 M-tiles

    // Weight preps (transposed bf16 splits)
    k_wprep<<<(512 * 128  + 255) / 256, tpb>>>(W1,  B + B_W1H,  B + B_W1L,  128,  D1,  512);
    k_wprep<<<(512 * 512  + 255) / 256, tpb>>>(W2,  B + B_W2H,  B + B_W2L,  512,  REP, 512);
    k_wprep<<<(512 * 256  + 255) / 256, tpb>>>(We2, B + B_WE2H, B + B_WE2L, 256,  REP, 512);
    k_wprep<<<(512 * 1536 + 255) / 256, tpb>>>(Wc1, B + B_WC1H, B + B_WC1L, 1536, 512, 512);
    k_wprep<<<(256 * 512  + 255) / 256, tpb>>>(Wc2, B + B_WC2H, B + B_WC2L, 512,  NCLS, 256);

    // GAT1
    k_split<<<((int)SZ_XP + 255) / 256, tpb>>>(x_param, B + B_XPH, B + B_XPL, (int)SZ_XP);
    {
        dim3 g(MT, 4);
        tgemm<<<g, tpb, TG_SMEM>>>(B + B_XPH, B + B_XPL, B + B_W1H, B + B_W1L,
                                   xl1, NN, FIN, D1, D1, nullptr, nullptr, 0);
    }
    k_sd1<<<(NN * HEADS + 255) / 256, tpb>>>(xl1, as1, ad1, s1, dd1);
    k_alpha1<<<(ESL * HEADS + 255) / 256, tpb>>>(ei, s1, dd1, alpha1, amax1);
    k_ex1<<<(ESL * HEADS + 255) / 256, tpb>>>(ei, alpha1, amax1, ex1, den1);
    k_agg1<<<(ESL * 32 + 255) / 256, tpb>>>(ei, xl1, ex1, den1, out1);
    k_elu<<<(NN * 512 + 255) / 256, tpb>>>(out1, b1, x1);

    // GAT2
    k_split<<<((int)SZ_X1 + 255) / 256, tpb>>>(x1, B + B_X1H, B + B_X1L, (int)SZ_X1);
    {
        dim3 g(MT, 4);
        tgemm<<<g, tpb, TG_SMEM>>>(B + B_X1H, B + B_X1L, B + B_W2H, B + B_W2L,
                                   xl2, NN, D1, REP, REP, nullptr, nullptr, 0);
    }
    k_sd2<<<(NN * 32 + 255) / 256, tpb>>>(xl2, as2, ad2, s2, dd2);
    k_alpha2<<<(ESL + 255) / 256, tpb>>>(ei, s2, dd2, alpha2, amax2);
    k_ex2<<<(ESL + 255) / 256, tpb>>>(ei, alpha2, amax2, ex2, den2);
    k_agg2<<<(ESL * 32 + 255) / 256, tpb>>>(ei, xl2, ex2, den2, finalb);
    k_bias2<<<(NN * 512 + 255) / 256, tpb>>>(finalb, b2);

    // Synapse encoder hidden + scatter means
    k_syn<<<(EE * 32 + 255) / 256, tpb>>>(ei, synapse, We1, be1, Hl, Hr, cntL, cntR);
    k_mean<<<(NN * 256 + 255) / 256, tpb>>>(Hl, Hr, cntL, cntR, bsL, bsR);

    // left/right = mean(H) @ We2 + be2*(cnt>0)
    k_split<<<((int)SZ_H + 255) / 256, tpb>>>(Hl, B + B_HLH, B + B_HLL, (int)SZ_H);
    k_split<<<((int)SZ_H + 255) / 256, tpb>>>(Hr, B + B_HRH, B + B_HRL, (int)SZ_H);
    {
        dim3 g(MT, 4);
        tgemm<<<g, tpb, TG_SMEM>>>(B + B_HLH, B + B_HLL, B + B_WE2H, B + B_WE2L,
                                   finalb + 512, NN, 256, REP, 1536, be2, bsL, 0);
        tgemm<<<g, tpb, TG_SMEM>>>(B + B_HRH, B + B_HRL, B + B_WE2H, B + B_WE2L,
                                   finalb + 1024, NN, 256, REP, 1536, be2, bsR, 0);
    }

    // Classifier
    k_split<<<((int)SZ_F + 255) / 256, tpb>>>(finalb, B + B_FH, B + B_FL, (int)SZ_F);
    {
        dim3 g(MT, 4);
        tgemm<<<g, tpb, TG_SMEM>>>(B + B_FH, B + B_FL, B + B_WC1H, B + B_WC1L,
                                   hidc, NN, 1536, 512, 512, bc1, nullptr, 1);
    }
    k_split<<<((int)SZ_HC + 255) / 256, tpb>>>(hidc, B + B_HCH, B + B_HCL, (int)SZ_HC);
    {
        dim3 g(MT, 2);
        tgemm<<<g, tpb, TG_SMEM>>>(B + B_HCH, B + B_HCL, B + B_WC2H, B + B_WC2L,
                                   out, NN, 512, NCLS, NCLS, bc2, nullptr, 0);
    }
}

// round 4
// speedup vs baseline: 2.1189x; 1.2508x over previous
#include <cuda_runtime.h>
#include <cuda_bf16.h>
#include <cstdint>

// ---------------------------------------------------------------------------
// Problem constants
// ---------------------------------------------------------------------------
constexpr int NN   = 20000;
constexpr int FIN  = 128;
constexpr int HEADS = 8;
constexpr int HIDC  = 64;
constexpr int D1    = HEADS * HIDC;  // 512
constexpr int REP   = 512;
constexpr int NCLS  = 133;
constexpr int EE    = 200000;
constexpr int ESL   = EE + NN;       // 220000

// ---------------------------------------------------------------------------
// fp32 scratch layout (zero-region first: one memset covers it)
// G = [x(512) | meanHl(256) | meanHr(256)] per node, width 1024
// ---------------------------------------------------------------------------
constexpr size_t OFF_OUT1   = 0;
constexpr size_t OFF_G      = OFF_OUT1   + (size_t)NN * 512;   // NN*1024
constexpr size_t OFF_AMAX1  = OFF_G      + (size_t)NN * 1024;
constexpr size_t OFF_DEN1   = OFF_AMAX1  + (size_t)NN * 8;
constexpr size_t OFF_AMAX2  = OFF_DEN1   + (size_t)NN * 8;
constexpr size_t OFF_DEN2   = OFF_AMAX2  + (size_t)NN;
constexpr size_t OFF_CNTL   = OFF_DEN2   + (size_t)NN;
constexpr size_t OFF_CNTR   = OFF_CNTL   + (size_t)NN;
constexpr size_t ZEND       = OFF_CNTR   + (size_t)NN;

constexpr size_t OFF_XL1    = ZEND;
constexpr size_t OFF_S1     = OFF_XL1    + (size_t)NN * 512;
constexpr size_t OFF_DD1    = OFF_S1     + (size_t)NN * 8;
constexpr size_t OFF_ALPHA1 = OFF_DD1    + (size_t)NN * 8;   // ESL*8 (also reused as WcombL/R fp32 temp early)
constexpr size_t OFF_EX1    = OFF_ALPHA1 + (size_t)ESL * 8;
constexpr size_t OFF_X1     = OFF_EX1    + (size_t)ESL * 8;
constexpr size_t OFF_XL2    = OFF_X1     + (size_t)NN * 512;
constexpr size_t OFF_S2     = OFF_XL2    + (size_t)NN * 512;
constexpr size_t OFF_DD2    = OFF_S2     + (size_t)NN;
constexpr size_t OFF_ALPHA2 = OFF_DD2    + (size_t)NN;
constexpr size_t OFF_EX2    = OFF_ALPHA2 + (size_t)ESL;
constexpr size_t OFF_BSL    = OFF_EX2    + (size_t)ESL;
constexpr size_t OFF_BSR    = OFF_BSL    + (size_t)NN;
constexpr size_t OFF_HIDC   = OFF_BSR    + (size_t)NN;
constexpr size_t OFF_VL     = OFF_HIDC   + (size_t)NN * 512;
constexpr size_t OFF_VR     = OFF_VL     + 512;
constexpr size_t TOTALF     = OFF_VR     + 512;

__device__ float g_scratch[TOTALF];

// ---------------------------------------------------------------------------
// bf16 split scratch (hi/lo pairs). Weights stored transposed [NP, K].
// ---------------------------------------------------------------------------
constexpr size_t SZ_XP   = (size_t)NN * 128;
constexpr size_t SZ_X1   = (size_t)NN * 512;
constexpr size_t SZ_G    = (size_t)NN * 1024;
constexpr size_t SZ_HC   = (size_t)NN * 512;
constexpr size_t SZ_W1   = 512 * 128;
constexpr size_t SZ_W2   = 512 * 512;
constexpr size_t SZ_WB   = 512 * 1024;   // fused classifier weight [512, 1024]
constexpr size_t SZ_WC2  = 256 * 512;
constexpr size_t SZ_WM   = 512 * 512;    // Wc1 mid/bot transposed temps
constexpr size_t SZ_WE2A = 256 * 512;    // We2 as A-side [256,512]

constexpr size_t B_XPH   = 0;
constexpr size_t B_XPL   = B_XPH   + SZ_XP;
constexpr size_t B_X1H   = B_XPL   + SZ_XP;
constexpr size_t B_X1L   = B_X1H   + SZ_X1;
constexpr size_t B_GH    = B_X1L   + SZ_X1;
constexpr size_t B_GL    = B_GH    + SZ_G;
constexpr size_t B_HCH   = B_GL    + SZ_G;
constexpr size_t B_HCL   = B_HCH   + SZ_HC;
constexpr size_t B_W1H   = B_HCL   + SZ_HC;
constexpr size_t B_W1L   = B_W1H   + SZ_W1;
constexpr size_t B_W2H   = B_W1L   + SZ_W1;
constexpr size_t B_W2L   = B_W2H   + SZ_W2;
constexpr size_t B_WBH   = B_W2L   + SZ_W2;
constexpr size_t B_WBL   = B_WBH   + SZ_WB;
constexpr size_t B_WC2H  = B_WBL   + SZ_WB;
constexpr size_t B_WC2L  = B_WC2H  + SZ_WC2;
constexpr size_t B_WM1H  = B_WC2L  + SZ_WC2;
constexpr size_t B_WM1L  = B_WM1H  + SZ_WM;
constexpr size_t B_WM2H  = B_WM1L  + SZ_WM;
constexpr size_t B_WM2L  = B_WM2H  + SZ_WM;
constexpr size_t B_WE2AH = B_WM2L  + SZ_WM;
constexpr size_t B_WE2AL = B_WE2AH + SZ_WE2A;
constexpr size_t TOTALB  = B_WE2AL + SZ_WE2A;

__device__ __align__(256) __nv_bfloat16 g_bf[TOTALB];

// ---------------------------------------------------------------------------
// Portable PTX helpers (sm_80-baseline only: cp.async, ldmatrix, mma.sync)
// ---------------------------------------------------------------------------
__device__ __forceinline__ uint32_t smem_to_u32(const void* p) {
    uint32_t a;
    asm("{ .reg .u64 t; cvta.to.shared.u64 t, %1; cvt.u32.u64 %0, t; }"
        : "=r"(a) : "l"(p));
    return a;
}
#define SWZ(off) ((off) ^ (((off) >> 3) & 0x70))

// ---------------------------------------------------------------------------
// mma.sync GEMM: C[M, realN] = A[M,K] @ Wt^T  (Wt stored [NP,K], bf16 split)
// CTA 128x128, BK=64, cp.async double buffer, 3 passes (hh, hl, lh).
// Epilogue: v = acc + bias[c] + s1[row]*v1[c] + s2[row]*v2[c]; optional relu.
// ---------------------------------------------------------------------------
constexpr int TG_SMEM = 2 * 32768;   // 64 KB

__global__ __launch_bounds__(256)
void tgemm(const __nv_bfloat16* __restrict__ Ah, const __nv_bfloat16* __restrict__ Al,
           const __nv_bfloat16* __restrict__ Bh, const __nv_bfloat16* __restrict__ Bl,
           float* __restrict__ C, int M, int K, int realN, int ldc,
           const float* __restrict__ bias,
           const float* __restrict__ v1, const float* __restrict__ s1,
           const float* __restrict__ v2, const float* __restrict__ s2,
           int relu)
{
    extern __shared__ __align__(1024) char smem[];
    const uint32_t sb = smem_to_u32(smem);
    const int tid = threadIdx.x;
    const int w = tid >> 5, l = tid & 31;
    const int m0 = blockIdx.x * 128, n0 = blockIdx.y * 128;
    const int wm = w & 1, wn = w >> 1;          // 2 x 4 warp grid, warp tile 64x32
    const int Kc = K >> 6;
    const int nch = 3 * Kc;

    float acc[4][4][4];
#pragma unroll
    for (int a = 0; a < 4; a++)
#pragma unroll
        for (int b = 0; b < 4; b++)
#pragma unroll
            for (int c = 0; c < 4; c++) acc[a][b][c] = 0.f;

    auto load_chunk = [&](int c, int st) {
        int part = c / Kc, kblk = c - part * Kc;
        const __nv_bfloat16* As = (part < 2) ? Ah : Al;
        const __nv_bfloat16* Bs = (part == 1) ? Bl : Bh;
        uint32_t abase = sb + st * 32768;
        uint32_t bbase = abase + 16384;
#pragma unroll
        for (int j = 0; j < 4; j++) {
            int id = tid + j * 256;
            int r = id >> 3, ck = id & 7;
            {
                int grow = m0 + r;
                const void* g = As + (size_t)grow * K + kblk * 64 + ck * 8;
                uint32_t d = abase + SWZ((uint32_t)(r * 128 + ck * 16));
                int sz = (grow < M) ? 16 : 0;
                asm volatile("cp.async.cg.shared.global [%0], [%1], 16, %2;"
                             :: "r"(d), "l"(g), "r"(sz));
            }
            {
                const void* g = Bs + (size_t)(n0 + r) * K + kblk * 64 + ck * 8;
                uint32_t d = bbase + SWZ((uint32_t)(r * 128 + ck * 16));
                asm volatile("cp.async.cg.shared.global [%0], [%1], 16;"
                             :: "r"(d), "l"(g));
            }
        }
        asm volatile("cp.async.commit_group;" ::: "memory");
    };

    auto compute = [&](int st) {
        uint32_t abase = sb + st * 32768;
        uint32_t bbase = abase + 16384;
#pragma unroll
        for (int ks = 0; ks < 4; ks++) {
            int kb = ks * 16;
            uint32_t af[4][4];
#pragma unroll
            for (int mt = 0; mt < 4; mt++) {
                int m = wm * 64 + mt * 16 + (l & 7) + ((l >> 3) & 1) * 8;
                int ke = kb + (l >> 4) * 8;
                uint32_t addr = abase + SWZ((uint32_t)(m * 128 + ke * 2));
                asm volatile("ldmatrix.sync.aligned.m8n8.x4.shared.b16 {%0,%1,%2,%3}, [%4];"
                             : "=r"(af[mt][0]), "=r"(af[mt][1]),
                               "=r"(af[mt][2]), "=r"(af[mt][3]) : "r"(addr));
            }
            uint32_t bf[4][2];
#pragma unroll
            for (int g = 0; g < 2; g++) {
                int n = wn * 32 + g * 16 + ((l >> 4) & 1) * 8 + (l & 7);
                int ke = kb + ((l >> 3) & 1) * 8;
                uint32_t addr = bbase + SWZ((uint32_t)(n * 128 + ke * 2));
                uint32_t r0, r1, r2, r3;
                asm volatile("ldmatrix.sync.aligned.m8n8.x4.shared.b16 {%0,%1,%2,%3}, [%4];"
                             : "=r"(r0), "=r"(r1), "=r"(r2), "=r"(r3) : "r"(addr));
                bf[2 * g][0] = r0; bf[2 * g][1] = r1;
                bf[2 * g + 1][0] = r2; bf[2 * g + 1][1] = r3;
            }
#pragma unroll
            for (int mt = 0; mt < 4; mt++)
#pragma unroll
                for (int nt = 0; nt < 4; nt++) {
                    asm volatile(
                        "mma.sync.aligned.m16n8k16.row.col.f32.bf16.bf16.f32 "
                        "{%0,%1,%2,%3}, {%4,%5,%6,%7}, {%8,%9}, {%0,%1,%2,%3};"
                        : "+f"(acc[mt][nt][0]), "+f"(acc[mt][nt][1]),
                          "+f"(acc[mt][nt][2]), "+f"(acc[mt][nt][3])
                        : "r"(af[mt][0]), "r"(af[mt][1]), "r"(af[mt][2]), "r"(af[mt][3]),
                          "r"(bf[nt][0]), "r"(bf[nt][1]));
                }
        }
    };

    load_chunk(0, 0);
    for (int c = 0; c < nch; c++) {
        asm volatile("cp.async.wait_group 0;" ::: "memory");
        __syncthreads();
        if (c + 1 < nch) load_chunk(c + 1, (c + 1) & 1);
        compute(c & 1);
    }

    // Epilogue: direct register -> gmem
    const int rbase = m0 + wm * 64, cbase = n0 + wn * 32;
#pragma unroll
    for (int mt = 0; mt < 4; mt++) {
#pragma unroll
        for (int half = 0; half < 2; half++) {
            int row = rbase + mt * 16 + (l >> 2) + half * 8;
            if (row >= M) continue;
            float a1 = s1 ? s1[row] : 0.f;
            float a2 = s2 ? s2[row] : 0.f;
#pragma unroll
            for (int nt = 0; nt < 4; nt++) {
                int col = cbase + nt * 8 + (l & 3) * 2;
#pragma unroll
                for (int q = 0; q < 2; q++) {
                    int cc = col + q;
                    if (cc >= realN) continue;
                    float v = acc[mt][nt][half * 2 + q];
                    if (bias) v += bias[cc];
                    if (v1) v += a1 * v1[cc];
                    if (v2) v += a2 * v2[cc];
                    if (relu) v = fmaxf(v, 0.f);
                    C[(size_t)row * ldc + cc] = v;
                }
            }
        }
    }
}

// ---------------------------------------------------------------------------
// bf16 split preps
// ---------------------------------------------------------------------------
__global__ void k_split(const float* __restrict__ x, __nv_bfloat16* __restrict__ h,
                        __nv_bfloat16* __restrict__ l, int n)
{
    int i = blockIdx.x * blockDim.x + threadIdx.x;
    if (i >= n) return;
    float v = x[i];
    __nv_bfloat16 hi = __float2bfloat16(v);
    h[i] = hi;
    l[i] = __float2bfloat16(v - __bfloat162float(hi));
}

// W [K rows, ldW cols] fp32 -> hi/lo transposed into out[n*ldout + koff + k]
// n in [0, NP), value 0 for n >= N.
__global__ void k_wprepT(const float* __restrict__ W, __nv_bfloat16* __restrict__ h,
                         __nv_bfloat16* __restrict__ l, int K, int N, int NP,
                         int ldW, int ldout, int koff)
{
    int i = blockIdx.x * blockDim.x + threadIdx.x;
    if (i >= NP * K) return;
    int n = i / K, k = i - n * K;
    float v = (n < N) ? W[(size_t)k * ldW + n] : 0.f;
    __nv_bfloat16 hi = __float2bfloat16(v);
    size_t o = (size_t)n * ldout + koff + k;
    h[o] = hi;
    l[o] = __float2bfloat16(v - __bfloat162float(hi));
}

// vL[c] = sum_k be2[k] * Wc1[(512+k)*512 + c];  vR with offset 1024
__global__ void k_vbias(const float* __restrict__ be2, const float* __restrict__ Wc1,
                        float* __restrict__ vL, float* __restrict__ vR)
{
    int c = blockIdx.x * blockDim.x + threadIdx.x;
    if (c >= 512) return;
    float sL = 0.f, sR = 0.f;
    for (int k = 0; k < 512; k++) {
        float b = be2[k];
        sL += b * Wc1[(size_t)(512 + k) * 512 + c];
        sR += b * Wc1[(size_t)(1024 + k) * 512 + c];
    }
    vL[c] = sL; vR[c] = sR;
}

// ---------------------------------------------------------------------------
// Graph/scatter helpers
// ---------------------------------------------------------------------------
__device__ __forceinline__ unsigned fenc(float f) {
    unsigned u = __float_as_uint(f);
    return (u & 0x80000000u) ? ~u : (u | 0x80000000u);
}
__device__ __forceinline__ float fdec(unsigned u) {
    return (u & 0x80000000u) ? __uint_as_float(u & 0x7FFFFFFFu) : __uint_as_float(~u);
}
__device__ __forceinline__ void red_add_v4(float* p, float4 v) {
    asm volatile("red.global.add.v4.f32 [%0], {%1,%2,%3,%4};"
                 :: "l"(p), "f"(v.x), "f"(v.y), "f"(v.z), "f"(v.w) : "memory");
}
__device__ __forceinline__ void edge_sd(const int* __restrict__ ei, int e, int& s, int& d) {
    if (e < EE) { s = ei[e]; d = ei[EE + e]; }
    else        { s = d = e - EE; }
}
__device__ __forceinline__ float lrelu02(float x) { return x > 0.f ? x : 0.2f * x; }

__global__ void k_sd1(const float* __restrict__ xl1,
                      const float* __restrict__ as1, const float* __restrict__ ad1,
                      float* __restrict__ s1, float* __restrict__ d1)
{
    int idx = blockIdx.x * blockDim.x + threadIdx.x;
    if (idx >= NN * HEADS) return;
    int n = idx >> 3, h = idx & 7;
    const float4* xr = (const float4*)(xl1 + (size_t)n * 512 + h * 64);
    const float4* av = (const float4*)(as1 + h * 64);
    const float4* bv = (const float4*)(ad1 + h * 64);
    float ss = 0.f, dd = 0.f;
#pragma unroll
    for (int q = 0; q < 16; q++) {
        float4 x = xr[q], a = av[q], b = bv[q];
        ss += x.x * a.x + x.y * a.y + x.z * a.z + x.w * a.w;
        dd += x.x * b.x + x.y * b.y + x.z * b.z + x.w * b.w;
    }
    s1[idx] = ss; d1[idx] = dd;
}

__global__ void k_alpha1(const int* __restrict__ ei,
                         const float* __restrict__ s1, const float* __restrict__ d1,
                         float* __restrict__ alpha1, unsigned* __restrict__ amax1)
{
    int idx = blockIdx.x * blockDim.x + threadIdx.x;
    if (idx >= ESL * HEADS) return;
    int e = idx >> 3, h = idx & 7;
    int s, d; edge_sd(ei, e, s, d);
    float a = lrelu02(s1[s * 8 + h] + d1[d * 8 + h]);
    alpha1[idx] = a;
    atomicMax(amax1 + d * 8 + h, fenc(a));
}

__global__ void k_ex1(const int* __restrict__ ei,
                      const float* __restrict__ alpha1, const unsigned* __restrict__ amax1,
                      float* __restrict__ ex1, float* __restrict__ den1)
{
    int idx = blockIdx.x * blockDim.x + threadIdx.x;
    if (idx >= ESL * HEADS) return;
    int e = idx >> 3, h = idx & 7;
    int s, d; edge_sd(ei, e, s, d);
    float ex = expf(alpha1[idx] - fdec(amax1[d * 8 + h]));
    ex1[idx] = ex;
    atomicAdd(den1 + d * 8 + h, ex);
}

__global__ void k_agg1(const int* __restrict__ ei, const float* __restrict__ xl1,
                       const float* __restrict__ ex1, const float* __restrict__ den1,
                       float* __restrict__ out1)
{
    int warp = (blockIdx.x * blockDim.x + threadIdx.x) >> 5;
    int lane = threadIdx.x & 31;
    if (warp >= ESL) return;
    int s, d; edge_sd(ei, warp, s, d);
    float w = 0.f;
    if (lane < 8) w = ex1[(size_t)warp * 8 + lane] / (den1[d * 8 + lane] + 1e-16f);
    float wh = __shfl_sync(0xffffffffu, w, lane >> 2);
    const float4* sp = (const float4*)(xl1 + (size_t)s * 512) + lane * 4;
    float* dp = out1 + (size_t)d * 512 + lane * 16;
#pragma unroll
    for (int q = 0; q < 4; q++) {
        float4 v = sp[q];
        v.x *= wh; v.y *= wh; v.z *= wh; v.w *= wh;
        red_add_v4(dp + q * 4, v);
    }
}

__global__ void k_elu(const float* __restrict__ out1, const float* __restrict__ b1,
                      float* __restrict__ x1)
{
    int idx = blockIdx.x * blockDim.x + threadIdx.x;
    if (idx >= NN * 512) return;
    float v = out1[idx] + b1[idx & 511];
    x1[idx] = v > 0.f ? v : expm1f(v);
}

__global__ void k_sd2(const float* __restrict__ xl2,
                      const float* __restrict__ as2, const float* __restrict__ ad2,
                      float* __restrict__ s2, float* __restrict__ d2)
{
    int warp = (blockIdx.x * blockDim.x + threadIdx.x) >> 5;
    int lane = threadIdx.x & 31;
    if (warp >= NN) return;
    const float4* xr = (const float4*)(xl2 + (size_t)warp * 512) + lane * 4;
    const float4* av = (const float4*)as2 + lane * 4;
    const float4* bv = (const float4*)ad2 + lane * 4;
    float ss = 0.f, dd = 0.f;
#pragma unroll
    for (int q = 0; q < 4; q++) {
        float4 x = xr[q], a = av[q], b = bv[q];
        ss += x.x * a.x + x.y * a.y + x.z * a.z + x.w * a.w;
        dd += x.x * b.x + x.y * b.y + x.z * b.z + x.w * b.w;
    }
#pragma unroll
    for (int o = 16; o > 0; o >>= 1) {
        ss += __shfl_xor_sync(0xffffffffu, ss, o);
        dd += __shfl_xor_sync(0xffffffffu, dd, o);
    }
    if (lane == 0) { s2[warp] = ss; d2[warp] = dd; }
}

__global__ void k_alpha2(const int* __restrict__ ei,
                         const float* __restrict__ s2, const float* __restrict__ d2,
                         float* __restrict__ alpha2, unsigned* __restrict__ amax2)
{
    int e = blockIdx.x * blockDim.x + threadIdx.x;
    if (e >= ESL) return;
    int s, d; edge_sd(ei, e, s, d);
    float a = lrelu02(s2[s] + d2[d]);
    alpha2[e] = a;
    atomicMax(amax2 + d, fenc(a));
}

__global__ void k_ex2(const int* __restrict__ ei,
                      const float* __restrict__ alpha2, const unsigned* __restrict__ amax2,
                      float* __restrict__ ex2, float* __restrict__ den2)
{
    int e = blockIdx.x * blockDim.x + threadIdx.x;
    if (e >= ESL) return;
    int s, d; edge_sd(ei, e, s, d);
    float ex = expf(alpha2[e] - fdec(amax2[d]));
    ex2[e] = ex;
    atomicAdd(den2 + d, ex);
}

// Aggregation into G columns [0,512) with row stride 1024
__global__ void k_agg2(const int* __restrict__ ei, const float* __restrict__ xl2,
                       const float* __restrict__ ex2, const float* __restrict__ den2,
                       float* __restrict__ G)
{
    int warp = (blockIdx.x * blockDim.x + threadIdx.x) >> 5;
    int lane = threadIdx.x & 31;
    if (warp >= ESL) return;
    int s, d; edge_sd(ei, warp, s, d);
    float w = 0.f;
    if (lane == 0) w = ex2[warp] / (den2[d] + 1e-16f);
    w = __shfl_sync(0xffffffffu, w, 0);
    const float4* sp = (const float4*)(xl2 + (size_t)s * 512) + lane * 4;
    float* dp = G + (size_t)d * 1024 + lane * 16;
#pragma unroll
    for (int q = 0; q < 4; q++) {
        float4 v = sp[q];
        v.x *= w; v.y *= w; v.z *= w; v.w *= w;
        red_add_v4(dp + q * 4, v);
    }
}

__global__ void k_bias2(float* __restrict__ G, const float* __restrict__ b2)
{
    int idx = blockIdx.x * blockDim.x + threadIdx.x;
    if (idx >= NN * 512) return;
    int n = idx >> 9, c = idx & 511;
    G[(size_t)n * 1024 + c] += b2[c];
}

// Synapse hidden (256) scattered into G cols [512,768) (by src) / [768,1024) (by dst)
__global__ void k_syn(const int* __restrict__ ei, const float* __restrict__ synapse,
                      const float* __restrict__ We1, const float* __restrict__ be1,
                      float* __restrict__ G,
                      float* __restrict__ cntL, float* __restrict__ cntR)
{
    int e = (blockIdx.x * blockDim.x + threadIdx.x) >> 5;
    int lane = threadIdx.x & 31;
    if (e >= EE) return;
    int s = ei[e], d = ei[EE + e];
    float m = 0.f;
    if (lane < 6) {
        const float* sp = synapse + (size_t)e * 24 + lane;
        m = sp[0];
        m = fmaxf(m, sp[6]);
        m = fmaxf(m, sp[12]);
        m = fmaxf(m, sp[18]);
    }
    float xp[6];
#pragma unroll
    for (int j = 0; j < 6; j++) xp[j] = __shfl_sync(0xffffffffu, m, j);

    float h[8];
#pragma unroll
    for (int o = 0; o < 8; o++) {
        int col = lane * 8 + o;
        float acc = be1[col];
#pragma unroll
        for (int k = 0; k < 6; k++) acc += xp[k] * We1[k * 256 + col];
        h[o] = fmaxf(acc, 0.f);
    }
    float* pl = G + (size_t)s * 1024 + 512 + lane * 8;
    float* pr = G + (size_t)d * 1024 + 768 + lane * 8;
    red_add_v4(pl,     make_float4(h[0], h[1], h[2], h[3]));
    red_add_v4(pl + 4, make_float4(h[4], h[5], h[6], h[7]));
    red_add_v4(pr,     make_float4(h[0], h[1], h[2], h[3]));
    red_add_v4(pr + 4, make_float4(h[4], h[5], h[6], h[7]));
    if (lane == 0) {
        atomicAdd(cntL + s, 1.f);
        atomicAdd(cntR + d, 1.f);
    }
}

// Scale mean columns of G; emit bsL/bsR indicator flags
__global__ void k_mean(float* __restrict__ G,
                       const float* __restrict__ cntL, const float* __restrict__ cntR,
                       float* __restrict__ bsL, float* __restrict__ bsR)
{
    int idx = blockIdx.x * blockDim.x + threadIdx.x;
    if (idx >= NN * 512) return;
    int n = idx >> 9, c = idx & 511;
    float cl = cntL[n], cr = cntR[n];
    float sc = (c < 256) ? 1.f / fmaxf(cl, 1.f) : 1.f / fmaxf(cr, 1.f);
    G[(size_t)n * 1024 + 512 + c] *= sc;
    if (c == 0) {
        bsL[n] = cl > 0.f ? 1.f : 0.f;
        bsR[n] = cr > 0.f ? 1.f : 0.f;
    }
}

// ---------------------------------------------------------------------------
// Host launcher
// ---------------------------------------------------------------------------
extern "C" void kernel_launch(void* const* d_in, const int* in_sizes, int n_in,
                              void* d_out, int out_size)
{
    const int*   ei      = (const int*)d_in[0];
    const float* synapse = (const float*)d_in[2];
    int ib = 4;
    if (n_in > 4 && in_sizes[4] == 1) ib = 5;
    const float* x_param = (const float*)d_in[ib + 0];
    const float* W1  = (const float*)d_in[ib + 1];
    const float* as1 = (const float*)d_in[ib + 2];
    const float* ad1 = (const float*)d_in[ib + 3];
    const float* b1  = (const float*)d_in[ib + 4];
    const float* W2  = (const float*)d_in[ib + 5];
    const float* as2 = (const float*)d_in[ib + 6];
    const float* ad2 = (const float*)d_in[ib + 7];
    const float* b2  = (const float*)d_in[ib + 8];
    const float* We1 = (const float*)d_in[ib + 9];
    const float* be1 = (const float*)d_in[ib + 10];
    const float* We2 = (const float*)d_in[ib + 11];
    const float* be2 = (const float*)d_in[ib + 12];
    const float* Wc1 = (const float*)d_in[ib + 13];
    const float* bc1 = (const float*)d_in[ib + 14];
    const float* Wc2 = (const float*)d_in[ib + 15];
    const float* bc2 = (const float*)d_in[ib + 16];
    float* out = (float*)d_out;

    void* sp = nullptr;
    cudaGetSymbolAddress(&sp, g_scratch);
    float* S = (float*)sp;
    void* bp = nullptr;
    cudaGetSymbolAddress(&bp, g_bf);
    __nv_bfloat16* B = (__nv_bfloat16*)bp;

    cudaFuncSetAttribute(tgemm, cudaFuncAttributeMaxDynamicSharedMemorySize, TG_SMEM);

    float*    out1   = S + OFF_OUT1;
    float*    G      = S + OFF_G;
    unsigned* amax1  = (unsigned*)(S + OFF_AMAX1);
    float*    den1   = S + OFF_DEN1;
    unsigned* amax2  = (unsigned*)(S + OFF_AMAX2);
    float*    den2   = S + OFF_DEN2;
    float*    cntL   = S + OFF_CNTL;
    float*    cntR   = S + OFF_CNTR;
    float*    xl1    = S + OFF_XL1;
    float*    s1     = S + OFF_S1;
    float*    dd1    = S + OFF_DD1;
    float*    alpha1 = S + OFF_ALPHA1;
    float*    ex1    = S + OFF_EX1;
    float*    x1     = S + OFF_X1;
    float*    xl2    = S + OFF_XL2;
    float*    s2     = S + OFF_S2;
    float*    dd2    = S + OFF_DD2;
    float*    alpha2 = S + OFF_ALPHA2;
    float*    ex2    = S + OFF_EX2;
    float*    bsL    = S + OFF_BSL;
    float*    bsR    = S + OFF_BSR;
    float*    hidc   = S + OFF_HIDC;
    float*    vL     = S + OFF_VL;
    float*    vR     = S + OFF_VR;
    // early temps (region reused by alpha1 later)
    float*    WcombL = alpha1;
    float*    WcombR = alpha1 + 256 * 512;

    cudaMemsetAsync(S, 0, ZEND * sizeof(float));

    dim3 tpb(256);
    const int MT = (NN + 127) / 128;   // 157 M-tiles

    // ---- Weight preps ----
    k_wprepT<<<(512 * 128  + 255) / 256, tpb>>>(W1,  B + B_W1H,  B + B_W1L,  128,  512, 512, 512, 128,  0);
    k_wprepT<<<(512 * 512  + 255) / 256, tpb>>>(W2,  B + B_W2H,  B + B_W2L,  512,  512, 512, 512, 512,  0);
    k_wprepT<<<(256 * 512  + 255) / 256, tpb>>>(Wc2, B + B_WC2H, B + B_WC2L, 512,  NCLS, 256, NCLS, 512, 0);
    // Wbig part 1: Wc1 top rows (k 0..511) transposed into [512,1024] at koff 0
    k_wprepT<<<(512 * 512  + 255) / 256, tpb>>>(Wc1, B + B_WBH,  B + B_WBL,  512,  512, 512, 512, 1024, 0);
    // Wc1 mid/bot transposed temps for the Wcomb gemms
    k_wprepT<<<(512 * 512  + 255) / 256, tpb>>>(Wc1 + (size_t)512 * 512,  B + B_WM1H, B + B_WM1L, 512, 512, 512, 512, 512, 0);
    k_wprepT<<<(512 * 512  + 255) / 256, tpb>>>(Wc1 + (size_t)1024 * 512, B + B_WM2H, B + B_WM2L, 512, 512, 512, 512, 512, 0);
    // We2 as A-side split [256,512]
    k_split<<<(256 * 512 + 255) / 256, tpb>>>(We2, B + B_WE2AH, B + B_WE2AL, 256 * 512);
    // rank-1 bias vectors
    k_vbias<<<2, tpb>>>(be2, Wc1, vL, vR);

    // WcombL = We2 @ Wc1_mid   [256, 512] fp32
    {
        dim3 g(2, 4);
        tgemm<<<g, tpb, TG_SMEM>>>(B + B_WE2AH, B + B_WE2AL, B + B_WM1H, B + B_WM1L,
                                   WcombL, 256, 512, 512, 512,
                                   nullptr, nullptr, nullptr, nullptr, nullptr, 0);
        tgemm<<<g, tpb, TG_SMEM>>>(B + B_WE2AH, B + B_WE2AL, B + B_WM2H, B + B_WM2L,
                                   WcombR, 256, 512, 512, 512,
                                   nullptr, nullptr, nullptr, nullptr, nullptr, 0);
    }
    // Wbig parts 2/3: Wcomb transposed into koff 512 / 768
    k_wprepT<<<(512 * 256 + 255) / 256, tpb>>>(WcombL, B + B_WBH, B + B_WBL, 256, 512, 512, 512, 1024, 512);
    k_wprepT<<<(512 * 256 + 255) / 256, tpb>>>(WcombR, B + B_WBH, B + B_WBL, 256, 512, 512, 512, 1024, 768);

    // ---- GAT1 ----
    k_split<<<((int)SZ_XP + 255) / 256, tpb>>>(x_param, B + B_XPH, B + B_XPL, (int)SZ_XP);
    {
        dim3 g(MT, 4);
        tgemm<<<g, tpb, TG_SMEM>>>(B + B_XPH, B + B_XPL, B + B_W1H, B + B_W1L,
                                   xl1, NN, FIN, D1, D1,
                                   nullptr, nullptr, nullptr, nullptr, nullptr, 0);
    }
    k_sd1<<<(NN * HEADS + 255) / 256, tpb>>>(xl1, as1, ad1, s1, dd1);
    k_alpha1<<<(ESL * HEADS + 255) / 256, tpb>>>(ei, s1, dd1, alpha1, amax1);
    k_ex1<<<(ESL * HEADS + 255) / 256, tpb>>>(ei, alpha1, amax1, ex1, den1);
    k_agg1<<<(ESL * 32 + 255) / 256, tpb>>>(ei, xl1, ex1, den1, out1);
    k_elu<<<(NN * 512 + 255) / 256, tpb>>>(out1, b1, x1);

    // ---- GAT2 (writes into G cols [0,512)) ----
    k_split<<<((int)SZ_X1 + 255) / 256, tpb>>>(x1, B + B_X1H, B + B_X1L, (int)SZ_X1);
    {
        dim3 g(MT, 4);
        tgemm<<<g, tpb, TG_SMEM>>>(B + B_X1H, B + B_X1L, B + B_W2H, B + B_W2L,
                                   xl2, NN, D1, REP, REP,
                                   nullptr, nullptr, nullptr, nullptr, nullptr, 0);
    }
    k_sd2<<<(NN * 32 + 255) / 256, tpb>>>(xl2, as2, ad2, s2, dd2);
    k_alpha2<<<(ESL + 255) / 256, tpb>>>(ei, s2, dd2, alpha2, amax2);
    k_ex2<<<(ESL + 255) / 256, tpb>>>(ei, alpha2, amax2, ex2, den2);
    k_agg2<<<(ESL * 32 + 255) / 256, tpb>>>(ei, xl2, ex2, den2, G);
    k_bias2<<<(NN * 512 + 255) / 256, tpb>>>(G, b2);

    // ---- Synapse encoder hidden + scatter means into G cols [512,1024) ----
    k_syn<<<(EE * 32 + 255) / 256, tpb>>>(ei, synapse, We1, be1, G, cntL, cntR);
    k_mean<<<(NN * 512 + 255) / 256, tpb>>>(G, cntL, cntR, bsL, bsR);

    // ---- Fused classifier layer 1: hidc = relu(G @ Wbig^T + bc1 + bsL*vL + bsR*vR)
    k_split<<<((int)SZ_G + 255) / 256, tpb>>>(G, B + B_GH, B + B_GL, (int)SZ_G);
    {
        dim3 g(MT, 4);
        tgemm<<<g, tpb, TG_SMEM>>>(B + B_GH, B + B_GL, B + B_WBH, B + B_WBL,
                                   hidc, NN, 1024, 512, 512,
                                   bc1, vL, bsL, vR, bsR, 1);
    }
    // ---- Classifier layer 2 ----
    k_split<<<((int)SZ_HC + 255) / 256, tpb>>>(hidc, B + B_HCH, B + B_HCL, (int)SZ_HC);
    {
        dim3 g(MT, 2);
        tgemm<<<g, tpb, TG_SMEM>>>(B + B_HCH, B + B_HCL, B + B_WC2H, B + B_WC2L,
                                   out, NN, 512, NCLS, NCLS,
                                   bc2, nullptr, nullptr, nullptr, nullptr, 0);
    }
}

// round 5
// speedup vs baseline: 2.1675x; 1.0229x over previous
#include <cuda_runtime.h>
#include <cuda_bf16.h>
#include <cstdint>

// ---------------------------------------------------------------------------
// Problem constants
// ---------------------------------------------------------------------------
constexpr int NN   = 20000;
constexpr int FIN  = 128;
constexpr int HEADS = 8;
constexpr int HIDC  = 64;
constexpr int D1    = HEADS * HIDC;  // 512
constexpr int REP   = 512;
constexpr int NCLS  = 133;
constexpr int EE    = 200000;
constexpr int ESL   = EE + NN;       // 220000

// ---------------------------------------------------------------------------
// fp32 scratch layout (zero-region first: one memset covers it)
// G = [x(512) | sumHl(256) | sumHr(256)] per node, width 1024
// ---------------------------------------------------------------------------
constexpr size_t OFF_OUT1   = 0;
constexpr size_t OFF_G      = OFF_OUT1   + (size_t)NN * 512;   // NN*1024
constexpr size_t OFF_AMAX1  = OFF_G      + (size_t)NN * 1024;
constexpr size_t OFF_DEN1   = OFF_AMAX1  + (size_t)NN * 8;
constexpr size_t OFF_AMAX2  = OFF_DEN1   + (size_t)NN * 8;
constexpr size_t OFF_DEN2   = OFF_AMAX2  + (size_t)NN;
constexpr size_t OFF_CNTL   = OFF_DEN2   + (size_t)NN;
constexpr size_t OFF_CNTR   = OFF_CNTL   + (size_t)NN;
constexpr size_t ZEND       = OFF_CNTR   + (size_t)NN;

constexpr size_t OFF_XL1    = ZEND;
constexpr size_t OFF_S1     = OFF_XL1    + (size_t)NN * 512;
constexpr size_t OFF_DD1    = OFF_S1     + (size_t)NN * 8;
constexpr size_t OFF_ALPHA1 = OFF_DD1    + (size_t)NN * 8;   // ESL*8 (reused as Wcomb temps early)
constexpr size_t OFF_EX1    = OFF_ALPHA1 + (size_t)ESL * 8;
constexpr size_t OFF_XL2    = OFF_EX1    + (size_t)ESL * 8;
constexpr size_t OFF_S2     = OFF_XL2    + (size_t)NN * 512;
constexpr size_t OFF_DD2    = OFF_S2     + (size_t)NN;
constexpr size_t OFF_ALPHA2 = OFF_DD2    + (size_t)NN;
constexpr size_t OFF_EX2    = OFF_ALPHA2 + (size_t)ESL;
constexpr size_t OFF_BSL    = OFF_EX2    + (size_t)ESL;
constexpr size_t OFF_BSR    = OFF_BSL    + (size_t)NN;
constexpr size_t OFF_VL     = OFF_BSR    + (size_t)NN;
constexpr size_t OFF_VR     = OFF_VL     + 512;
constexpr size_t TOTALF     = OFF_VR     + 512;

__device__ float g_scratch[TOTALF];

// ---------------------------------------------------------------------------
// bf16 split scratch (hi/lo pairs). Weights stored transposed [NP, K].
// ---------------------------------------------------------------------------
constexpr size_t SZ_XP   = (size_t)NN * 128;
constexpr size_t SZ_X1   = (size_t)NN * 512;
constexpr size_t SZ_G    = (size_t)NN * 1024;
constexpr size_t SZ_HC   = (size_t)NN * 512;
constexpr size_t SZ_W1   = 512 * 128;
constexpr size_t SZ_W2   = 512 * 512;
constexpr size_t SZ_WB   = 512 * 1024;
constexpr size_t SZ_WC2  = 256 * 512;
constexpr size_t SZ_WM   = 512 * 512;
constexpr size_t SZ_WE2A = 256 * 512;

constexpr size_t B_XPH   = 0;
constexpr size_t B_XPL   = B_XPH   + SZ_XP;
constexpr size_t B_X1H   = B_XPL   + SZ_XP;
constexpr size_t B_X1L   = B_X1H   + SZ_X1;
constexpr size_t B_GH    = B_X1L   + SZ_X1;
constexpr size_t B_GL    = B_GH    + SZ_G;
constexpr size_t B_HCH   = B_GL    + SZ_G;
constexpr size_t B_HCL   = B_HCH   + SZ_HC;
constexpr size_t B_W1H   = B_HCL   + SZ_HC;
constexpr size_t B_W1L   = B_W1H   + SZ_W1;
constexpr size_t B_W2H   = B_W1L   + SZ_W1;
constexpr size_t B_W2L   = B_W2H   + SZ_W2;
constexpr size_t B_WBH   = B_W2L   + SZ_W2;
constexpr size_t B_WBL   = B_WBH   + SZ_WB;
constexpr size_t B_WC2H  = B_WBL   + SZ_WB;
constexpr size_t B_WC2L  = B_WC2H  + SZ_WC2;
constexpr size_t B_WM1H  = B_WC2L  + SZ_WC2;
constexpr size_t B_WM1L  = B_WM1H  + SZ_WM;
constexpr size_t B_WM2H  = B_WM1L  + SZ_WM;
constexpr size_t B_WM2L  = B_WM2H  + SZ_WM;
constexpr size_t B_WE2AH = B_WM2L  + SZ_WM;
constexpr size_t B_WE2AL = B_WE2AH + SZ_WE2A;
constexpr size_t TOTALB  = B_WE2AL + SZ_WE2A;

__device__ __align__(256) __nv_bfloat16 g_bf[TOTALB];

// ---------------------------------------------------------------------------
// Portable PTX helpers
// ---------------------------------------------------------------------------
__device__ __forceinline__ uint32_t smem_to_u32(const void* p) {
    uint32_t a;
    asm("{ .reg .u64 t; cvta.to.shared.u64 t, %1; cvt.u32.u64 %0, t; }"
        : "=r"(a) : "l"(p));
    return a;
}
#define SWZ(off) ((off) ^ (((off) >> 3) & 0x70))

// ---------------------------------------------------------------------------
// mma.sync GEMM: out = A[M,K] @ Wt^T  (Wt stored [NP,K], bf16 split, 3 passes)
// CTA 128x128, BK=64, 3-stage cp.async pipeline.
// Epilogue: v = acc + bias[c] + s1[row]*v1[c] + s2[row]*v2[c]; optional relu.
// Output either fp32 C, or bf16 hi/lo split (Ch/Cl).
// ---------------------------------------------------------------------------
constexpr int TG_SMEM = 3 * 32768;   // 96 KB

__global__ __launch_bounds__(256)
void tgemm(const __nv_bfloat16* __restrict__ Ah, const __nv_bfloat16* __restrict__ Al,
           const __nv_bfloat16* __restrict__ Bh, const __nv_bfloat16* __restrict__ Bl,
           float* __restrict__ C,
           __nv_bfloat16* __restrict__ Ch, __nv_bfloat16* __restrict__ Cl,
           int M, int K, int realN, int ldc,
           const float* __restrict__ bias,
           const float* __restrict__ v1, const float* __restrict__ s1,
           const float* __restrict__ v2, const float* __restrict__ s2,
           int relu)
{
    extern __shared__ __align__(1024) char smem[];
    const uint32_t sb = smem_to_u32(smem);
    const int tid = threadIdx.x;
    const int w = tid >> 5, l = tid & 31;
    const int m0 = blockIdx.x * 128, n0 = blockIdx.y * 128;
    const int wm = w & 1, wn = w >> 1;          // 2 x 4 warp grid, warp tile 64x32
    const int Kc = K >> 6;
    const int nch = 3 * Kc;

    float acc[4][4][4];
#pragma unroll
    for (int a = 0; a < 4; a++)
#pragma unroll
        for (int b = 0; b < 4; b++)
#pragma unroll
            for (int c = 0; c < 4; c++) acc[a][b][c] = 0.f;

    auto load_chunk = [&](int c) {
        int st = c % 3;
        int part = c / Kc, kblk = c - part * Kc;
        const __nv_bfloat16* As = (part < 2) ? Ah : Al;
        const __nv_bfloat16* Bs = (part == 1) ? Bl : Bh;
        uint32_t abase = sb + st * 32768;
        uint32_t bbase = abase + 16384;
#pragma unroll
        for (int j = 0; j < 4; j++) {
            int id = tid + j * 256;
            int r = id >> 3, ck = id & 7;
            {
                int grow = m0 + r;
                const void* g = As + (size_t)grow * K + kblk * 64 + ck * 8;
                uint32_t d = abase + SWZ((uint32_t)(r * 128 + ck * 16));
                int sz = (grow < M) ? 16 : 0;
                asm volatile("cp.async.cg.shared.global [%0], [%1], 16, %2;"
                             :: "r"(d), "l"(g), "r"(sz));
            }
            {
                const void* g = Bs + (size_t)(n0 + r) * K + kblk * 64 + ck * 8;
                uint32_t d = bbase + SWZ((uint32_t)(r * 128 + ck * 16));
                asm volatile("cp.async.cg.shared.global [%0], [%1], 16;"
                             :: "r"(d), "l"(g));
            }
        }
        asm volatile("cp.async.commit_group;" ::: "memory");
    };

    auto compute = [&](int c) {
        int st = c % 3;
        uint32_t abase = sb + st * 32768;
        uint32_t bbase = abase + 16384;
#pragma unroll
        for (int ks = 0; ks < 4; ks++) {
            int kb = ks * 16;
            uint32_t af[4][4];
#pragma unroll
            for (int mt = 0; mt < 4; mt++) {
                int m = wm * 64 + mt * 16 + (l & 7) + ((l >> 3) & 1) * 8;
                int ke = kb + (l >> 4) * 8;
                uint32_t addr = abase + SWZ((uint32_t)(m * 128 + ke * 2));
                asm volatile("ldmatrix.sync.aligned.m8n8.x4.shared.b16 {%0,%1,%2,%3}, [%4];"
                             : "=r"(af[mt][0]), "=r"(af[mt][1]),
                               "=r"(af[mt][2]), "=r"(af[mt][3]) : "r"(addr));
            }
            uint32_t bf[4][2];
#pragma unroll
            for (int g = 0; g < 2; g++) {
                int n = wn * 32 + g * 16 + ((l >> 4) & 1) * 8 + (l & 7);
                int ke = kb + ((l >> 3) & 1) * 8;
                uint32_t addr = bbase + SWZ((uint32_t)(n * 128 + ke * 2));
                uint32_t r0, r1, r2, r3;
                asm volatile("ldmatrix.sync.aligned.m8n8.x4.shared.b16 {%0,%1,%2,%3}, [%4];"
                             : "=r"(r0), "=r"(r1), "=r"(r2), "=r"(r3) : "r"(addr));
                bf[2 * g][0] = r0; bf[2 * g][1] = r1;
                bf[2 * g + 1][0] = r2; bf[2 * g + 1][1] = r3;
            }
#pragma unroll
            for (int mt = 0; mt < 4; mt++)
#pragma unroll
                for (int nt = 0; nt < 4; nt++) {
                    asm volatile(
                        "mma.sync.aligned.m16n8k16.row.col.f32.bf16.bf16.f32 "
                        "{%0,%1,%2,%3}, {%4,%5,%6,%7}, {%8,%9}, {%0,%1,%2,%3};"
                        : "+f"(acc[mt][nt][0]), "+f"(acc[mt][nt][1]),
                          "+f"(acc[mt][nt][2]), "+f"(acc[mt][nt][3])
                        : "r"(af[mt][0]), "r"(af[mt][1]), "r"(af[mt][2]), "r"(af[mt][3]),
                          "r"(bf[nt][0]), "r"(bf[nt][1]));
                }
        }
    };

    load_chunk(0);
    if (nch > 1) load_chunk(1);
    for (int c = 0; c < nch; c++) {
        if (c + 1 < nch)
            asm volatile("cp.async.wait_group 1;" ::: "memory");
        else
            asm volatile("cp.async.wait_group 0;" ::: "memory");
        __syncthreads();
        if (c + 2 < nch) load_chunk(c + 2);
        compute(c);
    }

    // Epilogue
    const int rbase = m0 + wm * 64, cbase = n0 + wn * 32;
#pragma unroll
    for (int mt = 0; mt < 4; mt++) {
#pragma unroll
        for (int half = 0; half < 2; half++) {
            int row = rbase + mt * 16 + (l >> 2) + half * 8;
            if (row >= M) continue;
            float a1 = s1 ? s1[row] : 0.f;
            float a2 = s2 ? s2[row] : 0.f;
#pragma unroll
            for (int nt = 0; nt < 4; nt++) {
                int col = cbase + nt * 8 + (l & 3) * 2;
#pragma unroll
                for (int q = 0; q < 2; q++) {
                    int cc = col + q;
                    if (cc >= realN) continue;
                    float v = acc[mt][nt][half * 2 + q];
                    if (bias) v += bias[cc];
                    if (v1) v += a1 * v1[cc];
                    if (v2) v += a2 * v2[cc];
                    if (relu) v = fmaxf(v, 0.f);
                    if (Ch) {
                        __nv_bfloat16 hi = __float2bfloat16(v);
                        Ch[(size_t)row * ldc + cc] = hi;
                        Cl[(size_t)row * ldc + cc] = __float2bfloat16(v - __bfloat162float(hi));
                    } else {
                        C[(size_t)row * ldc + cc] = v;
                    }
                }
            }
        }
    }
}

// ---------------------------------------------------------------------------
// bf16 split preps
// ---------------------------------------------------------------------------
__global__ void k_split(const float* __restrict__ x, __nv_bfloat16* __restrict__ h,
                        __nv_bfloat16* __restrict__ l, int n)
{
    int i = blockIdx.x * blockDim.x + threadIdx.x;
    if (i >= n) return;
    float v = x[i];
    __nv_bfloat16 hi = __float2bfloat16(v);
    h[i] = hi;
    l[i] = __float2bfloat16(v - __bfloat162float(hi));
}

// W [K rows, ldW cols] fp32 -> hi/lo transposed into out[n*ldout + koff + k]
__global__ void k_wprepT(const float* __restrict__ W, __nv_bfloat16* __restrict__ h,
                         __nv_bfloat16* __restrict__ l, int K, int N, int NP,
                         int ldW, int ldout, int koff)
{
    int i = blockIdx.x * blockDim.x + threadIdx.x;
    if (i >= NP * K) return;
    int n = i / K, k = i - n * K;
    float v = (n < N) ? W[(size_t)k * ldW + n] : 0.f;
    __nv_bfloat16 hi = __float2bfloat16(v);
    size_t o = (size_t)n * ldout + koff + k;
    h[o] = hi;
    l[o] = __float2bfloat16(v - __bfloat162float(hi));
}

__global__ void k_vbias(const float* __restrict__ be2, const float* __restrict__ Wc1,
                        float* __restrict__ vL, float* __restrict__ vR)
{
    int c = blockIdx.x * blockDim.x + threadIdx.x;
    if (c >= 512) return;
    float sL = 0.f, sR = 0.f;
    for (int k = 0; k < 512; k++) {
        float b = be2[k];
        sL += b * Wc1[(size_t)(512 + k) * 512 + c];
        sR += b * Wc1[(size_t)(1024 + k) * 512 + c];
    }
    vL[c] = sL; vR[c] = sR;
}

// ---------------------------------------------------------------------------
// Graph/scatter helpers
// ---------------------------------------------------------------------------
__device__ __forceinline__ unsigned fenc(float f) {
    unsigned u = __float_as_uint(f);
    return (u & 0x80000000u) ? ~u : (u | 0x80000000u);
}
__device__ __forceinline__ float fdec(unsigned u) {
    return (u & 0x80000000u) ? __uint_as_float(u & 0x7FFFFFFFu) : __uint_as_float(~u);
}
__device__ __forceinline__ void red_add_v4(float* p, float4 v) {
    asm volatile("red.global.add.v4.f32 [%0], {%1,%2,%3,%4};"
                 :: "l"(p), "f"(v.x), "f"(v.y), "f"(v.z), "f"(v.w) : "memory");
}
__device__ __forceinline__ void edge_sd(const int* __restrict__ ei, int e, int& s, int& d) {
    if (e < EE) { s = ei[e]; d = ei[EE + e]; }
    else        { s = d = e - EE; }
}
__device__ __forceinline__ float lrelu02(float x) { return x > 0.f ? x : 0.2f * x; }

__global__ void k_sd1(const float* __restrict__ xl1,
                      const float* __restrict__ as1, const float* __restrict__ ad1,
                      float* __restrict__ s1, float* __restrict__ d1)
{
    int idx = blockIdx.x * blockDim.x + threadIdx.x;
    if (idx >= NN * HEADS) return;
    int n = idx >> 3, h = idx & 7;
    const float4* xr = (const float4*)(xl1 + (size_t)n * 512 + h * 64);
    const float4* av = (const float4*)(as1 + h * 64);
    const float4* bv = (const float4*)(ad1 + h * 64);
    float ss = 0.f, dd = 0.f;
#pragma unroll
    for (int q = 0; q < 16; q++) {
        float4 x = xr[q], a = av[q], b = bv[q];
        ss += x.x * a.x + x.y * a.y + x.z * a.z + x.w * a.w;
        dd += x.x * b.x + x.y * b.y + x.z * b.z + x.w * b.w;
    }
    s1[idx] = ss; d1[idx] = dd;
}

__global__ void k_alpha1(const int* __restrict__ ei,
                         const float* __restrict__ s1, const float* __restrict__ d1,
                         float* __restrict__ alpha1, unsigned* __restrict__ amax1)
{
    int idx = blockIdx.x * blockDim.x + threadIdx.x;
    if (idx >= ESL * HEADS) return;
    int e = idx >> 3, h = idx & 7;
    int s, d; edge_sd(ei, e, s, d);
    float a = lrelu02(s1[s * 8 + h] + d1[d * 8 + h]);
    alpha1[idx] = a;
    atomicMax(amax1 + d * 8 + h, fenc(a));
}

__global__ void k_ex1(const int* __restrict__ ei,
                      const float* __restrict__ alpha1, const unsigned* __restrict__ amax1,
                      float* __restrict__ ex1, float* __restrict__ den1)
{
    int idx = blockIdx.x * blockDim.x + threadIdx.x;
    if (idx >= ESL * HEADS) return;
    int e = idx >> 3, h = idx & 7;
    int s, d; edge_sd(ei, e, s, d);
    float ex = expf(alpha1[idx] - fdec(amax1[d * 8 + h]));
    ex1[idx] = ex;
    atomicAdd(den1 + d * 8 + h, ex);
}

__global__ void k_agg1(const int* __restrict__ ei, const float* __restrict__ xl1,
                       const float* __restrict__ ex1, const float* __restrict__ den1,
                       float* __restrict__ out1)
{
    int warp = (blockIdx.x * blockDim.x + threadIdx.x) >> 5;
    int lane = threadIdx.x & 31;
    if (warp >= ESL) return;
    int s, d; edge_sd(ei, warp, s, d);
    float w = 0.f;
    if (lane < 8) w = ex1[(size_t)warp * 8 + lane] / (den1[d * 8 + lane] + 1e-16f);
    float wh = __shfl_sync(0xffffffffu, w, lane >> 2);
    const float4* sp = (const float4*)(xl1 + (size_t)s * 512) + lane * 4;
    float* dp = out1 + (size_t)d * 512 + lane * 16;
#pragma unroll
    for (int q = 0; q < 4; q++) {
        float4 v = sp[q];
        v.x *= wh; v.y *= wh; v.z *= wh; v.w *= wh;
        red_add_v4(dp + q * 4, v);
    }
}

// x1 = elu(out1 + b1) -> bf16 hi/lo split directly
__global__ void k_elusplit(const float* __restrict__ out1, const float* __restrict__ b1,
                           __nv_bfloat16* __restrict__ xh, __nv_bfloat16* __restrict__ xl)
{
    int idx = blockIdx.x * blockDim.x + threadIdx.x;
    if (idx >= NN * 512) return;
    float v = out1[idx] + b1[idx & 511];
    v = v > 0.f ? v : expm1f(v);
    __nv_bfloat16 hi = __float2bfloat16(v);
    xh[idx] = hi;
    xl[idx] = __float2bfloat16(v - __bfloat162float(hi));
}

__global__ void k_sd2(const float* __restrict__ xl2,
                      const float* __restrict__ as2, const float* __restrict__ ad2,
                      float* __restrict__ s2, float* __restrict__ d2)
{
    int warp = (blockIdx.x * blockDim.x + threadIdx.x) >> 5;
    int lane = threadIdx.x & 31;
    if (warp >= NN) return;
    const float4* xr = (const float4*)(xl2 + (size_t)warp * 512) + lane * 4;
    const float4* av = (const float4*)as2 + lane * 4;
    const float4* bv = (const float4*)ad2 + lane * 4;
    float ss = 0.f, dd = 0.f;
#pragma unroll
    for (int q = 0; q < 4; q++) {
        float4 x = xr[q], a = av[q], b = bv[q];
        ss += x.x * a.x + x.y * a.y + x.z * a.z + x.w * a.w;
        dd += x.x * b.x + x.y * b.y + x.z * b.z + x.w * b.w;
    }
#pragma unroll
    for (int o = 16; o > 0; o >>= 1) {
        ss += __shfl_xor_sync(0xffffffffu, ss, o);
        dd += __shfl_xor_sync(0xffffffffu, dd, o);
    }
    if (lane == 0) { s2[warp] = ss; d2[warp] = dd; }
}

__global__ void k_alpha2(const int* __restrict__ ei,
                         const float* __restrict__ s2, const float* __restrict__ d2,
                         float* __restrict__ alpha2, unsigned* __restrict__ amax2)
{
    int e = blockIdx.x * blockDim.x + threadIdx.x;
    if (e >= ESL) return;
    int s, d; edge_sd(ei, e, s, d);
    float a = lrelu02(s2[s] + d2[d]);
    alpha2[e] = a;
    atomicMax(amax2 + d, fenc(a));
}

__global__ void k_ex2(const int* __restrict__ ei,
                      const float* __restrict__ alpha2, const unsigned* __restrict__ amax2,
                      float* __restrict__ ex2, float* __restrict__ den2)
{
    int e = blockIdx.x * blockDim.x + threadIdx.x;
    if (e >= ESL) return;
    int s, d; edge_sd(ei, e, s, d);
    float ex = expf(alpha2[e] - fdec(amax2[d]));
    ex2[e] = ex;
    atomicAdd(den2 + d, ex);
}

// Aggregation into G columns [0,512) with row stride 1024
__global__ void k_agg2(const int* __restrict__ ei, const float* __restrict__ xl2,
                       const float* __restrict__ ex2, const float* __restrict__ den2,
                       float* __restrict__ G)
{
    int warp = (blockIdx.x * blockDim.x + threadIdx.x) >> 5;
    int lane = threadIdx.x & 31;
    if (warp >= ESL) return;
    int s, d; edge_sd(ei, warp, s, d);
    float w = 0.f;
    if (lane == 0) w = ex2[warp] / (den2[d] + 1e-16f);
    w = __shfl_sync(0xffffffffu, w, 0);
    const float4* sp = (const float4*)(xl2 + (size_t)s * 512) + lane * 4;
    float* dp = G + (size_t)d * 1024 + lane * 16;
#pragma unroll
    for (int q = 0; q < 4; q++) {
        float4 v = sp[q];
        v.x *= w; v.y *= w; v.z *= w; v.w *= w;
        red_add_v4(dp + q * 4, v);
    }
}

// Synapse hidden (256) scattered into G cols [512,768) (src) / [768,1024) (dst)
__global__ void k_syn(const int* __restrict__ ei, const float* __restrict__ synapse,
                      const float* __restrict__ We1, const float* __restrict__ be1,
                      float* __restrict__ G,
                      float* __restrict__ cntL, float* __restrict__ cntR)
{
    int e = (blockIdx.x * blockDim.x + threadIdx.x) >> 5;
    int lane = threadIdx.x & 31;
    if (e >= EE) return;
    int s = ei[e], d = ei[EE + e];
    float m = 0.f;
    if (lane < 6) {
        const float* sp = synapse + (size_t)e * 24 + lane;
        m = sp[0];
        m = fmaxf(m, sp[6]);
        m = fmaxf(m, sp[12]);
        m = fmaxf(m, sp[18]);
    }
    float xp[6];
#pragma unroll
    for (int j = 0; j < 6; j++) xp[j] = __shfl_sync(0xffffffffu, m, j);

    float h[8];
#pragma unroll
    for (int o = 0; o < 8; o++) {
        int col = lane * 8 + o;
        float acc = be1[col];
#pragma unroll
        for (int k = 0; k < 6; k++) acc += xp[k] * We1[k * 256 + col];
        h[o] = fmaxf(acc, 0.f);
    }
    float* pl = G + (size_t)s * 1024 + 512 + lane * 8;
    float* pr = G + (size_t)d * 1024 + 768 + lane * 8;
    red_add_v4(pl,     make_float4(h[0], h[1], h[2], h[3]));
    red_add_v4(pl + 4, make_float4(h[4], h[5], h[6], h[7]));
    red_add_v4(pr,     make_float4(h[0], h[1], h[2], h[3]));
    red_add_v4(pr + 4, make_float4(h[4], h[5], h[6], h[7]));
    if (lane == 0) {
        atomicAdd(cntL + s, 1.f);
        atomicAdd(cntR + d, 1.f);
    }
}

// Post-process G: add b2 (cols<512), mean-scale (cols>=512), emit hi/lo split + flags
__global__ void k_postG(const float* __restrict__ G, const float* __restrict__ b2,
                        const float* __restrict__ cntL, const float* __restrict__ cntR,
                        __nv_bfloat16* __restrict__ Gh, __nv_bfloat16* __restrict__ Gl,
                        float* __restrict__ bsL, float* __restrict__ bsR)
{
    int idx = blockIdx.x * blockDim.x + threadIdx.x;
    if (idx >= NN * 1024) return;
    int n = idx >> 10, c = idx & 1023;
    float v = G[idx];
    if (c < 512) {
        v += b2[c];
    } else if (c < 768) {
        v *= 1.f / fmaxf(cntL[n], 1.f);
    } else {
        v *= 1.f / fmaxf(cntR[n], 1.f);
    }
    __nv_bfloat16 hi = __float2bfloat16(v);
    Gh[idx] = hi;
    Gl[idx] = __float2bfloat16(v - __bfloat162float(hi));
    if (c == 0) {
        bsL[n] = cntL[n] > 0.f ? 1.f : 0.f;
        bsR[n] = cntR[n] > 0.f ? 1.f : 0.f;
    }
}

// ---------------------------------------------------------------------------
// Host launcher
// ---------------------------------------------------------------------------
extern "C" void kernel_launch(void* const* d_in, const int* in_sizes, int n_in,
                              void* d_out, int out_size)
{
    const int*   ei      = (const int*)d_in[0];
    const float* synapse = (const float*)d_in[2];
    int ib = 4;
    if (n_in > 4 && in_sizes[4] == 1) ib = 5;
    const float* x_param = (const float*)d_in[ib + 0];
    const float* W1  = (const float*)d_in[ib + 1];
    const float* as1 = (const float*)d_in[ib + 2];
    const float* ad1 = (const float*)d_in[ib + 3];
    const float* b1  = (const float*)d_in[ib + 4];
    const float* W2  = (const float*)d_in[ib + 5];
    const float* as2 = (const float*)d_in[ib + 6];
    const float* ad2 = (const float*)d_in[ib + 7];
    const float* b2  = (const float*)d_in[ib + 8];
    const float* We1 = (const float*)d_in[ib + 9];
    const float* be1 = (const float*)d_in[ib + 10];
    const float* We2 = (const float*)d_in[ib + 11];
    const float* be2 = (const float*)d_in[ib + 12];
    const float* Wc1 = (const float*)d_in[ib + 13];
    const float* bc1 = (const float*)d_in[ib + 14];
    const float* Wc2 = (const float*)d_in[ib + 15];
    const float* bc2 = (const float*)d_in[ib + 16];
    float* out = (float*)d_out;

    void* sp = nullptr;
    cudaGetSymbolAddress(&sp, g_scratch);
    float* S = (float*)sp;
    void* bp = nullptr;
    cudaGetSymbolAddress(&bp, g_bf);
    __nv_bfloat16* B = (__nv_bfloat16*)bp;

    cudaFuncSetAttribute(tgemm, cudaFuncAttributeMaxDynamicSharedMemorySize, TG_SMEM);

    float*    out1   = S + OFF_OUT1;
    float*    G      = S + OFF_G;
    unsigned* amax1  = (unsigned*)(S + OFF_AMAX1);
    float*    den1   = S + OFF_DEN1;
    unsigned* amax2  = (unsigned*)(S + OFF_AMAX2);
    float*    den2   = S + OFF_DEN2;
    float*    cntL   = S + OFF_CNTL;
    float*    cntR   = S + OFF_CNTR;
    float*    xl1    = S + OFF_XL1;
    float*    s1     = S + OFF_S1;
    float*    dd1    = S + OFF_DD1;
    float*    alpha1 = S + OFF_ALPHA1;
    float*    ex1    = S + OFF_EX1;
    float*    xl2    = S + OFF_XL2;
    float*    s2     = S + OFF_S2;
    float*    dd2    = S + OFF_DD2;
    float*    alpha2 = S + OFF_ALPHA2;
    float*    ex2    = S + OFF_EX2;
    float*    bsL    = S + OFF_BSL;
    float*    bsR    = S + OFF_BSR;
    float*    vL     = S + OFF_VL;
    float*    vR     = S + OFF_VR;
    float*    WcombL = alpha1;               // early temps, region reused later
    float*    WcombR = alpha1 + 256 * 512;

    cudaMemsetAsync(S, 0, ZEND * sizeof(float));

    dim3 tpb(256);
    const int MT = (NN + 127) / 128;   // 157 M-tiles

    // ---- Weight preps ----
    k_wprepT<<<(512 * 128  + 255) / 256, tpb>>>(W1,  B + B_W1H,  B + B_W1L,  128,  512, 512, 512, 128,  0);
    k_wprepT<<<(512 * 512  + 255) / 256, tpb>>>(W2,  B + B_W2H,  B + B_W2L,  512,  512, 512, 512, 512,  0);
    k_wprepT<<<(256 * 512  + 255) / 256, tpb>>>(Wc2, B + B_WC2H, B + B_WC2L, 512,  NCLS, 256, NCLS, 512, 0);
    k_wprepT<<<(512 * 512  + 255) / 256, tpb>>>(Wc1, B + B_WBH,  B + B_WBL,  512,  512, 512, 512, 1024, 0);
    k_wprepT<<<(512 * 512  + 255) / 256, tpb>>>(Wc1 + (size_t)512 * 512,  B + B_WM1H, B + B_WM1L, 512, 512, 512, 512, 512, 0);
    k_wprepT<<<(512 * 512  + 255) / 256, tpb>>>(Wc1 + (size_t)1024 * 512, B + B_WM2H, B + B_WM2L, 512, 512, 512, 512, 512, 0);
    k_split<<<(256 * 512 + 255) / 256, tpb>>>(We2, B + B_WE2AH, B + B_WE2AL, 256 * 512);
    k_vbias<<<2, tpb>>>(be2, Wc1, vL, vR);

    // Wcomb = We2 @ Wc1_mid/bot   [256, 512] fp32
    {
        dim3 g(2, 4);
        tgemm<<<g, tpb, TG_SMEM>>>(B + B_WE2AH, B + B_WE2AL, B + B_WM1H, B + B_WM1L,
                                   WcombL, nullptr, nullptr, 256, 512, 512, 512,
                                   nullptr, nullptr, nullptr, nullptr, nullptr, 0);
        tgemm<<<g, tpb, TG_SMEM>>>(B + B_WE2AH, B + B_WE2AL, B + B_WM2H, B + B_WM2L,
                                   WcombR, nullptr, nullptr, 256, 512, 512, 512,
                                   nullptr, nullptr, nullptr, nullptr, nullptr, 0);
    }
    k_wprepT<<<(512 * 256 + 255) / 256, tpb>>>(WcombL, B + B_WBH, B + B_WBL, 256, 512, 512, 512, 1024, 512);
    k_wprepT<<<(512 * 256 + 255) / 256, tpb>>>(WcombR, B + B_WBH, B + B_WBL, 256, 512, 512, 512, 1024, 768);

    // ---- GAT1 ----
    k_split<<<((int)SZ_XP + 255) / 256, tpb>>>(x_param, B + B_XPH, B + B_XPL, (int)SZ_XP);
    {
        dim3 g(MT, 4);
        tgemm<<<g, tpb, TG_SMEM>>>(B + B_XPH, B + B_XPL, B + B_W1H, B + B_W1L,
                                   xl1, nullptr, nullptr, NN, FIN, D1, D1,
                                   nullptr, nullptr, nullptr, nullptr, nullptr, 0);
    }
    k_sd1<<<(NN * HEADS + 255) / 256, tpb>>>(xl1, as1, ad1, s1, dd1);
    k_alpha1<<<(ESL * HEADS + 255) / 256, tpb>>>(ei, s1, dd1, alpha1, amax1);
    k_ex1<<<(ESL * HEADS + 255) / 256, tpb>>>(ei, alpha1, amax1, ex1, den1);
    k_agg1<<<(ESL * 32 + 255) / 256, tpb>>>(ei, xl1, ex1, den1, out1);
    k_elusplit<<<(NN * 512 + 255) / 256, tpb>>>(out1, b1, B + B_X1H, B + B_X1L);

    // ---- GAT2 (into G cols [0,512)) ----
    {
        dim3 g(MT, 4);
        tgemm<<<g, tpb, TG_SMEM>>>(B + B_X1H, B + B_X1L, B + B_W2H, B + B_W2L,
                                   xl2, nullptr, nullptr, NN, D1, REP, REP,
                                   nullptr, nullptr, nullptr, nullptr, nullptr, 0);
    }
    k_sd2<<<(NN * 32 + 255) / 256, tpb>>>(xl2, as2, ad2, s2, dd2);
    k_alpha2<<<(ESL + 255) / 256, tpb>>>(ei, s2, dd2, alpha2, amax2);
    k_ex2<<<(ESL + 255) / 256, tpb>>>(ei, alpha2, amax2, ex2, den2);
    k_agg2<<<(ESL * 32 + 255) / 256, tpb>>>(ei, xl2, ex2, den2, G);

    // ---- Synapse encoder hidden + scatter into G cols [512,1024) ----
    k_syn<<<(EE * 32 + 255) / 256, tpb>>>(ei, synapse, We1, be1, G, cntL, cntR);

    // ---- G post-process: bias + mean + split ----
    k_postG<<<(NN * 1024 + 255) / 256, tpb>>>(G, b2, cntL, cntR,
                                              B + B_GH, B + B_GL, bsL, bsR);

    // ---- Fused classifier layer 1 -> hidc bf16 split directly ----
    {
        dim3 g(MT, 4);
        tgemm<<<g, tpb, TG_SMEM>>>(B + B_GH, B + B_GL, B + B_WBH, B + B_WBL,
                                   nullptr, B + B_HCH, B + B_HCL, NN, 1024, 512, 512,
                                   bc1, vL, bsL, vR, bsR, 1);
    }
    // ---- Classifier layer 2 ----
    {
        dim3 g(MT, 2);
        tgemm<<<g, tpb, TG_SMEM>>>(B + B_HCH, B + B_HCL, B + B_WC2H, B + B_WC2L,
                                   out, nullptr, nullptr, NN, 512, NCLS, NCLS,
                                   bc2, nullptr, nullptr, nullptr, nullptr, 0);
    }
}

// round 6
// speedup vs baseline: 2.9645x; 1.3677x over previous
#include <cuda_runtime.h>
#include <cuda_bf16.h>
#include <cstdint>

// ---------------------------------------------------------------------------
// Problem constants
// ---------------------------------------------------------------------------
constexpr int NN   = 20000;
constexpr int FIN  = 128;
constexpr int HEADS = 8;
constexpr int HIDC  = 64;
constexpr int D1    = HEADS * HIDC;  // 512
constexpr int REP   = 512;
constexpr int NCLS  = 133;
constexpr int EE    = 200000;
constexpr int ESL   = EE + NN;       // 220000

// ---------------------------------------------------------------------------
// fp32 scratch
// ---------------------------------------------------------------------------
constexpr size_t OFF_S1   = 0;                            // 8N
constexpr size_t OFF_DD1  = OFF_S1  + (size_t)NN * 8;     // 8N
constexpr size_t OFF_S2   = OFF_DD1 + (size_t)NN * 8;     // N
constexpr size_t OFF_DD2  = OFF_S2  + (size_t)NN;         // N
constexpr size_t OFF_BSL  = OFF_DD2 + (size_t)NN;         // N
constexpr size_t OFF_BSR  = OFF_BSL + (size_t)NN;         // N
constexpr size_t OFF_VL   = OFF_BSR + (size_t)NN;         // 512
constexpr size_t OFF_VR   = OFF_VL  + 512;                // 512
constexpr size_t OFF_XL1  = OFF_VR  + 512;                // 512N (also Wcomb temps early)
constexpr size_t OFF_XL2  = OFF_XL1 + (size_t)NN * 512;   // 512N
constexpr size_t TOTALF   = OFF_XL2 + (size_t)NN * 512;

__device__ float g_scratch[TOTALF];

// ---------------------------------------------------------------------------
// int scratch (CSR)
// ---------------------------------------------------------------------------
constexpr size_t I_ROWD = 0;                    // N+1
constexpr size_t I_ROWS = I_ROWD + NN + 1;      // N+1
constexpr size_t I_WRD  = I_ROWS + NN + 1;      // N  (zeroed: histogram counters)
constexpr size_t I_WRS  = I_WRD  + NN;          // N  (zeroed)
constexpr size_t I_COLD = I_WRS  + NN;          // ESL
constexpr size_t I_COLS = I_COLD + ESL;         // EE
constexpr size_t TOTALI = I_COLS + EE;

__device__ int g_int[TOTALI];

// ---------------------------------------------------------------------------
// bf16 split scratch (hi/lo pairs). Weights stored transposed [NP, K].
// ---------------------------------------------------------------------------
constexpr size_t SZ_XP   = (size_t)NN * 128;
constexpr size_t SZ_X1   = (size_t)NN * 512;
constexpr size_t SZ_G    = (size_t)NN * 1024;
constexpr size_t SZ_HC   = (size_t)NN * 512;
constexpr size_t SZ_W1   = 512 * 128;
constexpr size_t SZ_W2   = 512 * 512;
constexpr size_t SZ_WB   = 512 * 1024;
constexpr size_t SZ_WC2  = 256 * 512;
constexpr size_t SZ_WM   = 512 * 512;
constexpr size_t SZ_WE2A = 256 * 512;

constexpr size_t B_XPH   = 0;
constexpr size_t B_XPL   = B_XPH   + SZ_XP;
constexpr size_t B_X1H   = B_XPL   + SZ_XP;
constexpr size_t B_X1L   = B_X1H   + SZ_X1;
constexpr size_t B_GH    = B_X1L   + SZ_X1;
constexpr size_t B_GL    = B_GH    + SZ_G;
constexpr size_t B_HCH   = B_GL    + SZ_G;
constexpr size_t B_HCL   = B_HCH   + SZ_HC;
constexpr size_t B_W1H   = B_HCL   + SZ_HC;
constexpr size_t B_W1L   = B_W1H   + SZ_W1;
constexpr size_t B_W2H   = B_W1L   + SZ_W1;
constexpr size_t B_W2L   = B_W2H   + SZ_W2;
constexpr size_t B_WBH   = B_W2L   + SZ_W2;
constexpr size_t B_WBL   = B_WBH   + SZ_WB;
constexpr size_t B_WC2H  = B_WBL   + SZ_WB;
constexpr size_t B_WC2L  = B_WC2H  + SZ_WC2;
constexpr size_t B_WM1H  = B_WC2L  + SZ_WC2;
constexpr size_t B_WM1L  = B_WM1H  + SZ_WM;
constexpr size_t B_WM2H  = B_WM1L  + SZ_WM;
constexpr size_t B_WM2L  = B_WM2H  + SZ_WM;
constexpr size_t B_WE2AH = B_WM2L  + SZ_WM;
constexpr size_t B_WE2AL = B_WE2AH + SZ_WE2A;
constexpr size_t TOTALB  = B_WE2AL + SZ_WE2A;

__device__ __align__(256) __nv_bfloat16 g_bf[TOTALB];

// ---------------------------------------------------------------------------
// Helpers
// ---------------------------------------------------------------------------
__device__ __forceinline__ uint32_t smem_to_u32(const void* p) {
    uint32_t a;
    asm("{ .reg .u64 t; cvta.to.shared.u64 t, %1; cvt.u32.u64 %0, t; }"
        : "=r"(a) : "l"(p));
    return a;
}
#define SWZ(off) ((off) ^ (((off) >> 3) & 0x70))
__device__ __forceinline__ float lrelu02(float x) { return x > 0.f ? x : 0.2f * x; }

__device__ __forceinline__ void split_store(__nv_bfloat16* __restrict__ h,
                                            __nv_bfloat16* __restrict__ l,
                                            size_t idx, float v) {
    __nv_bfloat16 hi = __float2bfloat16(v);
    h[idx] = hi;
    l[idx] = __float2bfloat16(v - __bfloat162float(hi));
}

// ---------------------------------------------------------------------------
// mma.sync GEMM (unchanged from R5): 3-pass bf16 split, 3-stage cp.async
// ---------------------------------------------------------------------------
constexpr int TG_SMEM = 3 * 32768;   // 96 KB

__global__ __launch_bounds__(256)
void tgemm(const __nv_bfloat16* __restrict__ Ah, const __nv_bfloat16* __restrict__ Al,
           const __nv_bfloat16* __restrict__ Bh, const __nv_bfloat16* __restrict__ Bl,
           float* __restrict__ C,
           __nv_bfloat16* __restrict__ Ch, __nv_bfloat16* __restrict__ Cl,
           int M, int K, int realN, int ldc,
           const float* __restrict__ bias,
           const float* __restrict__ v1, const float* __restrict__ s1,
           const float* __restrict__ v2, const float* __restrict__ s2,
           int relu)
{
    extern __shared__ __align__(1024) char smem[];
    const uint32_t sb = smem_to_u32(smem);
    const int tid = threadIdx.x;
    const int w = tid >> 5, l = tid & 31;
    const int m0 = blockIdx.x * 128, n0 = blockIdx.y * 128;
    const int wm = w & 1, wn = w >> 1;
    const int Kc = K >> 6;
    const int nch = 3 * Kc;

    float acc[4][4][4];
#pragma unroll
    for (int a = 0; a < 4; a++)
#pragma unroll
        for (int b = 0; b < 4; b++)
#pragma unroll
            for (int c = 0; c < 4; c++) acc[a][b][c] = 0.f;

    auto load_chunk = [&](int c) {
        int st = c % 3;
        int part = c / Kc, kblk = c - part * Kc;
        const __nv_bfloat16* As = (part < 2) ? Ah : Al;
        const __nv_bfloat16* Bs = (part == 1) ? Bl : Bh;
        uint32_t abase = sb + st * 32768;
        uint32_t bbase = abase + 16384;
#pragma unroll
        for (int j = 0; j < 4; j++) {
            int id = tid + j * 256;
            int r = id >> 3, ck = id & 7;
            {
                int grow = m0 + r;
                const void* g = As + (size_t)grow * K + kblk * 64 + ck * 8;
                uint32_t d = abase + SWZ((uint32_t)(r * 128 + ck * 16));
                int sz = (grow < M) ? 16 : 0;
                asm volatile("cp.async.cg.shared.global [%0], [%1], 16, %2;"
                             :: "r"(d), "l"(g), "r"(sz));
            }
            {
                const void* g = Bs + (size_t)(n0 + r) * K + kblk * 64 + ck * 8;
                uint32_t d = bbase + SWZ((uint32_t)(r * 128 + ck * 16));
                asm volatile("cp.async.cg.shared.global [%0], [%1], 16;"
                             :: "r"(d), "l"(g));
            }
        }
        asm volatile("cp.async.commit_group;" ::: "memory");
    };

    auto compute = [&](int c) {
        int st = c % 3;
        uint32_t abase = sb + st * 32768;
        uint32_t bbase = abase + 16384;
#pragma unroll
        for (int ks = 0; ks < 4; ks++) {
            int kb = ks * 16;
            uint32_t af[4][4];
#pragma unroll
            for (int mt = 0; mt < 4; mt++) {
                int m = wm * 64 + mt * 16 + (l & 7) + ((l >> 3) & 1) * 8;
                int ke = kb + (l >> 4) * 8;
                uint32_t addr = abase + SWZ((uint32_t)(m * 128 + ke * 2));
                asm volatile("ldmatrix.sync.aligned.m8n8.x4.shared.b16 {%0,%1,%2,%3}, [%4];"
                             : "=r"(af[mt][0]), "=r"(af[mt][1]),
                               "=r"(af[mt][2]), "=r"(af[mt][3]) : "r"(addr));
            }
            uint32_t bf[4][2];
#pragma unroll
            for (int g = 0; g < 2; g++) {
                int n = wn * 32 + g * 16 + ((l >> 4) & 1) * 8 + (l & 7);
                int ke = kb + ((l >> 3) & 1) * 8;
                uint32_t addr = bbase + SWZ((uint32_t)(n * 128 + ke * 2));
                uint32_t r0, r1, r2, r3;
                asm volatile("ldmatrix.sync.aligned.m8n8.x4.shared.b16 {%0,%1,%2,%3}, [%4];"
                             : "=r"(r0), "=r"(r1), "=r"(r2), "=r"(r3) : "r"(addr));
                bf[2 * g][0] = r0; bf[2 * g][1] = r1;
                bf[2 * g + 1][0] = r2; bf[2 * g + 1][1] = r3;
            }
#pragma unroll
            for (int mt = 0; mt < 4; mt++)
#pragma unroll
                for (int nt = 0; nt < 4; nt++) {
                    asm volatile(
                        "mma.sync.aligned.m16n8k16.row.col.f32.bf16.bf16.f32 "
                        "{%0,%1,%2,%3}, {%4,%5,%6,%7}, {%8,%9}, {%0,%1,%2,%3};"
                        : "+f"(acc[mt][nt][0]), "+f"(acc[mt][nt][1]),
                          "+f"(acc[mt][nt][2]), "+f"(acc[mt][nt][3])
                        : "r"(af[mt][0]), "r"(af[mt][1]), "r"(af[mt][2]), "r"(af[mt][3]),
                          "r"(bf[nt][0]), "r"(bf[nt][1]));
                }
        }
    };

    load_chunk(0);
    if (nch > 1) load_chunk(1);
    for (int c = 0; c < nch; c++) {
        if (c + 1 < nch)
            asm volatile("cp.async.wait_group 1;" ::: "memory");
        else
            asm volatile("cp.async.wait_group 0;" ::: "memory");
        __syncthreads();
        if (c + 2 < nch) load_chunk(c + 2);
        compute(c);
    }

    const int rbase = m0 + wm * 64, cbase = n0 + wn * 32;
#pragma unroll
    for (int mt = 0; mt < 4; mt++) {
#pragma unroll
        for (int half = 0; half < 2; half++) {
            int row = rbase + mt * 16 + (l >> 2) + half * 8;
            if (row >= M) continue;
            float a1 = s1 ? s1[row] : 0.f;
            float a2 = s2 ? s2[row] : 0.f;
#pragma unroll
            for (int nt = 0; nt < 4; nt++) {
                int col = cbase + nt * 8 + (l & 3) * 2;
#pragma unroll
                for (int q = 0; q < 2; q++) {
                    int cc = col + q;
                    if (cc >= realN) continue;
                    float v = acc[mt][nt][half * 2 + q];
                    if (bias) v += bias[cc];
                    if (v1) v += a1 * v1[cc];
                    if (v2) v += a2 * v2[cc];
                    if (relu) v = fmaxf(v, 0.f);
                    if (Ch) {
                        split_store(Ch, Cl, (size_t)row * ldc + cc, v);
                    } else {
                        C[(size_t)row * ldc + cc] = v;
                    }
                }
            }
        }
    }
}

// ---------------------------------------------------------------------------
// bf16 split / weight preps
// ---------------------------------------------------------------------------
__global__ void k_split(const float* __restrict__ x, __nv_bfloat16* __restrict__ h,
                        __nv_bfloat16* __restrict__ l, int n)
{
    int i = blockIdx.x * blockDim.x + threadIdx.x;
    if (i >= n) return;
    split_store(h, l, i, x[i]);
}

__global__ void k_wprepT(const float* __restrict__ W, __nv_bfloat16* __restrict__ h,
                         __nv_bfloat16* __restrict__ l, int K, int N, int NP,
                         int ldW, int ldout, int koff)
{
    int i = blockIdx.x * blockDim.x + threadIdx.x;
    if (i >= NP * K) return;
    int n = i / K, k = i - n * K;
    float v = (n < N) ? W[(size_t)k * ldW + n] : 0.f;
    split_store(h, l, (size_t)n * ldout + koff + k, v);
}

__global__ void k_vbias(const float* __restrict__ be2, const float* __restrict__ Wc1,
                        float* __restrict__ vL, float* __restrict__ vR)
{
    int c = blockIdx.x * blockDim.x + threadIdx.x;
    if (c >= 512) return;
    float sL = 0.f, sR = 0.f;
    for (int k = 0; k < 512; k++) {
        float b = be2[k];
        sL += b * Wc1[(size_t)(512 + k) * 512 + c];
        sR += b * Wc1[(size_t)(1024 + k) * 512 + c];
    }
    vL[c] = sL; vR[c] = sR;
}

// ---------------------------------------------------------------------------
// CSR build
// ---------------------------------------------------------------------------
__global__ void k_hist(const int* __restrict__ ei, int* __restrict__ wrD,
                       int* __restrict__ wrS)
{
    int e = blockIdx.x * blockDim.x + threadIdx.x;
    if (e >= ESL) return;
    int dst = (e < EE) ? ei[EE + e] : e - EE;
    atomicAdd(wrD + dst, 1);
    if (e < EE) atomicAdd(wrS + ei[e], 1);
}

// exclusive scan of wrD/wrS -> rowD/rowS; resets wr to row starts
__global__ __launch_bounds__(1024)
void k_scan(int* __restrict__ wrD, int* __restrict__ wrS,
            int* __restrict__ rowD, int* __restrict__ rowS)
{
    __shared__ int sm[1024];
    const int t = threadIdx.x;
    const int CH = (NN + 1023) / 1024;
    for (int a = 0; a < 2; a++) {
        int* deg = a ? wrS : wrD;
        int* row = a ? rowS : rowD;
        int start = t * CH;
        int end = min(start + CH, NN);
        int s = 0;
        for (int i = start; i < end; i++) s += deg[i];
        sm[t] = s;
        __syncthreads();
        for (int off = 1; off < 1024; off <<= 1) {
            int v = (t >= off) ? sm[t - off] : 0;
            __syncthreads();
            sm[t] += v;
            __syncthreads();
        }
        int run = (t == 0) ? 0 : sm[t - 1];
        if (t == 0) row[NN] = sm[1023];
        for (int i = start; i < end; i++) {
            int d = deg[i];
            row[i] = run;
            deg[i] = run;          // reset as write cursor
            run += d;
        }
        __syncthreads();
    }
}

__global__ void k_scatter(const int* __restrict__ ei, int* __restrict__ wrD,
                          int* __restrict__ wrS, int* __restrict__ colD,
                          int* __restrict__ colS)
{
    int e = blockIdx.x * blockDim.x + threadIdx.x;
    if (e >= ESL) return;
    int dst = (e < EE) ? ei[EE + e] : e - EE;
    colD[atomicAdd(wrD + dst, 1)] = e;
    if (e < EE) colS[atomicAdd(wrS + ei[e], 1)] = e;
}

// ---------------------------------------------------------------------------
// Node-level attention logits
// ---------------------------------------------------------------------------
__global__ void k_sd1(const float* __restrict__ xl1,
                      const float* __restrict__ as1, const float* __restrict__ ad1,
                      float* __restrict__ s1, float* __restrict__ d1)
{
    int idx = blockIdx.x * blockDim.x + threadIdx.x;
    if (idx >= NN * HEADS) return;
    int n = idx >> 3, h = idx & 7;
    const float4* xr = (const float4*)(xl1 + (size_t)n * 512 + h * 64);
    const float4* av = (const float4*)(as1 + h * 64);
    const float4* bv = (const float4*)(ad1 + h * 64);
    float ss = 0.f, dd = 0.f;
#pragma unroll
    for (int q = 0; q < 16; q++) {
        float4 x = xr[q], a = av[q], b = bv[q];
        ss += x.x * a.x + x.y * a.y + x.z * a.z + x.w * a.w;
        dd += x.x * b.x + x.y * b.y + x.z * b.z + x.w * b.w;
    }
    s1[idx] = ss; d1[idx] = dd;
}

__global__ void k_sd2(const float* __restrict__ xl2,
                      const float* __restrict__ as2, const float* __restrict__ ad2,
                      float* __restrict__ s2, float* __restrict__ d2)
{
    int warp = (blockIdx.x * blockDim.x + threadIdx.x) >> 5;
    int lane = threadIdx.x & 31;
    if (warp >= NN) return;
    const float4* xr = (const float4*)(xl2 + (size_t)warp * 512) + lane * 4;
    const float4* av = (const float4*)as2 + lane * 4;
    const float4* bv = (const float4*)ad2 + lane * 4;
    float ss = 0.f, dd = 0.f;
#pragma unroll
    for (int q = 0; q < 4; q++) {
        float4 x = xr[q], a = av[q], b = bv[q];
        ss += x.x * a.x + x.y * a.y + x.z * a.z + x.w * a.w;
        dd += x.x * b.x + x.y * b.y + x.z * b.z + x.w * b.w;
    }
#pragma unroll
    for (int o = 16; o > 0; o >>= 1) {
        ss += __shfl_xor_sync(0xffffffffu, ss, o);
        dd += __shfl_xor_sync(0xffffffffu, dd, o);
    }
    if (lane == 0) { s2[warp] = ss; d2[warp] = dd; }
}

// ---------------------------------------------------------------------------
// GAT1: fused gather softmax + aggregate + bias + ELU + bf16 split
// warp per dst node, 8 heads tracked by lanes 0-7
// ---------------------------------------------------------------------------
__global__ __launch_bounds__(256)
void k_att1(const int* __restrict__ ei, const int* __restrict__ rowD,
            const int* __restrict__ colD, const float* __restrict__ xl1,
            const float* __restrict__ s1, const float* __restrict__ dd1,
            const float* __restrict__ b1,
            __nv_bfloat16* __restrict__ xh, __nv_bfloat16* __restrict__ xl)
{
    int n = (blockIdx.x * blockDim.x + threadIdx.x) >> 5;
    int lane = threadIdx.x & 31;
    if (n >= NN) return;
    int base = rowD[n], cnt = rowD[n + 1] - base;
    float dval = (lane < 8) ? dd1[n * 8 + lane] : 0.f;

    float mx = -1e30f;
    for (int i = 0; i < cnt; i++) {
        int eid = colD[base + i];
        int src = (eid < EE) ? ei[eid] : n;
        if (lane < 8)
            mx = fmaxf(mx, lrelu02(s1[src * 8 + lane] + dval));
    }
    float den = 0.f;
    for (int i = 0; i < cnt; i++) {
        int eid = colD[base + i];
        int src = (eid < EE) ? ei[eid] : n;
        if (lane < 8)
            den += expf(lrelu02(s1[src * 8 + lane] + dval) - mx);
    }
    float inv = 1.f / (den + 1e-16f);

    float acc[16];
#pragma unroll
    for (int q = 0; q < 16; q++) acc[q] = 0.f;
    for (int i = 0; i < cnt; i++) {
        int eid = colD[base + i];
        int src = (eid < EE) ? ei[eid] : n;
        float w = 0.f;
        if (lane < 8)
            w = expf(lrelu02(s1[src * 8 + lane] + dval) - mx) * inv;
        const float4* xr = (const float4*)(xl1 + (size_t)src * 512);
#pragma unroll
        for (int j = 0; j < 4; j++) {
            float wv = __shfl_sync(0xffffffffu, w, 2 * j + (lane >> 4));
            float4 v = xr[j * 32 + lane];
            acc[j * 4 + 0] += wv * v.x;
            acc[j * 4 + 1] += wv * v.y;
            acc[j * 4 + 2] += wv * v.z;
            acc[j * 4 + 3] += wv * v.w;
        }
    }
#pragma unroll
    for (int j = 0; j < 4; j++) {
        int c0 = (j * 32 + lane) * 4;
#pragma unroll
        for (int q = 0; q < 4; q++) {
            float v = acc[j * 4 + q] + b1[c0 + q];
            v = v > 0.f ? v : expm1f(v);
            split_store(xh, xl, (size_t)n * 512 + c0 + q, v);
        }
    }
}

// ---------------------------------------------------------------------------
// GAT2: fused gather softmax (1 head) + aggregate + b2 + bf16 split into G[0,512)
// ---------------------------------------------------------------------------
__global__ __launch_bounds__(256)
void k_att2(const int* __restrict__ ei, const int* __restrict__ rowD,
            const int* __restrict__ colD, const float* __restrict__ xl2,
            const float* __restrict__ s2, const float* __restrict__ d2,
            const float* __restrict__ b2,
            __nv_bfloat16* __restrict__ Gh, __nv_bfloat16* __restrict__ Gl)
{
    int n = (blockIdx.x * blockDim.x + threadIdx.x) >> 5;
    int lane = threadIdx.x & 31;
    if (n >= NN) return;
    int base = rowD[n], cnt = rowD[n + 1] - base;
    float dn = d2[n];

    float mx = -1e30f;
    for (int i = lane; i < cnt; i += 32) {
        int eid = colD[base + i];
        int src = (eid < EE) ? ei[eid] : n;
        mx = fmaxf(mx, lrelu02(s2[src] + dn));
    }
#pragma unroll
    for (int o = 16; o > 0; o >>= 1)
        mx = fmaxf(mx, __shfl_xor_sync(0xffffffffu, mx, o));

    float den = 0.f;
    for (int i = lane; i < cnt; i += 32) {
        int eid = colD[base + i];
        int src = (eid < EE) ? ei[eid] : n;
        den += expf(lrelu02(s2[src] + dn) - mx);
    }
#pragma unroll
    for (int o = 16; o > 0; o >>= 1)
        den += __shfl_xor_sync(0xffffffffu, den, o);
    float inv = 1.f / (den + 1e-16f);

    float acc[16];
#pragma unroll
    for (int q = 0; q < 16; q++) acc[q] = 0.f;
    for (int i = 0; i < cnt; i++) {
        int eid = colD[base + i];
        int src = (eid < EE) ? ei[eid] : n;
        float w = expf(lrelu02(s2[src] + dn) - mx) * inv;
        const float4* xr = (const float4*)(xl2 + (size_t)src * 512);
#pragma unroll
        for (int j = 0; j < 4; j++) {
            float4 v = xr[j * 32 + lane];
            acc[j * 4 + 0] += w * v.x;
            acc[j * 4 + 1] += w * v.y;
            acc[j * 4 + 2] += w * v.z;
            acc[j * 4 + 3] += w * v.w;
        }
    }
#pragma unroll
    for (int j = 0; j < 4; j++) {
        int c0 = (j * 32 + lane) * 4;
#pragma unroll
        for (int q = 0; q < 4; q++) {
            float v = acc[j * 4 + q] + b2[c0 + q];
            split_store(Gh, Gl, (size_t)n * 1024 + c0 + q, v);
        }
    }
}

// ---------------------------------------------------------------------------
// Synapse gather-mean: warp per node; recompute maxpool+MLP hidden per edge.
// skipSelf=1 -> csrD traversal skipping self-loop entries (eid>=EE).
// ---------------------------------------------------------------------------
__global__ __launch_bounds__(256)
void k_syng(const int* __restrict__ row, const int* __restrict__ col, int skipSelf,
            const float* __restrict__ synapse,
            const float* __restrict__ We1, const float* __restrict__ be1,
            __nv_bfloat16* __restrict__ Gh, __nv_bfloat16* __restrict__ Gl,
            int colOff, float* __restrict__ bs)
{
    __shared__ float sWe[6 * 256];
    __shared__ float sbe[256];
    for (int i = threadIdx.x; i < 6 * 256; i += blockDim.x) sWe[i] = We1[i];
    for (int i = threadIdx.x; i < 256; i += blockDim.x) sbe[i] = be1[i];
    __syncthreads();

    int n = (blockIdx.x * blockDim.x + threadIdx.x) >> 5;
    int lane = threadIdx.x & 31;
    if (n >= NN) return;
    int base = row[n], cnt = row[n + 1] - base;

    float acc[8];
#pragma unroll
    for (int o = 0; o < 8; o++) acc[o] = 0.f;
    int realc = 0;
    for (int i = 0; i < cnt; i++) {
        int eid = col[base + i];
        if (skipSelf && eid >= EE) continue;
        realc++;
        float m = 0.f;
        if (lane < 6) {
            const float* sp = synapse + (size_t)eid * 24 + lane;
            m = sp[0];
            m = fmaxf(m, sp[6]);
            m = fmaxf(m, sp[12]);
            m = fmaxf(m, sp[18]);
        }
        float xp[6];
#pragma unroll
        for (int j = 0; j < 6; j++) xp[j] = __shfl_sync(0xffffffffu, m, j);
#pragma unroll
        for (int o = 0; o < 8; o++) {
            int c = lane * 8 + o;
            float h = sbe[c];
#pragma unroll
            for (int k = 0; k < 6; k++) h += xp[k] * sWe[k * 256 + c];
            acc[o] += fmaxf(h, 0.f);
        }
    }
    float sc = 1.f / (float)max(realc, 1);
#pragma unroll
    for (int o = 0; o < 8; o++)
        split_store(Gh, Gl, (size_t)n * 1024 + colOff + lane * 8 + o, acc[o] * sc);
    if (lane == 0) bs[n] = realc > 0 ? 1.f : 0.f;
}

// ---------------------------------------------------------------------------
// Host launcher
// ---------------------------------------------------------------------------
extern "C" void kernel_launch(void* const* d_in, const int* in_sizes, int n_in,
                              void* d_out, int out_size)
{
    const int*   ei      = (const int*)d_in[0];
    const float* synapse = (const float*)d_in[2];
    int ib = 4;
    if (n_in > 4 && in_sizes[4] == 1) ib = 5;
    const float* x_param = (const float*)d_in[ib + 0];
    const float* W1  = (const float*)d_in[ib + 1];
    const float* as1 = (const float*)d_in[ib + 2];
    const float* ad1 = (const float*)d_in[ib + 3];
    const float* b1  = (const float*)d_in[ib + 4];
    const float* W2  = (const float*)d_in[ib + 5];
    const float* as2 = (const float*)d_in[ib + 6];
    const float* ad2 = (const float*)d_in[ib + 7];
    const float* b2  = (const float*)d_in[ib + 8];
    const float* We1 = (const float*)d_in[ib + 9];
    const float* be1 = (const float*)d_in[ib + 10];
    const float* We2 = (const float*)d_in[ib + 11];
    const float* be2 = (const float*)d_in[ib + 12];
    const float* Wc1 = (const float*)d_in[ib + 13];
    const float* bc1 = (const float*)d_in[ib + 14];
    const float* Wc2 = (const float*)d_in[ib + 15];
    const float* bc2 = (const float*)d_in[ib + 16];
    float* out = (float*)d_out;

    void* sp = nullptr;  cudaGetSymbolAddress(&sp, g_scratch);
    float* S = (float*)sp;
    void* bp = nullptr;  cudaGetSymbolAddress(&bp, g_bf);
    __nv_bfloat16* B = (__nv_bfloat16*)bp;
    void* ip = nullptr;  cudaGetSymbolAddress(&ip, g_int);
    int* I = (int*)ip;

    cudaFuncSetAttribute(tgemm, cudaFuncAttributeMaxDynamicSharedMemorySize, TG_SMEM);

    float* s1  = S + OFF_S1;
    float* dd1 = S + OFF_DD1;
    float* s2  = S + OFF_S2;
    float* dd2 = S + OFF_DD2;
    float* bsL = S + OFF_BSL;
    float* bsR = S + OFF_BSR;
    float* vL  = S + OFF_VL;
    float* vR  = S + OFF_VR;
    float* xl1 = S + OFF_XL1;
    float* xl2 = S + OFF_XL2;
    float* WcombL = xl1;                 // temps; consumed before GEMM1 writes xl1
    float* WcombR = xl1 + 256 * 512;

    int* rowD = I + I_ROWD;
    int* rowS = I + I_ROWS;
    int* wrD  = I + I_WRD;
    int* wrS  = I + I_WRS;
    int* colD = I + I_COLD;
    int* colS = I + I_COLS;

    cudaMemsetAsync(wrD, 0, 2 * NN * sizeof(int));

    dim3 tpb(256);
    const int MT = (NN + 127) / 128;
    const int NW = (NN * 32 + 255) / 256;    // warp-per-node grids

    // ---- CSR build ----
    k_hist<<<(ESL + 255) / 256, tpb>>>(ei, wrD, wrS);
    k_scan<<<1, 1024>>>(wrD, wrS, rowD, rowS);
    k_scatter<<<(ESL + 255) / 256, tpb>>>(ei, wrD, wrS, colD, colS);

    // ---- Weight preps ----
    k_wprepT<<<(512 * 128  + 255) / 256, tpb>>>(W1,  B + B_W1H,  B + B_W1L,  128,  512, 512, 512, 128,  0);
    k_wprepT<<<(512 * 512  + 255) / 256, tpb>>>(W2,  B + B_W2H,  B + B_W2L,  512,  512, 512, 512, 512,  0);
    k_wprepT<<<(256 * 512  + 255) / 256, tpb>>>(Wc2, B + B_WC2H, B + B_WC2L, 512,  NCLS, 256, NCLS, 512, 0);
    k_wprepT<<<(512 * 512  + 255) / 256, tpb>>>(Wc1, B + B_WBH,  B + B_WBL,  512,  512, 512, 512, 1024, 0);
    k_wprepT<<<(512 * 512  + 255) / 256, tpb>>>(Wc1 + (size_t)512 * 512,  B + B_WM1H, B + B_WM1L, 512, 512, 512, 512, 512, 0);
    k_wprepT<<<(512 * 512  + 255) / 256, tpb>>>(Wc1 + (size_t)1024 * 512, B + B_WM2H, B + B_WM2L, 512, 512, 512, 512, 512, 0);
    k_split<<<(256 * 512 + 255) / 256, tpb>>>(We2, B + B_WE2AH, B + B_WE2AL, 256 * 512);
    k_vbias<<<2, tpb>>>(be2, Wc1, vL, vR);

    // Wcomb = We2 @ Wc1_mid/bot
    {
        dim3 g(2, 4);
        tgemm<<<g, tpb, TG_SMEM>>>(B + B_WE2AH, B + B_WE2AL, B + B_WM1H, B + B_WM1L,
                                   WcombL, nullptr, nullptr, 256, 512, 512, 512,
                                   nullptr, nullptr, nullptr, nullptr, nullptr, 0);
        tgemm<<<g, tpb, TG_SMEM>>>(B + B_WE2AH, B + B_WE2AL, B + B_WM2H, B + B_WM2L,
                                   WcombR, nullptr, nullptr, 256, 512, 512, 512,
                                   nullptr, nullptr, nullptr, nullptr, nullptr, 0);
    }
    k_wprepT<<<(512 * 256 + 255) / 256, tpb>>>(WcombL, B + B_WBH, B + B_WBL, 256, 512, 512, 512, 1024, 512);
    k_wprepT<<<(512 * 256 + 255) / 256, tpb>>>(WcombR, B + B_WBH, B + B_WBL, 256, 512, 512, 512, 1024, 768);

    // ---- GAT1 ----
    k_split<<<((int)SZ_XP + 255) / 256, tpb>>>(x_param, B + B_XPH, B + B_XPL, (int)SZ_XP);
    {
        dim3 g(MT, 4);
        tgemm<<<g, tpb, TG_SMEM>>>(B + B_XPH, B + B_XPL, B + B_W1H, B + B_W1L,
                                   xl1, nullptr, nullptr, NN, FIN, D1, D1,
                                   nullptr, nullptr, nullptr, nullptr, nullptr, 0);
    }
    k_sd1<<<(NN * HEADS + 255) / 256, tpb>>>(xl1, as1, ad1, s1, dd1);
    k_att1<<<NW, tpb>>>(ei, rowD, colD, xl1, s1, dd1, b1, B + B_X1H, B + B_X1L);

    // ---- GAT2 ----
    {
        dim3 g(MT, 4);
        tgemm<<<g, tpb, TG_SMEM>>>(B + B_X1H, B + B_X1L, B + B_W2H, B + B_W2L,
                                   xl2, nullptr, nullptr, NN, D1, REP, REP,
                                   nullptr, nullptr, nullptr, nullptr, nullptr, 0);
    }
    k_sd2<<<(NN * 32 + 255) / 256, tpb>>>(xl2, as2, ad2, s2, dd2);
    k_att2<<<NW, tpb>>>(ei, rowD, colD, xl2, s2, dd2, b2, B + B_GH, B + B_GL);

    // ---- Synapse gather-means into G cols [512,1024) ----
    k_syng<<<NW, tpb>>>(rowS, colS, 0, synapse, We1, be1, B + B_GH, B + B_GL, 512, bsL);
    k_syng<<<NW, tpb>>>(rowD, colD, 1, synapse, We1, be1, B + B_GH, B + B_GL, 768, bsR);

    // ---- Fused classifier layer 1 -> hidc bf16 split ----
    {
        dim3 g(MT, 4);
        tgemm<<<g, tpb, TG_SMEM>>>(B + B_GH, B + B_GL, B + B_WBH, B + B_WBL,
                                   nullptr, B + B_HCH, B + B_HCL, NN, 1024, 512, 512,
                                   bc1, vL, bsL, vR, bsR, 1);
    }
    // ---- Classifier layer 2 ----
    {
        dim3 g(MT, 2);
        tgemm<<<g, tpb, TG_SMEM>>>(B + B_HCH, B + B_HCL, B + B_WC2H, B + B_WC2L,
                                   out, nullptr, nullptr, NN, 512, NCLS, NCLS,
                                   bc2, nullptr, nullptr, nullptr, nullptr, 0);
    }
}

// round 8
// speedup vs baseline: 3.0533x; 1.0300x over previous
#include <cuda_runtime.h>
#include <cuda_bf16.h>
#include <cstdint>

// ---------------------------------------------------------------------------
// Problem constants
// ---------------------------------------------------------------------------
constexpr int NN   = 20000;
constexpr int FIN  = 128;
constexpr int HEADS = 8;
constexpr int HIDC  = 64;
constexpr int D1    = HEADS * HIDC;  // 512
constexpr int REP   = 512;
constexpr int NCLS  = 133;
constexpr int EE    = 200000;
constexpr int ESL   = EE + NN;       // 220000

// ---------------------------------------------------------------------------
// fp32 scratch
// ---------------------------------------------------------------------------
constexpr size_t OFF_S1   = 0;                            // 8N
constexpr size_t OFF_DD1  = OFF_S1  + (size_t)NN * 8;     // 8N
constexpr size_t OFF_S2   = OFF_DD1 + (size_t)NN * 8;     // N
constexpr size_t OFF_DD2  = OFF_S2  + (size_t)NN;         // N
constexpr size_t OFF_BSL  = OFF_DD2 + (size_t)NN;         // N
constexpr size_t OFF_BSR  = OFF_BSL + (size_t)NN;         // N
constexpr size_t OFF_VL   = OFF_BSR + (size_t)NN;         // 512
constexpr size_t OFF_VR   = OFF_VL  + 512;                // 512
constexpr size_t OFF_XL1  = OFF_VR  + 512;                // 512N (also Wcomb temp early)
constexpr size_t OFF_XL2  = OFF_XL1 + (size_t)NN * 512;   // 512N
constexpr size_t TOTALF   = OFF_XL2 + (size_t)NN * 512;

__device__ float g_scratch[TOTALF];

// ---------------------------------------------------------------------------
// int scratch (CSR)
// ---------------------------------------------------------------------------
constexpr size_t I_ROWD = 0;                    // N+1
constexpr size_t I_ROWS = I_ROWD + NN + 1;      // N+1
constexpr size_t I_WRD  = I_ROWS + NN + 1;      // N (zeroed)
constexpr size_t I_WRS  = I_WRD  + NN;          // N (zeroed)
constexpr size_t I_COLD = I_WRS  + NN;          // ESL
constexpr size_t I_COLS = I_COLD + ESL;         // EE
constexpr size_t TOTALI = I_COLS + EE;

__device__ int g_int[TOTALI];

// ---------------------------------------------------------------------------
// bf16 split scratch (hi/lo pairs). Weights stored transposed [NP, K].
// ---------------------------------------------------------------------------
constexpr size_t SZ_XP   = (size_t)NN * 128;
constexpr size_t SZ_X1   = (size_t)NN * 512;
constexpr size_t SZ_G    = (size_t)NN * 1024;
constexpr size_t SZ_HC   = (size_t)NN * 512;
constexpr size_t SZ_W1   = 512 * 128;
constexpr size_t SZ_W2   = 512 * 512;
constexpr size_t SZ_WB   = 512 * 1024;
constexpr size_t SZ_WC2  = 256 * 512;
constexpr size_t SZ_WM   = 1024 * 512;   // stacked Wc1 mid+bot [1024, 512]
constexpr size_t SZ_WE2A = 256 * 512;

constexpr size_t B_XPH   = 0;
constexpr size_t B_XPL   = B_XPH   + SZ_XP;
constexpr size_t B_X1H   = B_XPL   + SZ_XP;
constexpr size_t B_X1L   = B_X1H   + SZ_X1;
constexpr size_t B_GH    = B_X1L   + SZ_X1;
constexpr size_t B_GL    = B_GH    + SZ_G;
constexpr size_t B_HCH   = B_GL    + SZ_G;
constexpr size_t B_HCL   = B_HCH   + SZ_HC;
constexpr size_t B_W1H   = B_HCL   + SZ_HC;
constexpr size_t B_W1L   = B_W1H   + SZ_W1;
constexpr size_t B_W2H   = B_W1L   + SZ_W1;
constexpr size_t B_W2L   = B_W2H   + SZ_W2;
constexpr size_t B_WBH   = B_W2L   + SZ_W2;
constexpr size_t B_WBL   = B_WBH   + SZ_WB;
constexpr size_t B_WC2H  = B_WBL   + SZ_WB;
constexpr size_t B_WC2L  = B_WC2H  + SZ_WC2;
constexpr size_t B_WMH   = B_WC2L  + SZ_WC2;
constexpr size_t B_WML   = B_WMH   + SZ_WM;
constexpr size_t B_WE2AH = B_WML   + SZ_WM;
constexpr size_t B_WE2AL = B_WE2AH + SZ_WE2A;
constexpr size_t TOTALB  = B_WE2AL + SZ_WE2A;

__device__ __align__(256) __nv_bfloat16 g_bf[TOTALB];

// ---------------------------------------------------------------------------
// Helpers
// ---------------------------------------------------------------------------
__device__ __forceinline__ uint32_t smem_to_u32(const void* p) {
    uint32_t a;
    asm("{ .reg .u64 t; cvta.to.shared.u64 t, %1; cvt.u32.u64 %0, t; }"
        : "=r"(a) : "l"(p));
    return a;
}
#define SWZ(off) ((off) ^ (((off) >> 3) & 0x70))
__device__ __forceinline__ float lrelu02(float x) { return x > 0.f ? x : 0.2f * x; }

__device__ __forceinline__ void split_store(__nv_bfloat16* __restrict__ h,
                                            __nv_bfloat16* __restrict__ l,
                                            size_t idx, float v) {
    __nv_bfloat16 hi = __float2bfloat16(v);
    h[idx] = hi;
    l[idx] = __float2bfloat16(v - __bfloat162float(hi));
}

// ---------------------------------------------------------------------------
// mma.sync GEMM: 3-pass bf16 split, 3-stage cp.async.
// n-tile on blockIdx.x so consecutive blocks share the SAME A tile (L2 reuse).
// ---------------------------------------------------------------------------
constexpr int TG_SMEM = 3 * 32768;   // 96 KB

__global__ __launch_bounds__(256)
void tgemm(const __nv_bfloat16* __restrict__ Ah, const __nv_bfloat16* __restrict__ Al,
           const __nv_bfloat16* __restrict__ Bh, const __nv_bfloat16* __restrict__ Bl,
           float* __restrict__ C,
           __nv_bfloat16* __restrict__ Ch, __nv_bfloat16* __restrict__ Cl,
           int M, int K, int realN, int ldc,
           const float* __restrict__ bias,
           const float* __restrict__ v1, const float* __restrict__ s1,
           const float* __restrict__ v2, const float* __restrict__ s2,
           int relu)
{
    extern __shared__ __align__(1024) char smem[];
    const uint32_t sb = smem_to_u32(smem);
    const int tid = threadIdx.x;
    const int w = tid >> 5, l = tid & 31;
    const int m0 = blockIdx.y * 128, n0 = blockIdx.x * 128;
    const int wm = w & 1, wn = w >> 1;
    const int Kc = K >> 6;
    const int nch = 3 * Kc;

    float acc[4][4][4];
#pragma unroll
    for (int a = 0; a < 4; a++)
#pragma unroll
        for (int b = 0; b < 4; b++)
#pragma unroll
            for (int c = 0; c < 4; c++) acc[a][b][c] = 0.f;

    auto load_chunk = [&](int c) {
        int st = c % 3;
        int part = c / Kc, kblk = c - part * Kc;
        const __nv_bfloat16* As = (part < 2) ? Ah : Al;
        const __nv_bfloat16* Bs = (part == 1) ? Bl : Bh;
        uint32_t abase = sb + st * 32768;
        uint32_t bbase = abase + 16384;
#pragma unroll
        for (int j = 0; j < 4; j++) {
            int id = tid + j * 256;
            int r = id >> 3, ck = id & 7;
            {
                int grow = m0 + r;
                const void* g = As + (size_t)grow * K + kblk * 64 + ck * 8;
                uint32_t d = abase + SWZ((uint32_t)(r * 128 + ck * 16));
                int sz = (grow < M) ? 16 : 0;
                asm volatile("cp.async.cg.shared.global [%0], [%1], 16, %2;"
                             :: "r"(d), "l"(g), "r"(sz));
            }
            {
                const void* g = Bs + (size_t)(n0 + r) * K + kblk * 64 + ck * 8;
                uint32_t d = bbase + SWZ((uint32_t)(r * 128 + ck * 16));
                asm volatile("cp.async.cg.shared.global [%0], [%1], 16;"
                             :: "r"(d), "l"(g));
            }
        }
        asm volatile("cp.async.commit_group;" ::: "memory");
    };

    auto compute = [&](int c) {
        int st = c % 3;
        uint32_t abase = sb + st * 32768;
        uint32_t bbase = abase + 16384;
#pragma unroll
        for (int ks = 0; ks < 4; ks++) {
            int kb = ks * 16;
            uint32_t af[4][4];
#pragma unroll
            for (int mt = 0; mt < 4; mt++) {
                int m = wm * 64 + mt * 16 + (l & 7) + ((l >> 3) & 1) * 8;
                int ke = kb + (l >> 4) * 8;
                uint32_t addr = abase + SWZ((uint32_t)(m * 128 + ke * 2));
                asm volatile("ldmatrix.sync.aligned.m8n8.x4.shared.b16 {%0,%1,%2,%3}, [%4];"
                             : "=r"(af[mt][0]), "=r"(af[mt][1]),
                               "=r"(af[mt][2]), "=r"(af[mt][3]) : "r"(addr));
            }
            uint32_t bf[4][2];
#pragma unroll
            for (int g = 0; g < 2; g++) {
                int n = wn * 32 + g * 16 + ((l >> 4) & 1) * 8 + (l & 7);
                int ke = kb + ((l >> 3) & 1) * 8;
                uint32_t addr = bbase + SWZ((uint32_t)(n * 128 + ke * 2));
                uint32_t r0, r1, r2, r3;
                asm volatile("ldmatrix.sync.aligned.m8n8.x4.shared.b16 {%0,%1,%2,%3}, [%4];"
                             : "=r"(r0), "=r"(r1), "=r"(r2), "=r"(r3) : "r"(addr));
                bf[2 * g][0] = r0; bf[2 * g][1] = r1;
                bf[2 * g + 1][0] = r2; bf[2 * g + 1][1] = r3;
            }
#pragma unroll
            for (int mt = 0; mt < 4; mt++)
#pragma unroll
                for (int nt = 0; nt < 4; nt++) {
                    asm volatile(
                        "mma.sync.aligned.m16n8k16.row.col.f32.bf16.bf16.f32 "
                        "{%0,%1,%2,%3}, {%4,%5,%6,%7}, {%8,%9}, {%0,%1,%2,%3};"
                        : "+f"(acc[mt][nt][0]), "+f"(acc[mt][nt][1]),
                          "+f"(acc[mt][nt][2]), "+f"(acc[mt][nt][3])
                        : "r"(af[mt][0]), "r"(af[mt][1]), "r"(af[mt][2]), "r"(af[mt][3]),
                          "r"(bf[nt][0]), "r"(bf[nt][1]));
                }
        }
    };

    load_chunk(0);
    if (nch > 1) load_chunk(1);
    for (int c = 0; c < nch; c++) {
        if (c + 1 < nch)
            asm volatile("cp.async.wait_group 1;" ::: "memory");
        else
            asm volatile("cp.async.wait_group 0;" ::: "memory");
        __syncthreads();
        if (c + 2 < nch) load_chunk(c + 2);
        compute(c);
    }

    const int rbase = m0 + wm * 64, cbase = n0 + wn * 32;
#pragma unroll
    for (int mt = 0; mt < 4; mt++) {
#pragma unroll
        for (int half = 0; half < 2; half++) {
            int row = rbase + mt * 16 + (l >> 2) + half * 8;
            if (row >= M) continue;
            float a1 = s1 ? s1[row] : 0.f;
            float a2 = s2 ? s2[row] : 0.f;
#pragma unroll
            for (int nt = 0; nt < 4; nt++) {
                int col = cbase + nt * 8 + (l & 3) * 2;
#pragma unroll
                for (int q = 0; q < 2; q++) {
                    int cc = col + q;
                    if (cc >= realN) continue;
                    float v = acc[mt][nt][half * 2 + q];
                    if (bias) v += bias[cc];
                    if (v1) v += a1 * v1[cc];
                    if (v2) v += a2 * v2[cc];
                    if (relu) v = fmaxf(v, 0.f);
                    if (Ch) {
                        split_store(Ch, Cl, (size_t)row * ldc + cc, v);
                    } else {
                        C[(size_t)row * ldc + cc] = v;
                    }
                }
            }
        }
    }
}

// ---------------------------------------------------------------------------
// bf16 split / weight preps
// ---------------------------------------------------------------------------
__global__ void k_split(const float* __restrict__ x, __nv_bfloat16* __restrict__ h,
                        __nv_bfloat16* __restrict__ l, int n)
{
    int i = blockIdx.x * blockDim.x + threadIdx.x;
    if (i >= n) return;
    split_store(h, l, i, x[i]);
}

__global__ void k_wprepT(const float* __restrict__ W, __nv_bfloat16* __restrict__ h,
                         __nv_bfloat16* __restrict__ l, int K, int N, int NP,
                         int ldW, int ldout, int koff)
{
    int i = blockIdx.x * blockDim.x + threadIdx.x;
    if (i >= NP * K) return;
    int n = i / K, k = i - n * K;
    float v = (n < N) ? W[(size_t)k * ldW + n] : 0.f;
    split_store(h, l, (size_t)n * ldout + koff + k, v);
}

__global__ void k_vbias(const float* __restrict__ be2, const float* __restrict__ Wc1,
                        float* __restrict__ vL, float* __restrict__ vR)
{
    int c = blockIdx.x * blockDim.x + threadIdx.x;
    if (c >= 512) return;
    float sL = 0.f, sR = 0.f;
    for (int k = 0; k < 512; k++) {
        float b = be2[k];
        sL += b * Wc1[(size_t)(512 + k) * 512 + c];
        sR += b * Wc1[(size_t)(1024 + k) * 512 + c];
    }
    vL[c] = sL; vR[c] = sR;
}

// ---------------------------------------------------------------------------
// CSR build
// ---------------------------------------------------------------------------
__global__ void k_hist(const int* __restrict__ ei, int* __restrict__ wrD,
                       int* __restrict__ wrS)
{
    int e = blockIdx.x * blockDim.x + threadIdx.x;
    if (e >= ESL) return;
    int dst = (e < EE) ? ei[EE + e] : e - EE;
    atomicAdd(wrD + dst, 1);
    if (e < EE) atomicAdd(wrS + ei[e], 1);
}

__global__ __launch_bounds__(1024)
void k_scan(int* __restrict__ wrD, int* __restrict__ wrS,
            int* __restrict__ rowD, int* __restrict__ rowS)
{
    __shared__ int sm[1024];
    const int t = threadIdx.x;
    const int CH = (NN + 1023) / 1024;
    for (int a = 0; a < 2; a++) {
        int* deg = a ? wrS : wrD;
        int* row = a ? rowS : rowD;
        int start = t * CH;
        int end = min(start + CH, NN);
        int s = 0;
        for (int i = start; i < end; i++) s += deg[i];
        sm[t] = s;
        __syncthreads();
        for (int off = 1; off < 1024; off <<= 1) {
            int v = (t >= off) ? sm[t - off] : 0;
            __syncthreads();
            sm[t] += v;
            __syncthreads();
        }
        int run = (t == 0) ? 0 : sm[t - 1];
        if (t == 0) row[NN] = sm[1023];
        for (int i = start; i < end; i++) {
            int d = deg[i];
            row[i] = run;
            deg[i] = run;
            run += d;
        }
        __syncthreads();
    }
}

__global__ void k_scatter(const int* __restrict__ ei, int* __restrict__ wrD,
                          int* __restrict__ wrS, int* __restrict__ colD,
                          int* __restrict__ colS)
{
    int e = blockIdx.x * blockDim.x + threadIdx.x;
    if (e >= ESL) return;
    int dst = (e < EE) ? ei[EE + e] : e - EE;
    colD[atomicAdd(wrD + dst, 1)] = e;
    if (e < EE) colS[atomicAdd(wrS + ei[e], 1)] = e;
}

// ---------------------------------------------------------------------------
// Node-level attention logits
// ---------------------------------------------------------------------------
__global__ void k_sd1(const float* __restrict__ xl1,
                      const float* __restrict__ as1, const float* __restrict__ ad1,
                      float* __restrict__ s1, float* __restrict__ d1)
{
    int idx = blockIdx.x * blockDim.x + threadIdx.x;
    if (idx >= NN * HEADS) return;
    int n = idx >> 3, h = idx & 7;
    const float4* xr = (const float4*)(xl1 + (size_t)n * 512 + h * 64);
    const float4* av = (const float4*)(as1 + h * 64);
    const float4* bv = (const float4*)(ad1 + h * 64);
    float ss = 0.f, dd = 0.f;
#pragma unroll
    for (int q = 0; q < 16; q++) {
        float4 x = xr[q], a = av[q], b = bv[q];
        ss += x.x * a.x + x.y * a.y + x.z * a.z + x.w * a.w;
        dd += x.x * b.x + x.y * b.y + x.z * b.z + x.w * b.w;
    }
    s1[idx] = ss; d1[idx] = dd;
}

__global__ void k_sd2(const float* __restrict__ xl2,
                      const float* __restrict__ as2, const float* __restrict__ ad2,
                      float* __restrict__ s2, float* __restrict__ d2)
{
    int warp = (blockIdx.x * blockDim.x + threadIdx.x) >> 5;
    int lane = threadIdx.x & 31;
    if (warp >= NN) return;
    const float4* xr = (const float4*)(xl2 + (size_t)warp * 512) + lane * 4;
    const float4* av = (const float4*)as2 + lane * 4;
    const float4* bv = (const float4*)ad2 + lane * 4;
    float ss = 0.f, dd = 0.f;
#pragma unroll
    for (int q = 0; q < 4; q++) {
        float4 x = xr[q], a = av[q], b = bv[q];
        ss += x.x * a.x + x.y * a.y + x.z * a.z + x.w * a.w;
        dd += x.x * b.x + x.y * b.y + x.z * b.z + x.w * b.w;
    }
#pragma unroll
    for (int o = 16; o > 0; o >>= 1) {
        ss += __shfl_xor_sync(0xffffffffu, ss, o);
        dd += __shfl_xor_sync(0xffffffffu, dd, o);
    }
    if (lane == 0) { s2[warp] = ss; d2[warp] = dd; }
}

// ---------------------------------------------------------------------------
// GAT1: fused gather softmax + aggregate + bias + ELU + bf16 split.
// max/den loops parallelized 4-way over edge slices (lane = head | slice<<3).
// ---------------------------------------------------------------------------
__global__ __launch_bounds__(256)
void k_att1(const int* __restrict__ ei, const int* __restrict__ rowD,
            const int* __restrict__ colD, const float* __restrict__ xl1,
            const float* __restrict__ s1, const float* __restrict__ dd1,
            const float* __restrict__ b1,
            __nv_bfloat16* __restrict__ xh, __nv_bfloat16* __restrict__ xl)
{
    int n = (blockIdx.x * blockDim.x + threadIdx.x) >> 5;
    int lane = threadIdx.x & 31;
    if (n >= NN) return;
    int base = rowD[n], cnt = rowD[n + 1] - base;
    int h = lane & 7, sl = lane >> 3;
    float dval = dd1[n * 8 + h];

    float mx = -1e30f;
    for (int i = sl; i < cnt; i += 4) {
        int eid = colD[base + i];
        int src = (eid < EE) ? ei[eid] : n;
        mx = fmaxf(mx, lrelu02(s1[src * 8 + h] + dval));
    }
    mx = fmaxf(mx, __shfl_xor_sync(0xffffffffu, mx, 8));
    mx = fmaxf(mx, __shfl_xor_sync(0xffffffffu, mx, 16));

    float den = 0.f;
    for (int i = sl; i < cnt; i += 4) {
        int eid = colD[base + i];
        int src = (eid < EE) ? ei[eid] : n;
        den += expf(lrelu02(s1[src * 8 + h] + dval) - mx);
    }
    den += __shfl_xor_sync(0xffffffffu, den, 8);
    den += __shfl_xor_sync(0xffffffffu, den, 16);
    float inv = 1.f / (den + 1e-16f);

    float acc[16];
#pragma unroll
    for (int q = 0; q < 16; q++) acc[q] = 0.f;
    for (int i = 0; i < cnt; i++) {
        int eid = colD[base + i];
        int src = (eid < EE) ? ei[eid] : n;
        float w = 0.f;
        if (lane < 8)
            w = expf(lrelu02(s1[src * 8 + lane] + dval) - mx) * inv;
        const float4* xr = (const float4*)(xl1 + (size_t)src * 512);
#pragma unroll
        for (int j = 0; j < 4; j++) {
            float wv = __shfl_sync(0xffffffffu, w, 2 * j + (lane >> 4));
            float4 v = xr[j * 32 + lane];
            acc[j * 4 + 0] += wv * v.x;
            acc[j * 4 + 1] += wv * v.y;
            acc[j * 4 + 2] += wv * v.z;
            acc[j * 4 + 3] += wv * v.w;
        }
    }
#pragma unroll
    for (int j = 0; j < 4; j++) {
        int c0 = (j * 32 + lane) * 4;
#pragma unroll
        for (int q = 0; q < 4; q++) {
            float v = acc[j * 4 + q] + b1[c0 + q];
            v = v > 0.f ? v : expm1f(v);
            split_store(xh, xl, (size_t)n * 512 + c0 + q, v);
        }
    }
}

// ---------------------------------------------------------------------------
// GAT2: fused gather softmax (1 head) + aggregate + b2 + bf16 split into G[0,512)
// ---------------------------------------------------------------------------
__global__ __launch_bounds__(256)
void k_att2(const int* __restrict__ ei, const int* __restrict__ rowD,
            const int* __restrict__ colD, const float* __restrict__ xl2,
            const float* __restrict__ s2, const float* __restrict__ d2,
            const float* __restrict__ b2,
            __nv_bfloat16* __restrict__ Gh, __nv_bfloat16* __restrict__ Gl)
{
    int n = (blockIdx.x * blockDim.x + threadIdx.x) >> 5;
    int lane = threadIdx.x & 31;
    if (n >= NN) return;
    int base = rowD[n], cnt = rowD[n + 1] - base;
    float dn = d2[n];

    float mx = -1e30f;
    for (int i = lane; i < cnt; i += 32) {
        int eid = colD[base + i];
        int src = (eid < EE) ? ei[eid] : n;
        mx = fmaxf(mx, lrelu02(s2[src] + dn));
    }
#pragma unroll
    for (int o = 16; o > 0; o >>= 1)
        mx = fmaxf(mx, __shfl_xor_sync(0xffffffffu, mx, o));

    float den = 0.f;
    for (int i = lane; i < cnt; i += 32) {
        int eid = colD[base + i];
        int src = (eid < EE) ? ei[eid] : n;
        den += expf(lrelu02(s2[src] + dn) - mx);
    }
#pragma unroll
    for (int o = 16; o > 0; o >>= 1)
        den += __shfl_xor_sync(0xffffffffu, den, o);
    float inv = 1.f / (den + 1e-16f);

    float acc[16];
#pragma unroll
    for (int q = 0; q < 16; q++) acc[q] = 0.f;
    for (int i = 0; i < cnt; i++) {
        int eid = colD[base + i];
        int src = (eid < EE) ? ei[eid] : n;
        float w = expf(lrelu02(s2[src] + dn) - mx) * inv;
        const float4* xr = (const float4*)(xl2 + (size_t)src * 512);
#pragma unroll
        for (int j = 0; j < 4; j++) {
            float4 v = xr[j * 32 + lane];
            acc[j * 4 + 0] += w * v.x;
            acc[j * 4 + 1] += w * v.y;
            acc[j * 4 + 2] += w * v.z;
            acc[j * 4 + 3] += w * v.w;
        }
    }
#pragma unroll
    for (int j = 0; j < 4; j++) {
        int c0 = (j * 32 + lane) * 4;
#pragma unroll
        for (int q = 0; q < 4; q++) {
            float v = acc[j * 4 + q] + b2[c0 + q];
            split_store(Gh, Gl, (size_t)n * 1024 + c0 + q, v);
        }
    }
}

// ---------------------------------------------------------------------------
// Synapse gather-mean: warp per node; recompute maxpool+MLP hidden per edge.
// ---------------------------------------------------------------------------
__global__ __launch_bounds__(256)
void k_syng(const int* __restrict__ row, const int* __restrict__ col, int skipSelf,
            const float* __restrict__ synapse,
            const float* __restrict__ We1, const float* __restrict__ be1,
            __nv_bfloat16* __restrict__ Gh, __nv_bfloat16* __restrict__ Gl,
            int colOff, float* __restrict__ bs)
{
    __shared__ float sWe[6 * 256];
    __shared__ float sbe[256];
    for (int i = threadIdx.x; i < 6 * 256; i += blockDim.x) sWe[i] = We1[i];
    for (int i = threadIdx.x; i < 256; i += blockDim.x) sbe[i] = be1[i];
    __syncthreads();

    int n = (blockIdx.x * blockDim.x + threadIdx.x) >> 5;
    int lane = threadIdx.x & 31;
    if (n >= NN) return;
    int base = row[n], cnt = row[n + 1] - base;

    float acc[8];
#pragma unroll
    for (int o = 0; o < 8; o++) acc[o] = 0.f;
    int realc = 0;
    for (int i = 0; i < cnt; i++) {
        int eid = col[base + i];
        if (skipSelf && eid >= EE) continue;
        realc++;
        float m = 0.f;
        if (lane < 6) {
            const float* sp = synapse + (size_t)eid * 24 + lane;
            m = sp[0];
            m = fmaxf(m, sp[6]);
            m = fmaxf(m, sp[12]);
            m = fmaxf(m, sp[18]);
        }
        float xp[6];
#pragma unroll
        for (int j = 0; j < 6; j++) xp[j] = __shfl_sync(0xffffffffu, m, j);
#pragma unroll
        for (int o = 0; o < 8; o++) {
            int c = lane * 8 + o;
            float h = sbe[c];
#pragma unroll
            for (int k = 0; k < 6; k++) h += xp[k] * sWe[k * 256 + c];
            acc[o] += fmaxf(h, 0.f);
        }
    }
    float sc = 1.f / (float)max(realc, 1);
#pragma unroll
    for (int o = 0; o < 8; o++)
        split_store(Gh, Gl, (size_t)n * 1024 + colOff + lane * 8 + o, acc[o] * sc);
    if (lane == 0) bs[n] = realc > 0 ? 1.f : 0.f;
}

// ---------------------------------------------------------------------------
// Host launcher
// ---------------------------------------------------------------------------
extern "C" void kernel_launch(void* const* d_in, const int* in_sizes, int n_in,
                              void* d_out, int out_size)
{
    const int*   ei      = (const int*)d_in[0];
    const float* synapse = (const float*)d_in[2];
    int ib = 4;
    if (n_in > 4 && in_sizes[4] == 1) ib = 5;
    const float* x_param = (const float*)d_in[ib + 0];
    const float* W1  = (const float*)d_in[ib + 1];
    const float* as1 = (const float*)d_in[ib + 2];
    const float* ad1 = (const float*)d_in[ib + 3];
    const float* b1  = (const float*)d_in[ib + 4];
    const float* W2  = (const float*)d_in[ib + 5];
    const float* as2 = (const float*)d_in[ib + 6];
    const float* ad2 = (const float*)d_in[ib + 7];
    const float* b2  = (const float*)d_in[ib + 8];
    const float* We1 = (const float*)d_in[ib + 9];
    const float* be1 = (const float*)d_in[ib + 10];
    const float* We2 = (const float*)d_in[ib + 11];
    const float* be2 = (const float*)d_in[ib + 12];
    const float* Wc1 = (const float*)d_in[ib + 13];
    const float* bc1 = (const float*)d_in[ib + 14];
    const float* Wc2 = (const float*)d_in[ib + 15];
    const float* bc2 = (const float*)d_in[ib + 16];
    float* out = (float*)d_out;

    void* sp = nullptr;  cudaGetSymbolAddress(&sp, g_scratch);
    float* S = (float*)sp;
    void* bp = nullptr;  cudaGetSymbolAddress(&bp, g_bf);
    __nv_bfloat16* B = (__nv_bfloat16*)bp;
    void* ip = nullptr;  cudaGetSymbolAddress(&ip, g_int);
    int* I = (int*)ip;

    cudaFuncSetAttribute(tgemm, cudaFuncAttributeMaxDynamicSharedMemorySize, TG_SMEM);

    float* s1  = S + OFF_S1;
    float* dd1 = S + OFF_DD1;
    float* s2  = S + OFF_S2;
    float* dd2 = S + OFF_DD2;
    float* bsL = S + OFF_BSL;
    float* bsR = S + OFF_BSR;
    float* vL  = S + OFF_VL;
    float* vR  = S + OFF_VR;
    float* xl1 = S + OFF_XL1;
    float* xl2 = S + OFF_XL2;
    float* Wcomb = xl1;                  // [256,1024] fp32 temp; consumed pre-GAT1

    int* rowD = I + I_ROWD;
    int* rowS = I + I_ROWS;
    int* wrD  = I + I_WRD;
    int* wrS  = I + I_WRS;
    int* colD = I + I_COLD;
    int* colS = I + I_COLS;

    cudaMemsetAsync(wrD, 0, 2 * NN * sizeof(int));

    dim3 tpb(256);
    const int MT = (NN + 127) / 128;
    const int NW = (NN * 32 + 255) / 256;

    // ---- CSR build ----
    k_hist<<<(ESL + 255) / 256, tpb>>>(ei, wrD, wrS);
    k_scan<<<1, 1024>>>(wrD, wrS, rowD, rowS);
    k_scatter<<<(ESL + 255) / 256, tpb>>>(ei, wrD, wrS, colD, colS);

    // ---- Weight preps ----
    k_wprepT<<<(512 * 128  + 255) / 256, tpb>>>(W1,  B + B_W1H,  B + B_W1L,  128,  512, 512, 512, 128,  0);
    k_wprepT<<<(512 * 512  + 255) / 256, tpb>>>(W2,  B + B_W2H,  B + B_W2L,  512,  512, 512, 512, 512,  0);
    k_wprepT<<<(256 * 512  + 255) / 256, tpb>>>(Wc2, B + B_WC2H, B + B_WC2L, 512,  NCLS, 256, NCLS, 512, 0);
    k_wprepT<<<(512 * 512  + 255) / 256, tpb>>>(Wc1, B + B_WBH,  B + B_WBL,  512,  512, 512, 512, 1024, 0);
    // Wc1 mid/bot stacked as one [1024, 512] transposed B-matrix
    k_wprepT<<<(512 * 512  + 255) / 256, tpb>>>(Wc1 + (size_t)512 * 512,
                                                B + B_WMH, B + B_WML, 512, 512, 512, 512, 512, 0);
    k_wprepT<<<(512 * 512  + 255) / 256, tpb>>>(Wc1 + (size_t)1024 * 512,
                                                B + B_WMH + 512 * 512, B + B_WML + 512 * 512,
                                                512, 512, 512, 512, 512, 0);
    k_split<<<(256 * 512 + 255) / 256, tpb>>>(We2, B + B_WE2AH, B + B_WE2AL, 256 * 512);
    k_vbias<<<2, tpb>>>(be2, Wc1, vL, vR);

    // Wcomb = We2 @ [Wc1_mid | Wc1_bot]   -> [256, 1024] fp32, one launch
    {
        dim3 g(8, 2);
        tgemm<<<g, tpb, TG_SMEM>>>(B + B_WE2AH, B + B_WE2AL, B + B_WMH, B + B_WML,
                                   Wcomb, nullptr, nullptr, 256, 512, 1024, 1024,
                                   nullptr, nullptr, nullptr, nullptr, nullptr, 0);
    }
    k_wprepT<<<(512 * 256 + 255) / 256, tpb>>>(Wcomb,       B + B_WBH, B + B_WBL, 256, 512, 512, 1024, 1024, 512);
    k_wprepT<<<(512 * 256 + 255) / 256, tpb>>>(Wcomb + 512, B + B_WBH, B + B_WBL, 256, 512, 512, 1024, 1024, 768);

    // ---- GAT1 ----
    k_split<<<((int)SZ_XP + 255) / 256, tpb>>>(x_param, B + B_XPH, B + B_XPL, (int)SZ_XP);
    {
        dim3 g(4, MT);
        tgemm<<<g, tpb, TG_SMEM>>>(B + B_XPH, B + B_XPL, B + B_W1H, B + B_W1L,
                                   xl1, nullptr, nullptr, NN, FIN, D1, D1,
                                   nullptr, nullptr, nullptr, nullptr, nullptr, 0);
    }
    k_sd1<<<(NN * HEADS + 255) / 256, tpb>>>(xl1, as1, ad1, s1, dd1);
    k_att1<<<NW, tpb>>>(ei, rowD, colD, xl1, s1, dd1, b1, B + B_X1H, B + B_X1L);

    // ---- GAT2 ----
    {
        dim3 g(4, MT);
        tgemm<<<g, tpb, TG_SMEM>>>(B + B_X1H, B + B_X1L, B + B_W2H, B + B_W2L,
                                   xl2, nullptr, nullptr, NN, D1, REP, REP,
                                   nullptr, nullptr, nullptr, nullptr, nullptr, 0);
    }
    k_sd2<<<(NN * 32 + 255) / 256, tpb>>>(xl2, as2, ad2, s2, dd2);
    k_att2<<<NW, tpb>>>(ei, rowD, colD, xl2, s2, dd2, b2, B + B_GH, B + B_GL);

    // ---- Synapse gather-means into G cols [512,1024) ----
    k_syng<<<NW, tpb>>>(rowS, colS, 0, synapse, We1, be1, B + B_GH, B + B_GL, 512, bsL);
    k_syng<<<NW, tpb>>>(rowD, colD, 1, synapse, We1, be1, B + B_GH, B + B_GL, 768, bsR);

    // ---- Fused classifier layer 1 -> hidc bf16 split ----
    {
        dim3 g(4, MT);
        tgemm<<<g, tpb, TG_SMEM>>>(B + B_GH, B + B_GL, B + B_WBH, B + B_WBL,
                                   nullptr, B + B_HCH, B + B_HCL, NN, 1024, 512, 512,
                                   bc1, vL, bsL, vR, bsR, 1);
    }
    // ---- Classifier layer 2 ----
    {
        dim3 g(2, MT);
        tgemm<<<g, tpb, TG_SMEM>>>(B + B_HCH, B + B_HCL, B + B_WC2H, B + B_WC2L,
                                   out, nullptr, nullptr, NN, 512, NCLS, NCLS,
                                   bc2, nullptr, nullptr, nullptr, nullptr, 0);
    }
}

// round 10
// speedup vs baseline: 3.1434x; 1.0295x over previous
#include <cuda_runtime.h>
#include <cuda_bf16.h>
#include <cstdint>

// ---------------------------------------------------------------------------
// Problem constants
// ---------------------------------------------------------------------------
constexpr int NN   = 20000;
constexpr int FIN  = 128;
constexpr int HEADS = 8;
constexpr int HIDC  = 64;
constexpr int D1    = HEADS * HIDC;  // 512
constexpr int REP   = 512;
constexpr int NCLS  = 133;
constexpr int EE    = 200000;
constexpr int ESL   = EE + NN;       // 220000

// ---------------------------------------------------------------------------
// fp32 scratch. Zero region = [0, 18N) : s1(8N), dd1(8N), s2(N), dd2(N)
// ---------------------------------------------------------------------------
constexpr size_t OFF_S1   = 0;
constexpr size_t OFF_DD1  = OFF_S1  + (size_t)NN * 8;
constexpr size_t OFF_S2   = OFF_DD1 + (size_t)NN * 8;
constexpr size_t OFF_DD2  = OFF_S2  + (size_t)NN;
constexpr size_t ZFLOATS  = OFF_DD2 + (size_t)NN;         // 18N = 360000
constexpr size_t OFF_BSL  = ZFLOATS;
constexpr size_t OFF_BSR  = OFF_BSL + (size_t)NN;
constexpr size_t OFF_VL   = OFF_BSR + (size_t)NN;
constexpr size_t OFF_VR   = OFF_VL  + 512;
constexpr size_t OFF_XL1  = OFF_VR  + 512;                // 512N (Wcomb temp early)
constexpr size_t OFF_XL2  = OFF_XL1 + (size_t)NN * 512;
constexpr size_t TOTALF   = OFF_XL2 + (size_t)NN * 512;

__device__ float g_scratch[TOTALF];

// ---------------------------------------------------------------------------
// int scratch (CSR). wrD/wrS zeroed by k_prep.
// ---------------------------------------------------------------------------
constexpr size_t I_WRD  = 0;                    // N
constexpr size_t I_WRS  = I_WRD + NN;           // N
constexpr size_t I_ROWD = I_WRS + NN;           // N+1
constexpr size_t I_ROWS = I_ROWD + NN + 1;      // N+1
constexpr size_t I_COLD = I_ROWS + NN + 1;      // ESL
constexpr size_t I_COLS = I_COLD + ESL;         // EE
constexpr size_t TOTALI = I_COLS + EE;

__device__ int g_int[TOTALI];

// ---------------------------------------------------------------------------
// bf16 split scratch
// ---------------------------------------------------------------------------
constexpr size_t SZ_XP   = (size_t)NN * 128;
constexpr size_t SZ_X1   = (size_t)NN * 512;
constexpr size_t SZ_G    = (size_t)NN * 1024;
constexpr size_t SZ_HC   = (size_t)NN * 512;
constexpr size_t SZ_W1   = 512 * 128;
constexpr size_t SZ_W2   = 512 * 512;
constexpr size_t SZ_WB   = 512 * 1024;
constexpr size_t SZ_WC2  = 256 * 512;
constexpr size_t SZ_WM   = 1024 * 512;
constexpr size_t SZ_WE2A = 256 * 512;

constexpr size_t B_XPH   = 0;
constexpr size_t B_XPL   = B_XPH   + SZ_XP;
constexpr size_t B_X1H   = B_XPL   + SZ_XP;
constexpr size_t B_X1L   = B_X1H   + SZ_X1;
constexpr size_t B_GH    = B_X1L   + SZ_X1;
constexpr size_t B_GL    = B_GH    + SZ_G;
constexpr size_t B_HCH   = B_GL    + SZ_G;
constexpr size_t B_HCL   = B_HCH   + SZ_HC;
constexpr size_t B_W1H   = B_HCL   + SZ_HC;
constexpr size_t B_W1L   = B_W1H   + SZ_W1;
constexpr size_t B_W2H   = B_W1L   + SZ_W1;
constexpr size_t B_W2L   = B_W2H   + SZ_W2;
constexpr size_t B_WBH   = B_W2L   + SZ_W2;
constexpr size_t B_WBL   = B_WBH   + SZ_WB;
constexpr size_t B_WC2H  = B_WBL   + SZ_WB;
constexpr size_t B_WC2L  = B_WC2H  + SZ_WC2;
constexpr size_t B_WMH   = B_WC2L  + SZ_WC2;
constexpr size_t B_WML   = B_WMH   + SZ_WM;
constexpr size_t B_WE2AH = B_WML   + SZ_WM;
constexpr size_t B_WE2AL = B_WE2AH + SZ_WE2A;
constexpr size_t TOTALB  = B_WE2AL + SZ_WE2A;

__device__ __align__(256) __nv_bfloat16 g_bf[TOTALB];

// ---------------------------------------------------------------------------
// Helpers
// ---------------------------------------------------------------------------
__device__ __forceinline__ uint32_t smem_to_u32(const void* p) {
    uint32_t a;
    asm("{ .reg .u64 t; cvta.to.shared.u64 t, %1; cvt.u32.u64 %0, t; }"
        : "=r"(a) : "l"(p));
    return a;
}
#define SWZ(off) ((off) ^ (((off) >> 3) & 0x70))
__device__ __forceinline__ float lrelu02(float x) { return x > 0.f ? x : 0.2f * x; }

__device__ __forceinline__ void split_store(__nv_bfloat16* __restrict__ h,
                                            __nv_bfloat16* __restrict__ l,
                                            size_t idx, float v) {
    __nv_bfloat16 hi = __float2bfloat16(v);
    h[idx] = hi;
    l[idx] = __float2bfloat16(v - __bfloat162float(hi));
}

__device__ __forceinline__ void wprep_el(const float* __restrict__ W,
                                         __nv_bfloat16* __restrict__ h,
                                         __nv_bfloat16* __restrict__ l,
                                         int i, int K, int N, int ldW,
                                         int ldout, int koff) {
    int n = i / K, k = i - n * K;
    float v = (n < N) ? W[(size_t)k * ldW + n] : 0.f;
    split_store(h, l, (size_t)n * ldout + koff + k, v);
}

// ---------------------------------------------------------------------------
// mma.sync GEMM: 3-pass bf16 split, 3-stage cp.async.
// Optional epilogue attention dots: atomicAdd per-row partial dots with
// avS/avD into attS/attD (head = col >> hshift).
// ---------------------------------------------------------------------------
constexpr int TG_SMEM = 3 * 32768;

__global__ __launch_bounds__(256)
void tgemm(const __nv_bfloat16* __restrict__ Ah, const __nv_bfloat16* __restrict__ Al,
           const __nv_bfloat16* __restrict__ Bh, const __nv_bfloat16* __restrict__ Bl,
           float* __restrict__ C,
           __nv_bfloat16* __restrict__ Ch, __nv_bfloat16* __restrict__ Cl,
           int M, int K, int realN, int ldc,
           const float* __restrict__ bias,
           const float* __restrict__ v1, const float* __restrict__ s1,
           const float* __restrict__ v2, const float* __restrict__ s2,
           int relu,
           float* __restrict__ attS, float* __restrict__ attD,
           const float* __restrict__ avS, const float* __restrict__ avD,
           int hshift)
{
    extern __shared__ __align__(1024) char smem[];
    const uint32_t sb = smem_to_u32(smem);
    const int tid = threadIdx.x;
    const int w = tid >> 5, l = tid & 31;
    const int m0 = blockIdx.y * 128, n0 = blockIdx.x * 128;
    const int wm = w & 1, wn = w >> 1;
    const int Kc = K >> 6;
    const int nch = 3 * Kc;

    float acc[4][4][4];
#pragma unroll
    for (int a = 0; a < 4; a++)
#pragma unroll
        for (int b = 0; b < 4; b++)
#pragma unroll
            for (int c = 0; c < 4; c++) acc[a][b][c] = 0.f;

    auto load_chunk = [&](int c) {
        int st = c % 3;
        int part = c / Kc, kblk = c - part * Kc;
        const __nv_bfloat16* As = (part < 2) ? Ah : Al;
        const __nv_bfloat16* Bs = (part == 1) ? Bl : Bh;
        uint32_t abase = sb + st * 32768;
        uint32_t bbase = abase + 16384;
#pragma unroll
        for (int j = 0; j < 4; j++) {
            int id = tid + j * 256;
            int r = id >> 3, ck = id & 7;
            {
                int grow = m0 + r;
                const void* g = As + (size_t)grow * K + kblk * 64 + ck * 8;
                uint32_t d = abase + SWZ((uint32_t)(r * 128 + ck * 16));
                int sz = (grow < M) ? 16 : 0;
                asm volatile("cp.async.cg.shared.global [%0], [%1], 16, %2;"
                             :: "r"(d), "l"(g), "r"(sz));
            }
            {
                const void* g = Bs + (size_t)(n0 + r) * K + kblk * 64 + ck * 8;
                uint32_t d = bbase + SWZ((uint32_t)(r * 128 + ck * 16));
                asm volatile("cp.async.cg.shared.global [%0], [%1], 16;"
                             :: "r"(d), "l"(g));
            }
        }
        asm volatile("cp.async.commit_group;" ::: "memory");
    };

    auto compute = [&](int c) {
        int st = c % 3;
        uint32_t abase = sb + st * 32768;
        uint32_t bbase = abase + 16384;
#pragma unroll
        for (int ks = 0; ks < 4; ks++) {
            int kb = ks * 16;
            uint32_t af[4][4];
#pragma unroll
            for (int mt = 0; mt < 4; mt++) {
                int m = wm * 64 + mt * 16 + (l & 7) + ((l >> 3) & 1) * 8;
                int ke = kb + (l >> 4) * 8;
                uint32_t addr = abase + SWZ((uint32_t)(m * 128 + ke * 2));
                asm volatile("ldmatrix.sync.aligned.m8n8.x4.shared.b16 {%0,%1,%2,%3}, [%4];"
                             : "=r"(af[mt][0]), "=r"(af[mt][1]),
                               "=r"(af[mt][2]), "=r"(af[mt][3]) : "r"(addr));
            }
            uint32_t bf[4][2];
#pragma unroll
            for (int g = 0; g < 2; g++) {
                int n = wn * 32 + g * 16 + ((l >> 4) & 1) * 8 + (l & 7);
                int ke = kb + ((l >> 3) & 1) * 8;
                uint32_t addr = bbase + SWZ((uint32_t)(n * 128 + ke * 2));
                uint32_t r0, r1, r2, r3;
                asm volatile("ldmatrix.sync.aligned.m8n8.x4.shared.b16 {%0,%1,%2,%3}, [%4];"
                             : "=r"(r0), "=r"(r1), "=r"(r2), "=r"(r3) : "r"(addr));
                bf[2 * g][0] = r0; bf[2 * g][1] = r1;
                bf[2 * g + 1][0] = r2; bf[2 * g + 1][1] = r3;
            }
#pragma unroll
            for (int mt = 0; mt < 4; mt++)
#pragma unroll
                for (int nt = 0; nt < 4; nt++) {
                    asm volatile(
                        "mma.sync.aligned.m16n8k16.row.col.f32.bf16.bf16.f32 "
                        "{%0,%1,%2,%3}, {%4,%5,%6,%7}, {%8,%9}, {%0,%1,%2,%3};"
                        : "+f"(acc[mt][nt][0]), "+f"(acc[mt][nt][1]),
                          "+f"(acc[mt][nt][2]), "+f"(acc[mt][nt][3])
                        : "r"(af[mt][0]), "r"(af[mt][1]), "r"(af[mt][2]), "r"(af[mt][3]),
                          "r"(bf[nt][0]), "r"(bf[nt][1]));
                }
        }
    };

    load_chunk(0);
    if (nch > 1) load_chunk(1);
    for (int c = 0; c < nch; c++) {
        if (c + 1 < nch)
            asm volatile("cp.async.wait_group 1;" ::: "memory");
        else
            asm volatile("cp.async.wait_group 0;" ::: "memory");
        __syncthreads();
        if (c + 2 < nch) load_chunk(c + 2);
        compute(c);
    }

    const int rbase = m0 + wm * 64, cbase = n0 + wn * 32;

    // Hoisted attention vectors (8 cols per thread)
    float avs[8], avd[8];
    if (attS) {
#pragma unroll
        for (int nt = 0; nt < 4; nt++)
#pragma unroll
            for (int q = 0; q < 2; q++) {
                int cc = cbase + nt * 8 + (l & 3) * 2 + q;
                avs[nt * 2 + q] = avS[cc];
                avd[nt * 2 + q] = avD[cc];
            }
    }

#pragma unroll
    for (int mt = 0; mt < 4; mt++) {
#pragma unroll
        for (int half = 0; half < 2; half++) {
            int row = rbase + mt * 16 + (l >> 2) + half * 8;
            bool valid = row < M;
            float sp = 0.f, dp = 0.f;
            if (valid) {
                float a1 = s1 ? s1[row] : 0.f;
                float a2 = s2 ? s2[row] : 0.f;
#pragma unroll
                for (int nt = 0; nt < 4; nt++) {
                    int col = cbase + nt * 8 + (l & 3) * 2;
#pragma unroll
                    for (int q = 0; q < 2; q++) {
                        int cc = col + q;
                        if (cc >= realN) continue;
                        float v = acc[mt][nt][half * 2 + q];
                        if (bias) v += bias[cc];
                        if (v1) v += a1 * v1[cc];
                        if (v2) v += a2 * v2[cc];
                        if (relu) v = fmaxf(v, 0.f);
                        if (attS) {
                            sp += v * avs[nt * 2 + q];
                            dp += v * avd[nt * 2 + q];
                        }
                        if (Ch) {
                            split_store(Ch, Cl, (size_t)row * ldc + cc, v);
                        } else {
                            C[(size_t)row * ldc + cc] = v;
                        }
                    }
                }
            }
            if (attS) {
                sp += __shfl_xor_sync(0xffffffffu, sp, 1);
                sp += __shfl_xor_sync(0xffffffffu, sp, 2);
                dp += __shfl_xor_sync(0xffffffffu, dp, 1);
                dp += __shfl_xor_sync(0xffffffffu, dp, 2);
                if (valid && (l & 3) == 0) {
                    int H = realN >> hshift;
                    int head = cbase >> hshift;
                    atomicAdd(attS + (size_t)row * H + head, sp);
                    atomicAdd(attD + (size_t)row * H + head, dp);
                }
            }
        }
    }
}

// ---------------------------------------------------------------------------
// Mega-prep: zeroing + all weight transposes/splits + x_param split + vbias
// ---------------------------------------------------------------------------
constexpr int P_Z0   = 0;                       // 360000 zero floats
constexpr int P_Z1   = P_Z0 + 360000;           // 40000 zero ints (wrD/wrS)
constexpr int P_W1   = P_Z1 + 40000;            // 65536
constexpr int P_W2   = P_W1 + 65536;            // 262144
constexpr int P_WC2  = P_W2 + 262144;           // 131072
constexpr int P_WBT  = P_WC2 + 131072;          // 262144 (Wc1 top)
constexpr int P_WMA  = P_WBT + 262144;          // 262144
constexpr int P_WMB  = P_WMA + 262144;          // 262144
constexpr int P_WE2  = P_WMB + 262144;          // 131072
constexpr int P_XP   = P_WE2 + 131072;          // 2560000
constexpr int P_VB   = P_XP + 2560000;          // 512
constexpr int P_TOT  = P_VB + 512;

__global__ void k_prep(const float* __restrict__ W1, const float* __restrict__ W2,
                       const float* __restrict__ Wc1, const float* __restrict__ Wc2,
                       const float* __restrict__ We2, const float* __restrict__ xp,
                       const float* __restrict__ be2,
                       float* __restrict__ S, int* __restrict__ wr,
                       __nv_bfloat16* __restrict__ B,
                       float* __restrict__ vL, float* __restrict__ vR)
{
    int i = blockIdx.x * blockDim.x + threadIdx.x;
    if (i >= P_TOT) return;
    if (i < P_Z1) {
        S[i] = 0.f;
    } else if (i < P_W1) {
        wr[i - P_Z1] = 0;
    } else if (i < P_W2) {
        wprep_el(W1, B + B_W1H, B + B_W1L, i - P_W1, 128, 512, 512, 128, 0);
    } else if (i < P_WC2) {
        wprep_el(W2, B + B_W2H, B + B_W2L, i - P_W2, 512, 512, 512, 512, 0);
    } else if (i < P_WBT) {
        wprep_el(Wc2, B + B_WC2H, B + B_WC2L, i - P_WC2, 512, NCLS, NCLS, 512, 0);
    } else if (i < P_WMA) {
        wprep_el(Wc1, B + B_WBH, B + B_WBL, i - P_WBT, 512, 512, 512, 1024, 0);
    } else if (i < P_WMB) {
        wprep_el(Wc1 + (size_t)512 * 512, B + B_WMH, B + B_WML,
                 i - P_WMA, 512, 512, 512, 512, 0);
    } else if (i < P_WE2) {
        wprep_el(Wc1 + (size_t)1024 * 512, B + B_WMH + 512 * 512, B + B_WML + 512 * 512,
                 i - P_WMB, 512, 512, 512, 512, 0);
    } else if (i < P_XP) {
        int j = i - P_WE2;
        split_store(B + B_WE2AH, B + B_WE2AL, j, We2[j]);
    } else if (i < P_VB) {
        int j = i - P_XP;
        split_store(B + B_XPH, B + B_XPL, j, xp[j]);
    } else {
        int c = i - P_VB;
        float sL = 0.f, sR = 0.f;
        for (int k = 0; k < 512; k++) {
            float b = be2[k];
            sL += b * Wc1[(size_t)(512 + k) * 512 + c];
            sR += b * Wc1[(size_t)(1024 + k) * 512 + c];
        }
        vL[c] = sL; vR[c] = sR;
    }
}

// Wcomb [256 x 1024] fp32 -> WB transposed at koff 512 (cols 0..511) / 768 (512..1023)
__global__ void k_prep2(const float* __restrict__ Wcomb, __nv_bfloat16* __restrict__ B)
{
    int i = blockIdx.x * blockDim.x + threadIdx.x;
    if (i >= 2 * 131072) return;
    if (i < 131072)
        wprep_el(Wcomb, B + B_WBH, B + B_WBL, i, 256, 512, 1024, 1024, 512);
    else
        wprep_el(Wcomb + 512, B + B_WBH, B + B_WBL, i - 131072, 256, 512, 1024, 1024, 768);
}

// ---------------------------------------------------------------------------
// CSR build
// ---------------------------------------------------------------------------
__global__ void k_hist(const int* __restrict__ ei, int* __restrict__ wrD,
                       int* __restrict__ wrS)
{
    int e = blockIdx.x * blockDim.x + threadIdx.x;
    if (e >= ESL) return;
    int dst = (e < EE) ? ei[EE + e] : e - EE;
    atomicAdd(wrD + dst, 1);
    if (e < EE) atomicAdd(wrS + ei[e], 1);
}

__global__ __launch_bounds__(1024)
void k_scan(int* __restrict__ wrD, int* __restrict__ wrS,
            int* __restrict__ rowD, int* __restrict__ rowS)
{
    __shared__ int sm[1024];
    const int t = threadIdx.x;
    const int CH = (NN + 1023) / 1024;
    for (int a = 0; a < 2; a++) {
        int* deg = a ? wrS : wrD;
        int* row = a ? rowS : rowD;
        int start = t * CH;
        int end = min(start + CH, NN);
        int s = 0;
        for (int i = start; i < end; i++) s += deg[i];
        sm[t] = s;
        __syncthreads();
        for (int off = 1; off < 1024; off <<= 1) {
            int v = (t >= off) ? sm[t - off] : 0;
            __syncthreads();
            sm[t] += v;
            __syncthreads();
        }
        int run = (t == 0) ? 0 : sm[t - 1];
        if (t == 0) row[NN] = sm[1023];
        for (int i = start; i < end; i++) {
            int d = deg[i];
            row[i] = run;
            deg[i] = run;
            run += d;
        }
        __syncthreads();
    }
}

__global__ void k_scatter(const int* __restrict__ ei, int* __restrict__ wrD,
                          int* __restrict__ wrS, int* __restrict__ colD,
                          int* __restrict__ colS)
{
    int e = blockIdx.x * blockDim.x + threadIdx.x;
    if (e >= ESL) return;
    int dst = (e < EE) ? ei[EE + e] : e - EE;
    colD[atomicAdd(wrD + dst, 1)] = e;
    if (e < EE) colS[atomicAdd(wrS + ei[e], 1)] = e;
}

// ---------------------------------------------------------------------------
// GAT1: fused gather softmax + aggregate + bias + ELU + bf16 split
// ---------------------------------------------------------------------------
__global__ __launch_bounds__(256)
void k_att1(const int* __restrict__ ei, const int* __restrict__ rowD,
            const int* __restrict__ colD, const float* __restrict__ xl1,
            const float* __restrict__ s1, const float* __restrict__ dd1,
            const float* __restrict__ b1,
            __nv_bfloat16* __restrict__ xh, __nv_bfloat16* __restrict__ xl)
{
    int n = (blockIdx.x * blockDim.x + threadIdx.x) >> 5;
    int lane = threadIdx.x & 31;
    if (n >= NN) return;
    int base = rowD[n], cnt = rowD[n + 1] - base;
    int h = lane & 7, sl = lane >> 3;
    float dval = dd1[n * 8 + h];

    float mx = -1e30f;
    for (int i = sl; i < cnt; i += 4) {
        int eid = colD[base + i];
        int src = (eid < EE) ? ei[eid] : n;
        mx = fmaxf(mx, lrelu02(s1[src * 8 + h] + dval));
    }
    mx = fmaxf(mx, __shfl_xor_sync(0xffffffffu, mx, 8));
    mx = fmaxf(mx, __shfl_xor_sync(0xffffffffu, mx, 16));

    float den = 0.f;
    for (int i = sl; i < cnt; i += 4) {
        int eid = colD[base + i];
        int src = (eid < EE) ? ei[eid] : n;
        den += expf(lrelu02(s1[src * 8 + h] + dval) - mx);
    }
    den += __shfl_xor_sync(0xffffffffu, den, 8);
    den += __shfl_xor_sync(0xffffffffu, den, 16);
    float inv = 1.f / (den + 1e-16f);

    float acc[16];
#pragma unroll
    for (int q = 0; q < 16; q++) acc[q] = 0.f;
    for (int i = 0; i < cnt; i++) {
        int eid = colD[base + i];
        int src = (eid < EE) ? ei[eid] : n;
        float w = 0.f;
        if (lane < 8)
            w = expf(lrelu02(s1[src * 8 + lane] + dval) - mx) * inv;
        const float4* xr = (const float4*)(xl1 + (size_t)src * 512);
#pragma unroll
        for (int j = 0; j < 4; j++) {
            float wv = __shfl_sync(0xffffffffu, w, 2 * j + (lane >> 4));
            float4 v = xr[j * 32 + lane];
            acc[j * 4 + 0] += wv * v.x;
            acc[j * 4 + 1] += wv * v.y;
            acc[j * 4 + 2] += wv * v.z;
            acc[j * 4 + 3] += wv * v.w;
        }
    }
#pragma unroll
    for (int j = 0; j < 4; j++) {
        int c0 = (j * 32 + lane) * 4;
#pragma unroll
        for (int q = 0; q < 4; q++) {
            float v = acc[j * 4 + q] + b1[c0 + q];
            v = v > 0.f ? v : expm1f(v);
            split_store(xh, xl, (size_t)n * 512 + c0 + q, v);
        }
    }
}

// ---------------------------------------------------------------------------
// GAT2: fused gather softmax (1 head) + aggregate + b2 + split into G[0,512)
// ---------------------------------------------------------------------------
__global__ __launch_bounds__(256)
void k_att2(const int* __restrict__ ei, const int* __restrict__ rowD,
            const int* __restrict__ colD, const float* __restrict__ xl2,
            const float* __restrict__ s2, const float* __restrict__ d2,
            const float* __restrict__ b2,
            __nv_bfloat16* __restrict__ Gh, __nv_bfloat16* __restrict__ Gl)
{
    int n = (blockIdx.x * blockDim.x + threadIdx.x) >> 5;
    int lane = threadIdx.x & 31;
    if (n >= NN) return;
    int base = rowD[n], cnt = rowD[n + 1] - base;
    float dn = d2[n];

    float mx = -1e30f;
    for (int i = lane; i < cnt; i += 32) {
        int eid = colD[base + i];
        int src = (eid < EE) ? ei[eid] : n;
        mx = fmaxf(mx, lrelu02(s2[src] + dn));
    }
#pragma unroll
    for (int o = 16; o > 0; o >>= 1)
        mx = fmaxf(mx, __shfl_xor_sync(0xffffffffu, mx, o));

    float den = 0.f;
    for (int i = lane; i < cnt; i += 32) {
        int eid = colD[base + i];
        int src = (eid < EE) ? ei[eid] : n;
        den += expf(lrelu02(s2[src] + dn) - mx);
    }
#pragma unroll
    for (int o = 16; o > 0; o >>= 1)
        den += __shfl_xor_sync(0xffffffffu, den, o);
    float inv = 1.f / (den + 1e-16f);

    float acc[16];
#pragma unroll
    for (int q = 0; q < 16; q++) acc[q] = 0.f;
    for (int i = 0; i < cnt; i++) {
        int eid = colD[base + i];
        int src = (eid < EE) ? ei[eid] : n;
        float w = expf(lrelu02(s2[src] + dn) - mx) * inv;
        const float4* xr = (const float4*)(xl2 + (size_t)src * 512);
#pragma unroll
        for (int j = 0; j < 4; j++) {
            float4 v = xr[j * 32 + lane];
            acc[j * 4 + 0] += w * v.x;
            acc[j * 4 + 1] += w * v.y;
            acc[j * 4 + 2] += w * v.z;
            acc[j * 4 + 3] += w * v.w;
        }
    }
#pragma unroll
    for (int j = 0; j < 4; j++) {
        int c0 = (j * 32 + lane) * 4;
#pragma unroll
        for (int q = 0; q < 4; q++) {
            float v = acc[j * 4 + q] + b2[c0 + q];
            split_store(Gh, Gl, (size_t)n * 1024 + c0 + q, v);
        }
    }
}

// ---------------------------------------------------------------------------
// Synapse gather-mean: grid.y = 0 -> by-src (colS), 1 -> by-dst (colD, skip SL)
// ---------------------------------------------------------------------------
__global__ __launch_bounds__(256)
void k_syng(const int* __restrict__ rowS, const int* __restrict__ colS,
            const int* __restrict__ rowDd, const int* __restrict__ colDd,
            const float* __restrict__ synapse,
            const float* __restrict__ We1, const float* __restrict__ be1,
            __nv_bfloat16* __restrict__ Gh, __nv_bfloat16* __restrict__ Gl,
            float* __restrict__ bsL, float* __restrict__ bsR)
{
    __shared__ float sWe[6 * 256];
    __shared__ float sbe[256];
    for (int i = threadIdx.x; i < 6 * 256; i += blockDim.x) sWe[i] = We1[i];
    for (int i = threadIdx.x; i < 256; i += blockDim.x) sbe[i] = be1[i];
    __syncthreads();

    int part = blockIdx.y;
    const int* row = part ? rowDd : rowS;
    const int* col = part ? colDd : colS;
    int skipSelf = part;
    int colOff = 512 + part * 256;
    float* bs = part ? bsR : bsL;

    int n = (blockIdx.x * blockDim.x + threadIdx.x) >> 5;
    int lane = threadIdx.x & 31;
    if (n >= NN) return;
    int base = row[n], cnt = row[n + 1] - base;

    float acc[8];
#pragma unroll
    for (int o = 0; o < 8; o++) acc[o] = 0.f;
    int realc = 0;
    for (int i = 0; i < cnt; i++) {
        int eid = col[base + i];
        if (skipSelf && eid >= EE) continue;
        realc++;
        float m = 0.f;
        if (lane < 6) {
            const float* sp = synapse + (size_t)eid * 24 + lane;
            m = sp[0];
            m = fmaxf(m, sp[6]);
            m = fmaxf(m, sp[12]);
            m = fmaxf(m, sp[18]);
        }
        float xp[6];
#pragma unroll
        for (int j = 0; j < 6; j++) xp[j] = __shfl_sync(0xffffffffu, m, j);
#pragma unroll
        for (int o = 0; o < 8; o++) {
            int c = lane * 8 + o;
            float h = sbe[c];
#pragma unroll
            for (int k = 0; k < 6; k++) h += xp[k] * sWe[k * 256 + c];
            acc[o] += fmaxf(h, 0.f);
        }
    }
    float sc = 1.f / (float)max(realc, 1);
#pragma unroll
    for (int o = 0; o < 8; o++)
        split_store(Gh, Gl, (size_t)n * 1024 + colOff + lane * 8 + o, acc[o] * sc);
    if (lane == 0) bs[n] = realc > 0 ? 1.f : 0.f;
}

// ---------------------------------------------------------------------------
// Host launcher
// ---------------------------------------------------------------------------
extern "C" void kernel_launch(void* const* d_in, const int* in_sizes, int n_in,
                              void* d_out, int out_size)
{
    const int*   ei      = (const int*)d_in[0];
    const float* synapse = (const float*)d_in[2];
    int ib = 4;
    if (n_in > 4 && in_sizes[4] == 1) ib = 5;
    const float* x_param = (const float*)d_in[ib + 0];
    const float* W1  = (const float*)d_in[ib + 1];
    const float* as1 = (const float*)d_in[ib + 2];
    const float* ad1 = (const float*)d_in[ib + 3];
    const float* b1  = (const float*)d_in[ib + 4];
    const float* W2  = (const float*)d_in[ib + 5];
    const float* as2 = (const float*)d_in[ib + 6];
    const float* ad2 = (const float*)d_in[ib + 7];
    const float* b2  = (const float*)d_in[ib + 8];
    const float* We1 = (const float*)d_in[ib + 9];
    const float* be1 = (const float*)d_in[ib + 10];
    const float* We2 = (const float*)d_in[ib + 11];
    const float* be2 = (const float*)d_in[ib + 12];
    const float* Wc1 = (const float*)d_in[ib + 13];
    const float* bc1 = (const float*)d_in[ib + 14];
    const float* Wc2 = (const float*)d_in[ib + 15];
    const float* bc2 = (const float*)d_in[ib + 16];
    float* out = (float*)d_out;

    void* sp = nullptr;  cudaGetSymbolAddress(&sp, g_scratch);
    float* S = (float*)sp;
    void* bp = nullptr;  cudaGetSymbolAddress(&bp, g_bf);
    __nv_bfloat16* B = (__nv_bfloat16*)bp;
    void* ip = nullptr;  cudaGetSymbolAddress(&ip, g_int);
    int* I = (int*)ip;

    cudaFuncSetAttribute(tgemm, cudaFuncAttributeMaxDynamicSharedMemorySize, TG_SMEM);

    float* s1  = S + OFF_S1;
    float* dd1 = S + OFF_DD1;
    float* s2  = S + OFF_S2;
    float* dd2 = S + OFF_DD2;
    float* bsL = S + OFF_BSL;
    float* bsR = S + OFF_BSR;
    float* vL  = S + OFF_VL;
    float* vR  = S + OFF_VR;
    float* xl1 = S + OFF_XL1;
    float* xl2 = S + OFF_XL2;
    float* Wcomb = xl1;   // [256,1024] fp32 temp; consumed before GAT1 writes xl1

    int* wrD  = I + I_WRD;
    int* wrS  = I + I_WRS;
    int* rowD = I + I_ROWD;
    int* rowS = I + I_ROWS;
    int* colD = I + I_COLD;
    int* colS = I + I_COLS;

    dim3 tpb(256);
    const int MT = (NN + 127) / 128;
    const int NW = (NN * 32 + 255) / 256;

    // 1. Mega-prep (zeroing + all weight transforms + x_param split + vbias)
    k_prep<<<(P_TOT + 255) / 256, tpb>>>(W1, W2, Wc1, Wc2, We2, x_param, be2,
                                         S, wrD, B, vL, vR);

    // 2-4. CSR build
    k_hist<<<(ESL + 255) / 256, tpb>>>(ei, wrD, wrS);
    k_scan<<<1, 1024>>>(wrD, wrS, rowD, rowS);
    k_scatter<<<(ESL + 255) / 256, tpb>>>(ei, wrD, wrS, colD, colS);

    // 5. Wcomb = We2 @ [Wc1_mid | Wc1_bot] -> [256, 1024] fp32
    {
        dim3 g(8, 2);
        tgemm<<<g, tpb, TG_SMEM>>>(B + B_WE2AH, B + B_WE2AL, B + B_WMH, B + B_WML,
                                   Wcomb, nullptr, nullptr, 256, 512, 1024, 1024,
                                   nullptr, nullptr, nullptr, nullptr, nullptr, 0,
                                   nullptr, nullptr, nullptr, nullptr, 0);
    }
    // 6. Wcomb -> WB transposed splits
    k_prep2<<<(2 * 131072 + 255) / 256, tpb>>>(Wcomb, B);

    // 7. GAT1 GEMM (+ fused s1/dd1 dots)
    {
        dim3 g(4, MT);
        tgemm<<<g, tpb, TG_SMEM>>>(B + B_XPH, B + B_XPL, B + B_W1H, B + B_W1L,
                                   xl1, nullptr, nullptr, NN, FIN, D1, D1,
                                   nullptr, nullptr, nullptr, nullptr, nullptr, 0,
                                   s1, dd1, as1, ad1, 6);
    }
    // 8. GAT1 attention/aggregate
    k_att1<<<NW, tpb>>>(ei, rowD, colD, xl1, s1, dd1, b1, B + B_X1H, B + B_X1L);

    // 9. GAT2 GEMM (+ fused s2/dd2 dots)
    {
        dim3 g(4, MT);
        tgemm<<<g, tpb, TG_SMEM>>>(B + B_X1H, B + B_X1L, B + B_W2H, B + B_W2L,
                                   xl2, nullptr, nullptr, NN, D1, REP, REP,
                                   nullptr, nullptr, nullptr, nullptr, nullptr, 0,
                                   s2, dd2, as2, ad2, 9);
    }
    // 10. GAT2 attention/aggregate
    k_att2<<<NW, tpb>>>(ei, rowD, colD, xl2, s2, dd2, b2, B + B_GH, B + B_GL);

    // 11. Synapse gather-means (both directions, one launch)
    {
        dim3 g(NW, 2);
        k_syng<<<g, tpb>>>(rowS, colS, rowD, colD, synapse, We1, be1,
                           B + B_GH, B + B_GL, bsL, bsR);
    }

    // 12. Fused classifier layer 1 -> hidc bf16 split
    {
        dim3 g(4, MT);
        tgemm<<<g, tpb, TG_SMEM>>>(B + B_GH, B + B_GL, B + B_WBH, B + B_WBL,
                                   nullptr, B + B_HCH, B + B_HCL, NN, 1024, 512, 512,
                                   bc1, vL, bsL, vR, bsR, 1,
                                   nullptr, nullptr, nullptr, nullptr, 0);
    }
    // 13. Classifier layer 2
    {
        dim3 g(2, MT);
        tgemm<<<g, tpb, TG_SMEM>>>(B + B_HCH, B + B_HCL, B + B_WC2H, B + B_WC2L,
                                   out, nullptr, nullptr, NN, 512, NCLS, NCLS,
                                   bc2, nullptr, nullptr, nullptr, nullptr, 0,
                                   nullptr, nullptr, nullptr, nullptr, 0);
    }
}

// round 11
// speedup vs baseline: 3.5087x; 1.1162x over previous
#include <cuda_runtime.h>
#include <cuda_bf16.h>
#include <cstdint>

// ---------------------------------------------------------------------------
// Problem constants
// ---------------------------------------------------------------------------
constexpr int NN   = 20000;
constexpr int FIN  = 128;
constexpr int HEADS = 8;
constexpr int HIDC  = 64;
constexpr int D1    = HEADS * HIDC;  // 512
constexpr int REP   = 512;
constexpr int NCLS  = 133;
constexpr int EE    = 200000;
constexpr int ESL   = EE + NN;       // 220000

// ---------------------------------------------------------------------------
// fp32 scratch. Zero region = [0, 18N) : s1(8N), dd1(8N), s2(N), dd2(N)
// ---------------------------------------------------------------------------
constexpr size_t OFF_S1    = 0;
constexpr size_t OFF_DD1   = OFF_S1  + (size_t)NN * 8;
constexpr size_t OFF_S2    = OFF_DD1 + (size_t)NN * 8;
constexpr size_t OFF_DD2   = OFF_S2  + (size_t)NN;
constexpr size_t ZFLOATS   = OFF_DD2 + (size_t)NN;        // 360000
constexpr size_t OFF_BSL   = ZFLOATS;
constexpr size_t OFF_BSR   = OFF_BSL + (size_t)NN;
constexpr size_t OFF_VL    = OFF_BSR + (size_t)NN;
constexpr size_t OFF_VR    = OFF_VL  + 512;
constexpr size_t OFF_WCOMB = OFF_VR  + 512;               // 256*1024 (dedicated!)
constexpr size_t OFF_XL1   = OFF_WCOMB + 262144;
constexpr size_t OFF_XL2   = OFF_XL1 + (size_t)NN * 512;
constexpr size_t TOTALF    = OFF_XL2 + (size_t)NN * 512;

__device__ float g_scratch[TOTALF];

// ---------------------------------------------------------------------------
// int scratch (CSR). wrD/wrS zeroed by memsetAsync on stream B.
// ---------------------------------------------------------------------------
constexpr size_t I_WRD  = 0;
constexpr size_t I_WRS  = I_WRD + NN;
constexpr size_t I_ROWD = I_WRS + NN;
constexpr size_t I_ROWS = I_ROWD + NN + 1;
constexpr size_t I_COLD = I_ROWS + NN + 1;
constexpr size_t I_COLS = I_COLD + ESL;
constexpr size_t TOTALI = I_COLS + EE;

__device__ int g_int[TOTALI];

// ---------------------------------------------------------------------------
// bf16 split scratch
// ---------------------------------------------------------------------------
constexpr size_t SZ_XP   = (size_t)NN * 128;
constexpr size_t SZ_X1   = (size_t)NN * 512;
constexpr size_t SZ_G    = (size_t)NN * 1024;
constexpr size_t SZ_HC   = (size_t)NN * 512;
constexpr size_t SZ_W1   = 512 * 128;
constexpr size_t SZ_W2   = 512 * 512;
constexpr size_t SZ_WB   = 512 * 1024;
constexpr size_t SZ_WC2  = 256 * 512;
constexpr size_t SZ_WM   = 1024 * 512;
constexpr size_t SZ_WE2A = 256 * 512;

constexpr size_t B_XPH   = 0;
constexpr size_t B_XPL   = B_XPH   + SZ_XP;
constexpr size_t B_X1H   = B_XPL   + SZ_XP;
constexpr size_t B_X1L   = B_X1H   + SZ_X1;
constexpr size_t B_GH    = B_X1L   + SZ_X1;
constexpr size_t B_GL    = B_GH    + SZ_G;
constexpr size_t B_HCH   = B_GL    + SZ_G;
constexpr size_t B_HCL   = B_HCH   + SZ_HC;
constexpr size_t B_W1H   = B_HCL   + SZ_HC;
constexpr size_t B_W1L   = B_W1H   + SZ_W1;
constexpr size_t B_W2H   = B_W1L   + SZ_W1;
constexpr size_t B_W2L   = B_W2H   + SZ_W2;
constexpr size_t B_WBH   = B_W2L   + SZ_W2;
constexpr size_t B_WBL   = B_WBH   + SZ_WB;
constexpr size_t B_WC2H  = B_WBL   + SZ_WB;
constexpr size_t B_WC2L  = B_WC2H  + SZ_WC2;
constexpr size_t B_WMH   = B_WC2L  + SZ_WC2;
constexpr size_t B_WML   = B_WMH   + SZ_WM;
constexpr size_t B_WE2AH = B_WML   + SZ_WM;
constexpr size_t B_WE2AL = B_WE2AH + SZ_WE2A;
constexpr size_t TOTALB  = B_WE2AL + SZ_WE2A;

__device__ __align__(256) __nv_bfloat16 g_bf[TOTALB];

// ---------------------------------------------------------------------------
// Helpers
// ---------------------------------------------------------------------------
__device__ __forceinline__ uint32_t smem_to_u32(const void* p) {
    uint32_t a;
    asm("{ .reg .u64 t; cvta.to.shared.u64 t, %1; cvt.u32.u64 %0, t; }"
        : "=r"(a) : "l"(p));
    return a;
}
#define SWZ(off) ((off) ^ (((off) >> 3) & 0x70))
__device__ __forceinline__ float lrelu02(float x) { return x > 0.f ? x : 0.2f * x; }

__device__ __forceinline__ void split_store(__nv_bfloat16* __restrict__ h,
                                            __nv_bfloat16* __restrict__ l,
                                            size_t idx, float v) {
    __nv_bfloat16 hi = __float2bfloat16(v);
    h[idx] = hi;
    l[idx] = __float2bfloat16(v - __bfloat162float(hi));
}

__device__ __forceinline__ void wprep_el(const float* __restrict__ W,
                                         __nv_bfloat16* __restrict__ h,
                                         __nv_bfloat16* __restrict__ l,
                                         int i, int K, int N, int ldW,
                                         int ldout, int koff) {
    int n = i / K, k = i - n * K;
    float v = (n < N) ? W[(size_t)k * ldW + n] : 0.f;
    split_store(h, l, (size_t)n * ldout + koff + k, v);
}

// ---------------------------------------------------------------------------
// mma.sync GEMM: 3-pass bf16 split, 3-stage cp.async, fused attention dots
// ---------------------------------------------------------------------------
constexpr int TG_SMEM = 3 * 32768;

__global__ __launch_bounds__(256)
void tgemm(const __nv_bfloat16* __restrict__ Ah, const __nv_bfloat16* __restrict__ Al,
           const __nv_bfloat16* __restrict__ Bh, const __nv_bfloat16* __restrict__ Bl,
           float* __restrict__ C,
           __nv_bfloat16* __restrict__ Ch, __nv_bfloat16* __restrict__ Cl,
           int M, int K, int realN, int ldc,
           const float* __restrict__ bias,
           const float* __restrict__ v1, const float* __restrict__ s1,
           const float* __restrict__ v2, const float* __restrict__ s2,
           int relu,
           float* __restrict__ attS, float* __restrict__ attD,
           const float* __restrict__ avS, const float* __restrict__ avD,
           int hshift)
{
    extern __shared__ __align__(1024) char smem[];
    const uint32_t sb = smem_to_u32(smem);
    const int tid = threadIdx.x;
    const int w = tid >> 5, l = tid & 31;
    const int m0 = blockIdx.y * 128, n0 = blockIdx.x * 128;
    const int wm = w & 1, wn = w >> 1;
    const int Kc = K >> 6;
    const int nch = 3 * Kc;

    float acc[4][4][4];
#pragma unroll
    for (int a = 0; a < 4; a++)
#pragma unroll
        for (int b = 0; b < 4; b++)
#pragma unroll
            for (int c = 0; c < 4; c++) acc[a][b][c] = 0.f;

    auto load_chunk = [&](int c) {
        int st = c % 3;
        int part = c / Kc, kblk = c - part * Kc;
        const __nv_bfloat16* As = (part < 2) ? Ah : Al;
        const __nv_bfloat16* Bs = (part == 1) ? Bl : Bh;
        uint32_t abase = sb + st * 32768;
        uint32_t bbase = abase + 16384;
#pragma unroll
        for (int j = 0; j < 4; j++) {
            int id = tid + j * 256;
            int r = id >> 3, ck = id & 7;
            {
                int grow = m0 + r;
                const void* g = As + (size_t)grow * K + kblk * 64 + ck * 8;
                uint32_t d = abase + SWZ((uint32_t)(r * 128 + ck * 16));
                int sz = (grow < M) ? 16 : 0;
                asm volatile("cp.async.cg.shared.global [%0], [%1], 16, %2;"
                             :: "r"(d), "l"(g), "r"(sz));
            }
            {
                const void* g = Bs + (size_t)(n0 + r) * K + kblk * 64 + ck * 8;
                uint32_t d = bbase + SWZ((uint32_t)(r * 128 + ck * 16));
                asm volatile("cp.async.cg.shared.global [%0], [%1], 16;"
                             :: "r"(d), "l"(g));
            }
        }
        asm volatile("cp.async.commit_group;" ::: "memory");
    };

    auto compute = [&](int c) {
        int st = c % 3;
        uint32_t abase = sb + st * 32768;
        uint32_t bbase = abase + 16384;
#pragma unroll
        for (int ks = 0; ks < 4; ks++) {
            int kb = ks * 16;
            uint32_t af[4][4];
#pragma unroll
            for (int mt = 0; mt < 4; mt++) {
                int m = wm * 64 + mt * 16 + (l & 7) + ((l >> 3) & 1) * 8;
                int ke = kb + (l >> 4) * 8;
                uint32_t addr = abase + SWZ((uint32_t)(m * 128 + ke * 2));
                asm volatile("ldmatrix.sync.aligned.m8n8.x4.shared.b16 {%0,%1,%2,%3}, [%4];"
                             : "=r"(af[mt][0]), "=r"(af[mt][1]),
                               "=r"(af[mt][2]), "=r"(af[mt][3]) : "r"(addr));
            }
            uint32_t bf[4][2];
#pragma unroll
            for (int g = 0; g < 2; g++) {
                int n = wn * 32 + g * 16 + ((l >> 4) & 1) * 8 + (l & 7);
                int ke = kb + ((l >> 3) & 1) * 8;
                uint32_t addr = bbase + SWZ((uint32_t)(n * 128 + ke * 2));
                uint32_t r0, r1, r2, r3;
                asm volatile("ldmatrix.sync.aligned.m8n8.x4.shared.b16 {%0,%1,%2,%3}, [%4];"
                             : "=r"(r0), "=r"(r1), "=r"(r2), "=r"(r3) : "r"(addr));
                bf[2 * g][0] = r0; bf[2 * g][1] = r1;
                bf[2 * g + 1][0] = r2; bf[2 * g + 1][1] = r3;
            }
#pragma unroll
            for (int mt = 0; mt < 4; mt++)
#pragma unroll
                for (int nt = 0; nt < 4; nt++) {
                    asm volatile(
                        "mma.sync.aligned.m16n8k16.row.col.f32.bf16.bf16.f32 "
                        "{%0,%1,%2,%3}, {%4,%5,%6,%7}, {%8,%9}, {%0,%1,%2,%3};"
                        : "+f"(acc[mt][nt][0]), "+f"(acc[mt][nt][1]),
                          "+f"(acc[mt][nt][2]), "+f"(acc[mt][nt][3])
                        : "r"(af[mt][0]), "r"(af[mt][1]), "r"(af[mt][2]), "r"(af[mt][3]),
                          "r"(bf[nt][0]), "r"(bf[nt][1]));
                }
        }
    };

    load_chunk(0);
    if (nch > 1) load_chunk(1);
    for (int c = 0; c < nch; c++) {
        if (c + 1 < nch)
            asm volatile("cp.async.wait_group 1;" ::: "memory");
        else
            asm volatile("cp.async.wait_group 0;" ::: "memory");
        __syncthreads();
        if (c + 2 < nch) load_chunk(c + 2);
        compute(c);
    }

    const int rbase = m0 + wm * 64, cbase = n0 + wn * 32;

    float avs[8], avd[8];
    if (attS) {
#pragma unroll
        for (int nt = 0; nt < 4; nt++)
#pragma unroll
            for (int q = 0; q < 2; q++) {
                int cc = cbase + nt * 8 + (l & 3) * 2 + q;
                avs[nt * 2 + q] = avS[cc];
                avd[nt * 2 + q] = avD[cc];
            }
    }

#pragma unroll
    for (int mt = 0; mt < 4; mt++) {
#pragma unroll
        for (int half = 0; half < 2; half++) {
            int row = rbase + mt * 16 + (l >> 2) + half * 8;
            bool valid = row < M;
            float sp = 0.f, dp = 0.f;
            if (valid) {
                float a1 = s1 ? s1[row] : 0.f;
                float a2 = s2 ? s2[row] : 0.f;
#pragma unroll
                for (int nt = 0; nt < 4; nt++) {
                    int col = cbase + nt * 8 + (l & 3) * 2;
#pragma unroll
                    for (int q = 0; q < 2; q++) {
                        int cc = col + q;
                        if (cc >= realN) continue;
                        float v = acc[mt][nt][half * 2 + q];
                        if (bias) v += bias[cc];
                        if (v1) v += a1 * v1[cc];
                        if (v2) v += a2 * v2[cc];
                        if (relu) v = fmaxf(v, 0.f);
                        if (attS) {
                            sp += v * avs[nt * 2 + q];
                            dp += v * avd[nt * 2 + q];
                        }
                        if (Ch) {
                            split_store(Ch, Cl, (size_t)row * ldc + cc, v);
                        } else {
                            C[(size_t)row * ldc + cc] = v;
                        }
                    }
                }
            }
            if (attS) {
                sp += __shfl_xor_sync(0xffffffffu, sp, 1);
                sp += __shfl_xor_sync(0xffffffffu, sp, 2);
                dp += __shfl_xor_sync(0xffffffffu, dp, 1);
                dp += __shfl_xor_sync(0xffffffffu, dp, 2);
                if (valid && (l & 3) == 0) {
                    int H = realN >> hshift;
                    int head = cbase >> hshift;
                    atomicAdd(attS + (size_t)row * H + head, sp);
                    atomicAdd(attD + (size_t)row * H + head, dp);
                }
            }
        }
    }
}

// ---------------------------------------------------------------------------
// Mega-prep: zeroing + weight transposes/splits + x_param split + vbias
// ---------------------------------------------------------------------------
constexpr int P_Z   = 360000;
constexpr int P_W1  = P_Z   + 65536;
constexpr int P_W2  = P_W1  + 262144;
constexpr int P_WC2 = P_W2  + 131072;
constexpr int P_WBT = P_WC2 + 262144;
constexpr int P_WMA = P_WBT + 262144;
constexpr int P_WMB = P_WMA + 262144;
constexpr int P_WE2 = P_WMB + 131072;
constexpr int P_XP  = P_WE2 + 2560000;
constexpr int P_TOT = P_XP  + 512;

__global__ void k_prep(const float* __restrict__ W1, const float* __restrict__ W2,
                       const float* __restrict__ Wc1, const float* __restrict__ Wc2,
                       const float* __restrict__ We2, const float* __restrict__ xp,
                       const float* __restrict__ be2,
                       float* __restrict__ S,
                       __nv_bfloat16* __restrict__ B,
                       float* __restrict__ vL, float* __restrict__ vR)
{
    int i = blockIdx.x * blockDim.x + threadIdx.x;
    if (i >= P_TOT) return;
    if (i < P_Z) {
        S[i] = 0.f;
    } else if (i < P_W1) {
        wprep_el(W1, B + B_W1H, B + B_W1L, i - P_Z, 128, 512, 512, 128, 0);
    } else if (i < P_W2) {
        wprep_el(W2, B + B_W2H, B + B_W2L, i - P_W1, 512, 512, 512, 512, 0);
    } else if (i < P_WC2) {
        wprep_el(Wc2, B + B_WC2H, B + B_WC2L, i - P_W2, 512, NCLS, NCLS, 512, 0);
    } else if (i < P_WBT) {
        wprep_el(Wc1, B + B_WBH, B + B_WBL, i - P_WC2, 512, 512, 512, 1024, 0);
    } else if (i < P_WMA) {
        wprep_el(Wc1 + (size_t)512 * 512, B + B_WMH, B + B_WML,
                 i - P_WBT, 512, 512, 512, 512, 0);
    } else if (i < P_WMB) {
        wprep_el(Wc1 + (size_t)1024 * 512, B + B_WMH + 512 * 512, B + B_WML + 512 * 512,
                 i - P_WMA, 512, 512, 512, 512, 0);
    } else if (i < P_WE2) {
        int j = i - P_WMB;
        split_store(B + B_WE2AH, B + B_WE2AL, j, We2[j]);
    } else if (i < P_XP) {
        int j = i - P_WE2;
        split_store(B + B_XPH, B + B_XPL, j, xp[j]);
    } else {
        int c = i - P_XP;
        float sL = 0.f, sR = 0.f;
        for (int k = 0; k < 512; k++) {
            float b = be2[k];
            sL += b * Wc1[(size_t)(512 + k) * 512 + c];
            sR += b * Wc1[(size_t)(1024 + k) * 512 + c];
        }
        vL[c] = sL; vR[c] = sR;
    }
}

__global__ void k_prep2(const float* __restrict__ Wcomb, __nv_bfloat16* __restrict__ B)
{
    int i = blockIdx.x * blockDim.x + threadIdx.x;
    if (i >= 2 * 131072) return;
    if (i < 131072)
        wprep_el(Wcomb, B + B_WBH, B + B_WBL, i, 256, 512, 1024, 1024, 512);
    else
        wprep_el(Wcomb + 512, B + B_WBH, B + B_WBL, i - 131072, 256, 512, 1024, 1024, 768);
}

// ---------------------------------------------------------------------------
// CSR build
// ---------------------------------------------------------------------------
__global__ void k_hist(const int* __restrict__ ei, int* __restrict__ wrD,
                       int* __restrict__ wrS)
{
    int e = blockIdx.x * blockDim.x + threadIdx.x;
    if (e >= ESL) return;
    int dst = (e < EE) ? ei[EE + e] : e - EE;
    atomicAdd(wrD + dst, 1);
    if (e < EE) atomicAdd(wrS + ei[e], 1);
}

__global__ __launch_bounds__(1024)
void k_scan(int* __restrict__ wrD, int* __restrict__ wrS,
            int* __restrict__ rowD, int* __restrict__ rowS)
{
    __shared__ int sm[1024];
    const int t = threadIdx.x;
    const int CH = (NN + 1023) / 1024;
    for (int a = 0; a < 2; a++) {
        int* deg = a ? wrS : wrD;
        int* row = a ? rowS : rowD;
        int start = t * CH;
        int end = min(start + CH, NN);
        int s = 0;
        for (int i = start; i < end; i++) s += deg[i];
        sm[t] = s;
        __syncthreads();
        for (int off = 1; off < 1024; off <<= 1) {
            int v = (t >= off) ? sm[t - off] : 0;
            __syncthreads();
            sm[t] += v;
            __syncthreads();
        }
        int run = (t == 0) ? 0 : sm[t - 1];
        if (t == 0) row[NN] = sm[1023];
        for (int i = start; i < end; i++) {
            int d = deg[i];
            row[i] = run;
            deg[i] = run;
            run += d;
        }
        __syncthreads();
    }
}

__global__ void k_scatter(const int* __restrict__ ei, int* __restrict__ wrD,
                          int* __restrict__ wrS, int* __restrict__ colD,
                          int* __restrict__ colS)
{
    int e = blockIdx.x * blockDim.x + threadIdx.x;
    if (e >= ESL) return;
    int dst = (e < EE) ? ei[EE + e] : e - EE;
    colD[atomicAdd(wrD + dst, 1)] = e;
    if (e < EE) colS[atomicAdd(wrS + ei[e], 1)] = e;
}

// ---------------------------------------------------------------------------
// GAT1 attention/aggregate
// ---------------------------------------------------------------------------
__global__ __launch_bounds__(256)
void k_att1(const int* __restrict__ ei, const int* __restrict__ rowD,
            const int* __restrict__ colD, const float* __restrict__ xl1,
            const float* __restrict__ s1, const float* __restrict__ dd1,
            const float* __restrict__ b1,
            __nv_bfloat16* __restrict__ xh, __nv_bfloat16* __restrict__ xl)
{
    int n = (blockIdx.x * blockDim.x + threadIdx.x) >> 5;
    int lane = threadIdx.x & 31;
    if (n >= NN) return;
    int base = rowD[n], cnt = rowD[n + 1] - base;
    int h = lane & 7, sl = lane >> 3;
    float dval = dd1[n * 8 + h];

    float mx = -1e30f;
    for (int i = sl; i < cnt; i += 4) {
        int eid = colD[base + i];
        int src = (eid < EE) ? ei[eid] : n;
        mx = fmaxf(mx, lrelu02(s1[src * 8 + h] + dval));
    }
    mx = fmaxf(mx, __shfl_xor_sync(0xffffffffu, mx, 8));
    mx = fmaxf(mx, __shfl_xor_sync(0xffffffffu, mx, 16));

    float den = 0.f;
    for (int i = sl; i < cnt; i += 4) {
        int eid = colD[base + i];
        int src = (eid < EE) ? ei[eid] : n;
        den += expf(lrelu02(s1[src * 8 + h] + dval) - mx);
    }
    den += __shfl_xor_sync(0xffffffffu, den, 8);
    den += __shfl_xor_sync(0xffffffffu, den, 16);
    float inv = 1.f / (den + 1e-16f);

    float acc[16];
#pragma unroll
    for (int q = 0; q < 16; q++) acc[q] = 0.f;
    for (int i = 0; i < cnt; i++) {
        int eid = colD[base + i];
        int src = (eid < EE) ? ei[eid] : n;
        float w = 0.f;
        if (lane < 8)
            w = expf(lrelu02(s1[src * 8 + lane] + dval) - mx) * inv;
        const float4* xr = (const float4*)(xl1 + (size_t)src * 512);
#pragma unroll
        for (int j = 0; j < 4; j++) {
            float wv = __shfl_sync(0xffffffffu, w, 2 * j + (lane >> 4));
            float4 v = xr[j * 32 + lane];
            acc[j * 4 + 0] += wv * v.x;
            acc[j * 4 + 1] += wv * v.y;
            acc[j * 4 + 2] += wv * v.z;
            acc[j * 4 + 3] += wv * v.w;
        }
    }
#pragma unroll
    for (int j = 0; j < 4; j++) {
        int c0 = (j * 32 + lane) * 4;
#pragma unroll
        for (int q = 0; q < 4; q++) {
            float v = acc[j * 4 + q] + b1[c0 + q];
            v = v > 0.f ? v : expm1f(v);
            split_store(xh, xl, (size_t)n * 512 + c0 + q, v);
        }
    }
}

// ---------------------------------------------------------------------------
// GAT2 attention/aggregate into G[0,512)
// ---------------------------------------------------------------------------
__global__ __launch_bounds__(256)
void k_att2(const int* __restrict__ ei, const int* __restrict__ rowD,
            const int* __restrict__ colD, const float* __restrict__ xl2,
            const float* __restrict__ s2, const float* __restrict__ d2,
            const float* __restrict__ b2,
            __nv_bfloat16* __restrict__ Gh, __nv_bfloat16* __restrict__ Gl)
{
    int n = (blockIdx.x * blockDim.x + threadIdx.x) >> 5;
    int lane = threadIdx.x & 31;
    if (n >= NN) return;
    int base = rowD[n], cnt = rowD[n + 1] - base;
    float dn = d2[n];

    float mx = -1e30f;
    for (int i = lane; i < cnt; i += 32) {
        int eid = colD[base + i];
        int src = (eid < EE) ? ei[eid] : n;
        mx = fmaxf(mx, lrelu02(s2[src] + dn));
    }
#pragma unroll
    for (int o = 16; o > 0; o >>= 1)
        mx = fmaxf(mx, __shfl_xor_sync(0xffffffffu, mx, o));

    float den = 0.f;
    for (int i = lane; i < cnt; i += 32) {
        int eid = colD[base + i];
        int src = (eid < EE) ? ei[eid] : n;
        den += expf(lrelu02(s2[src] + dn) - mx);
    }
#pragma unroll
    for (int o = 16; o > 0; o >>= 1)
        den += __shfl_xor_sync(0xffffffffu, den, o);
    float inv = 1.f / (den + 1e-16f);

    float acc[16];
#pragma unroll
    for (int q = 0; q < 16; q++) acc[q] = 0.f;
    for (int i = 0; i < cnt; i++) {
        int eid = colD[base + i];
        int src = (eid < EE) ? ei[eid] : n;
        float w = expf(lrelu02(s2[src] + dn) - mx) * inv;
        const float4* xr = (const float4*)(xl2 + (size_t)src * 512);
#pragma unroll
        for (int j = 0; j < 4; j++) {
            float4 v = xr[j * 32 + lane];
            acc[j * 4 + 0] += w * v.x;
            acc[j * 4 + 1] += w * v.y;
            acc[j * 4 + 2] += w * v.z;
            acc[j * 4 + 3] += w * v.w;
        }
    }
#pragma unroll
    for (int j = 0; j < 4; j++) {
        int c0 = (j * 32 + lane) * 4;
#pragma unroll
        for (int q = 0; q < 4; q++) {
            float v = acc[j * 4 + q] + b2[c0 + q];
            split_store(Gh, Gl, (size_t)n * 1024 + c0 + q, v);
        }
    }
}

// ---------------------------------------------------------------------------
// Synapse gather-mean: grid.y = 0 -> by-src, 1 -> by-dst (skip self-loops)
// ---------------------------------------------------------------------------
__global__ __launch_bounds__(256)
void k_syng(const int* __restrict__ rowS, const int* __restrict__ colS,
            const int* __restrict__ rowDd, const int* __restrict__ colDd,
            const float* __restrict__ synapse,
            const float* __restrict__ We1, const float* __restrict__ be1,
            __nv_bfloat16* __restrict__ Gh, __nv_bfloat16* __restrict__ Gl,
            float* __restrict__ bsL, float* __restrict__ bsR)
{
    __shared__ float sWe[6 * 256];
    __shared__ float sbe[256];
    for (int i = threadIdx.x; i < 6 * 256; i += blockDim.x) sWe[i] = We1[i];
    for (int i = threadIdx.x; i < 256; i += blockDim.x) sbe[i] = be1[i];
    __syncthreads();

    int part = blockIdx.y;
    const int* row = part ? rowDd : rowS;
    const int* col = part ? colDd : colS;
    int skipSelf = part;
    int colOff = 512 + part * 256;
    float* bs = part ? bsR : bsL;

    int n = (blockIdx.x * blockDim.x + threadIdx.x) >> 5;
    int lane = threadIdx.x & 31;
    if (n >= NN) return;
    int base = row[n], cnt = row[n + 1] - base;

    float acc[8];
#pragma unroll
    for (int o = 0; o < 8; o++) acc[o] = 0.f;
    int realc = 0;
    for (int i = 0; i < cnt; i++) {
        int eid = col[base + i];
        if (skipSelf && eid >= EE) continue;
        realc++;
        float m = 0.f;
        if (lane < 6) {
            const float* sp = synapse + (size_t)eid * 24 + lane;
            m = sp[0];
            m = fmaxf(m, sp[6]);
            m = fmaxf(m, sp[12]);
            m = fmaxf(m, sp[18]);
        }
        float xp[6];
#pragma unroll
        for (int j = 0; j < 6; j++) xp[j] = __shfl_sync(0xffffffffu, m, j);
#pragma unroll
        for (int o = 0; o < 8; o++) {
            int c = lane * 8 + o;
            float h = sbe[c];
#pragma unroll
            for (int k = 0; k < 6; k++) h += xp[k] * sWe[k * 256 + c];
            acc[o] += fmaxf(h, 0.f);
        }
    }
    float sc = 1.f / (float)max(realc, 1);
#pragma unroll
    for (int o = 0; o < 8; o++)
        split_store(Gh, Gl, (size_t)n * 1024 + colOff + lane * 8 + o, acc[o] * sc);
    if (lane == 0) bs[n] = realc > 0 ? 1.f : 0.f;
}

// ---------------------------------------------------------------------------
// Host launcher (dual-stream fork/join, graph-capturable)
// ---------------------------------------------------------------------------
extern "C" void kernel_launch(void* const* d_in, const int* in_sizes, int n_in,
                              void* d_out, int out_size)
{
    const int*   ei      = (const int*)d_in[0];
    const float* synapse = (const float*)d_in[2];
    int ib = 4;
    if (n_in > 4 && in_sizes[4] == 1) ib = 5;
    const float* x_param = (const float*)d_in[ib + 0];
    const float* W1  = (const float*)d_in[ib + 1];
    const float* as1 = (const float*)d_in[ib + 2];
    const float* ad1 = (const float*)d_in[ib + 3];
    const float* b1  = (const float*)d_in[ib + 4];
    const float* W2  = (const float*)d_in[ib + 5];
    const float* as2 = (const float*)d_in[ib + 6];
    const float* ad2 = (const float*)d_in[ib + 7];
    const float* b2  = (const float*)d_in[ib + 8];
    const float* We1 = (const float*)d_in[ib + 9];
    const float* be1 = (const float*)d_in[ib + 10];
    const float* We2 = (const float*)d_in[ib + 11];
    const float* be2 = (const float*)d_in[ib + 12];
    const float* Wc1 = (const float*)d_in[ib + 13];
    const float* bc1 = (const float*)d_in[ib + 14];
    const float* Wc2 = (const float*)d_in[ib + 15];
    const float* bc2 = (const float*)d_in[ib + 16];
    float* out = (float*)d_out;

    void* sp = nullptr;  cudaGetSymbolAddress(&sp, g_scratch);
    float* S = (float*)sp;
    void* bp = nullptr;  cudaGetSymbolAddress(&bp, g_bf);
    __nv_bfloat16* B = (__nv_bfloat16*)bp;
    void* ip = nullptr;  cudaGetSymbolAddress(&ip, g_int);
    int* I = (int*)ip;

    cudaFuncSetAttribute(tgemm, cudaFuncAttributeMaxDynamicSharedMemorySize, TG_SMEM);

    // Lazy one-time host-side stream/event creation (no device memory involved)
    static cudaStream_t sB = nullptr;
    static cudaEvent_t evFork, evPrep, evCSR, evB2;
    if (!sB) {
        cudaStreamCreateWithFlags(&sB, cudaStreamNonBlocking);
        cudaEventCreateWithFlags(&evFork, cudaEventDisableTiming);
        cudaEventCreateWithFlags(&evPrep, cudaEventDisableTiming);
        cudaEventCreateWithFlags(&evCSR, cudaEventDisableTiming);
        cudaEventCreateWithFlags(&evB2, cudaEventDisableTiming);
    }

    float* s1  = S + OFF_S1;
    float* dd1 = S + OFF_DD1;
    float* s2  = S + OFF_S2;
    float* dd2 = S + OFF_DD2;
    float* bsL = S + OFF_BSL;
    float* bsR = S + OFF_BSR;
    float* vL  = S + OFF_VL;
    float* vR  = S + OFF_VR;
    float* Wcomb = S + OFF_WCOMB;
    float* xl1 = S + OFF_XL1;
    float* xl2 = S + OFF_XL2;

    int* wrD  = I + I_WRD;
    int* wrS  = I + I_WRS;
    int* rowD = I + I_ROWD;
    int* rowS = I + I_ROWS;
    int* colD = I + I_COLD;
    int* colS = I + I_COLS;

    dim3 tpb(256);
    const int MT = (NN + 127) / 128;
    const int NW = (NN * 32 + 255) / 256;

    // ---- Fork stream B ----
    cudaEventRecord(evFork, 0);
    cudaStreamWaitEvent(sB, evFork, 0);

    // ---- Stream B: CSR build + synapse gather ----
    cudaMemsetAsync(wrD, 0, 2 * NN * sizeof(int), sB);
    k_hist<<<(ESL + 255) / 256, tpb, 0, sB>>>(ei, wrD, wrS);
    k_scan<<<1, 1024, 0, sB>>>(wrD, wrS, rowD, rowS);
    k_scatter<<<(ESL + 255) / 256, tpb, 0, sB>>>(ei, wrD, wrS, colD, colS);
    cudaEventRecord(evCSR, sB);
    {
        dim3 g(NW, 2);
        k_syng<<<g, tpb, 0, sB>>>(rowS, colS, rowD, colD, synapse, We1, be1,
                                  B + B_GH, B + B_GL, bsL, bsR);
    }

    // ---- Stream 0: mega-prep ----
    k_prep<<<(P_TOT + 255) / 256, tpb>>>(W1, W2, Wc1, Wc2, We2, x_param, be2,
                                         S, B, vL, vR);
    cudaEventRecord(evPrep, 0);

    // ---- Stream B (after prep): Wcomb GEMM + prep2 ----
    cudaStreamWaitEvent(sB, evPrep, 0);
    {
        dim3 g(8, 2);
        tgemm<<<g, tpb, TG_SMEM, sB>>>(B + B_WE2AH, B + B_WE2AL, B + B_WMH, B + B_WML,
                                       Wcomb, nullptr, nullptr, 256, 512, 1024, 1024,
                                       nullptr, nullptr, nullptr, nullptr, nullptr, 0,
                                       nullptr, nullptr, nullptr, nullptr, 0);
    }
    k_prep2<<<(2 * 131072 + 255) / 256, tpb, 0, sB>>>(Wcomb, B);
    cudaEventRecord(evB2, sB);

    // ---- Stream 0: GAT1 GEMM (+ fused s1/dd1 dots) ----
    {
        dim3 g(4, MT);
        tgemm<<<g, tpb, TG_SMEM>>>(B + B_XPH, B + B_XPL, B + B_W1H, B + B_W1L,
                                   xl1, nullptr, nullptr, NN, FIN, D1, D1,
                                   nullptr, nullptr, nullptr, nullptr, nullptr, 0,
                                   s1, dd1, as1, ad1, 6);
    }
    // GAT1 attention (needs CSR)
    cudaStreamWaitEvent(0, evCSR, 0);
    k_att1<<<NW, tpb>>>(ei, rowD, colD, xl1, s1, dd1, b1, B + B_X1H, B + B_X1L);

    // ---- GAT2 ----
    {
        dim3 g(4, MT);
        tgemm<<<g, tpb, TG_SMEM>>>(B + B_X1H, B + B_X1L, B + B_W2H, B + B_W2L,
                                   xl2, nullptr, nullptr, NN, D1, REP, REP,
                                   nullptr, nullptr, nullptr, nullptr, nullptr, 0,
                                   s2, dd2, as2, ad2, 9);
    }
    k_att2<<<NW, tpb>>>(ei, rowD, colD, xl2, s2, dd2, b2, B + B_GH, B + B_GL);

    // ---- Join stream B, then classifier ----
    cudaStreamWaitEvent(0, evB2, 0);
    {
        dim3 g(4, MT);
        tgemm<<<g, tpb, TG_SMEM>>>(B + B_GH, B + B_GL, B + B_WBH, B + B_WBL,
                                   nullptr, B + B_HCH, B + B_HCL, NN, 1024, 512, 512,
                                   bc1, vL, bsL, vR, bsR, 1,
                                   nullptr, nullptr, nullptr, nullptr, 0);
    }
    {
        dim3 g(2, MT);
        tgemm<<<g, tpb, TG_SMEM>>>(B + B_HCH, B + B_HCL, B + B_WC2H, B + B_WC2L,
                                   out, nullptr, nullptr, NN, 512, NCLS, NCLS,
                                   bc2, nullptr, nullptr, nullptr, nullptr, 0,
                                   nullptr, nullptr, nullptr, nullptr, 0);
    }
}